// round 3
// baseline (speedup 1.0000x reference)
#include <cuda_runtime.h>
#include <math.h>

// ---------------- model dims ----------------
#define NTOK 8192          // B*T
#define BB   8
#define TT   1024
#define DD   512
#define FF   2048
#define VV   8192
#define HH   8
#define HD   64
#define LL   6

// ---------------- scratch (device globals; no runtime allocation) ----------------
__device__ float g_x   [NTOK * DD];        // embed output (pre-mask)
__device__ float g_res [NTOK * DD];        // residual stream
__device__ float g_h   [NTOK * DD];        // layernorm temp
__device__ float g_z   [NTOK * DD];        // projected z
__device__ float g_qkv [NTOK * 3 * DD];
__device__ float g_attn[NTOK * DD];
__device__ float g_ffn [NTOK * FF];
__device__ float g_big [(size_t)NTOK * VV];  // dist scores, later logits (256MB)
__device__ float g_enorm[VV];
__device__ int   g_tgt [NTOK];
__device__ float g_ent [NTOK];
__device__ float g_act [NTOK];

// ---------------- generic SGEMM: C[M,N] = A[M,K] @ B[K,N], row-major ----------------
// MODE 0: store, MODE 1: C += A@B (residual add), MODE 2: relu(A@B)
#define BM 128
#define BN 128
#define BK 8

template <int MODE>
__global__ void __launch_bounds__(256) sgemm_kernel(int M, int N, int K,
                                                    const float* __restrict__ A,
                                                    const float* __restrict__ B,
                                                    float* __restrict__ C)
{
    __shared__ float As[BK][BM];
    __shared__ float Bs[BK][BN];

    const int tid = threadIdx.x;
    const int bm  = blockIdx.y * BM;
    const int bn  = blockIdx.x * BN;
    const int tx  = tid & 15;     // 0..15
    const int ty  = tid >> 4;     // 0..15

    float acc[8][8];
#pragma unroll
    for (int i = 0; i < 8; i++)
#pragma unroll
        for (int j = 0; j < 8; j++) acc[i][j] = 0.f;

    const int aRow = tid >> 1;          // 0..127
    const int aCol = (tid & 1) * 4;     // 0 or 4
    const int bRow = tid >> 5;          // 0..7
    const int bCol = (tid & 31) * 4;    // 0..124

    const float* Aptr = A + (size_t)(bm + aRow) * K + aCol;
    const float* Bptr = B + (size_t)bRow * N + bn + bCol;

    for (int k0 = 0; k0 < K; k0 += BK) {
        float4 av = *(const float4*)(Aptr + k0);
        float4 bv = *(const float4*)(Bptr + (size_t)k0 * N);
        As[aCol + 0][aRow] = av.x;
        As[aCol + 1][aRow] = av.y;
        As[aCol + 2][aRow] = av.z;
        As[aCol + 3][aRow] = av.w;
        *(float4*)&Bs[bRow][bCol] = bv;
        __syncthreads();
#pragma unroll
        for (int k = 0; k < BK; k++) {
            float a[8], b[8];
#pragma unroll
            for (int i = 0; i < 8; i++) a[i] = As[k][ty * 8 + i];
#pragma unroll
            for (int j = 0; j < 8; j++) b[j] = Bs[k][tx * 8 + j];
#pragma unroll
            for (int i = 0; i < 8; i++)
#pragma unroll
                for (int j = 0; j < 8; j++) acc[i][j] += a[i] * b[j];
        }
        __syncthreads();
    }

#pragma unroll
    for (int i = 0; i < 8; i++) {
        float* crow = C + (size_t)(bm + ty * 8 + i) * N + bn + tx * 8;
#pragma unroll
        for (int j = 0; j < 8; j += 4) {
            float4 v = make_float4(acc[i][j], acc[i][j + 1], acc[i][j + 2], acc[i][j + 3]);
            if (MODE == 1) {
                float4 o = *(const float4*)(crow + j);
                v.x += o.x; v.y += o.y; v.z += o.z; v.w += o.w;
            }
            if (MODE == 2) {
                v.x = fmaxf(v.x, 0.f); v.y = fmaxf(v.y, 0.f);
                v.z = fmaxf(v.z, 0.f); v.w = fmaxf(v.w, 0.f);
            }
            *(float4*)(crow + j) = v;
        }
    }
}

// ---------------- sinusoidal positional encoding add (fp64 for angle accuracy) ----------------
__global__ void __launch_bounds__(256) pe_add_kernel(float* __restrict__ x)
{
    const int n = blockIdx.x;           // 0..8191 (token row)
    const int j = threadIdx.x;          // 0..255 (dim pair)
    const int t = n & (TT - 1);
    double freq = exp(-(double)j * (9.210340371976184 / 256.0));  // 10000^(-2j/512)
    double ang  = (double)t * freq;
    float* p = x + (size_t)n * DD + 2 * j;
    p[0] += (float)sin(ang);
    p[1] += (float)cos(ang);
}

// ---------------- layernorm (one row per block, D=512, 256 threads) ----------------
__global__ void __launch_bounds__(256) ln_kernel(const float* __restrict__ in,
                                                 float* __restrict__ out,
                                                 const float* __restrict__ gam,
                                                 const float* __restrict__ bet)
{
    const int n = blockIdx.x;
    const int t = threadIdx.x;
    const float* row = in + (size_t)n * DD;
    float x0 = row[t];
    float x1 = row[t + 256];
    __shared__ float s1[256], s2[256];
    s1[t] = x0 + x1;
    s2[t] = x0 * x0 + x1 * x1;
    __syncthreads();
    for (int o = 128; o > 0; o >>= 1) {
        if (t < o) { s1[t] += s1[t + o]; s2[t] += s2[t + o]; }
        __syncthreads();
    }
    float mean = s1[0] * (1.f / DD);
    float var  = s2[0] * (1.f / DD) - mean * mean;
    float r = rsqrtf(var + 1e-5f);
    float* orow = out + (size_t)n * DD;
    orow[t]       = (x0 - mean) * r * gam[t]       + bet[t];
    orow[t + 256] = (x1 - mean) * r * gam[t + 256] + bet[t + 256];
}

// ---------------- mask mix: res = mask ? mask_emb : x ----------------
__global__ void __launch_bounds__(256) maskmix_kernel(const float* __restrict__ x,
                                                      const unsigned* __restrict__ mask,
                                                      const float* __restrict__ memb,
                                                      float* __restrict__ out)
{
    int idx = blockIdx.x * 256 + threadIdx.x;
    int n = idx >> 9;          // /512
    int d = idx & 511;
    out[idx] = (mask[n] != 0u) ? memb[d] : x[idx];
}

// ---------------- codebook column norms ----------------
__global__ void __launch_bounds__(256) enorm_kernel(const float* __restrict__ emb,
                                                    float* __restrict__ enorm)
{
    int v = blockIdx.x * 256 + threadIdx.x;
    float s = 0.f;
    for (int e = 0; e < DD; e++) {
        float x = emb[(size_t)e * VV + v];
        s += x * x;
    }
    enorm[v] = s;
}

// ---------------- per-row argmin of (|e|^2 - 2 z.e) ----------------
__global__ void __launch_bounds__(256) argmin_kernel(const float* __restrict__ big,
                                                     const float* __restrict__ enorm,
                                                     int* __restrict__ tgt)
{
    const int n = blockIdx.x;
    const float* row = big + (size_t)n * VV;
    const int tid = threadIdx.x;
    float best = 3.4e38f;
    int bi = 0;
    for (int v = tid; v < VV; v += 256) {
        float sc = enorm[v] - 2.f * row[v];
        if (sc < best) { best = sc; bi = v; }
    }
    __shared__ float bv[256];
    __shared__ int bix[256];
    bv[tid] = best; bix[tid] = bi;
    __syncthreads();
    for (int o = 128; o > 0; o >>= 1) {
        if (tid < o) {
            if (bv[tid + o] < bv[tid] || (bv[tid + o] == bv[tid] && bix[tid + o] < bix[tid])) {
                bv[tid] = bv[tid + o]; bix[tid] = bix[tid + o];
            }
        }
        __syncthreads();
    }
    if (tid == 0) tgt[n] = bix[0];
}

// ---------------- fused attention: one block = (b, h, 64-query tile), online softmax ----------------
__global__ void __launch_bounds__(256) attn_kernel(const float* __restrict__ qkv,
                                                   const int* __restrict__ lens,
                                                   float* __restrict__ out)
{
    const int b  = blockIdx.z;
    const int h  = blockIdx.y;
    const int q0 = blockIdx.x * 64;
    const int tid = threadIdx.x;
    const int tx = tid & 15;   // key/out-dim tile coord
    const int ty = tid >> 4;   // query tile coord
    const int len = lens[b];

    __shared__ __align__(16) float Qs[64][64];
    __shared__ __align__(16) float KV[64][64];   // K phase: [d][k] transposed ; V phase: [k][d]
    __shared__ __align__(16) float Ps[64][64];

    // load Q tile [64 q][64 d]
    {
        const int r  = tid >> 2;
        const int c0 = (tid & 3) * 16;
        const float* src = qkv + (size_t)(b * TT + q0 + r) * (3 * DD) + h * HD + c0;
#pragma unroll
        for (int c = 0; c < 16; c += 4)
            *(float4*)&Qs[r][c0 + c] = *(const float4*)(src + c);
    }

    float m[4], l[4], acc[4][4];
#pragma unroll
    for (int i = 0; i < 4; i++) {
        m[i] = -1e30f; l[i] = 0.f;
#pragma unroll
        for (int j = 0; j < 4; j++) acc[i][j] = 0.f;
    }

    for (int kt = 0; kt < 16; kt++) {
        // load K tile transposed into KV[d][k]
        {
            const int r  = tid >> 2;
            const int c0 = (tid & 3) * 16;
            const float* src = qkv + (size_t)(b * TT + kt * 64 + r) * (3 * DD) + DD + h * HD + c0;
#pragma unroll
            for (int c = 0; c < 16; c += 4) {
                float4 v = *(const float4*)(src + c);
                KV[c0 + c + 0][r] = v.x;
                KV[c0 + c + 1][r] = v.y;
                KV[c0 + c + 2][r] = v.z;
                KV[c0 + c + 3][r] = v.w;
            }
        }
        __syncthreads();

        // S = Q K^T  (4x4 per thread)
        float s[4][4];
#pragma unroll
        for (int i = 0; i < 4; i++)
#pragma unroll
            for (int j = 0; j < 4; j++) s[i][j] = 0.f;
#pragma unroll 8
        for (int d = 0; d < 64; d++) {
            float a[4], bb[4];
#pragma unroll
            for (int i = 0; i < 4; i++) a[i] = Qs[ty * 4 + i][d];
#pragma unroll
            for (int j = 0; j < 4; j++) bb[j] = KV[d][tx * 4 + j];
#pragma unroll
            for (int i = 0; i < 4; i++)
#pragma unroll
                for (int j = 0; j < 4; j++) s[i][j] += a[i] * bb[j];
        }

        // scale + key-padding bias
        const int kb = kt * 64 + tx * 4;
        float bias[4];
#pragma unroll
        for (int j = 0; j < 4; j++) bias[j] = (kb + j < len) ? 0.f : -1e9f;
#pragma unroll
        for (int i = 0; i < 4; i++)
#pragma unroll
            for (int j = 0; j < 4; j++) s[i][j] = s[i][j] * 0.125f + bias[j];

        // online softmax: row max over 16 lanes sharing ty
        float mt[4];
#pragma unroll
        for (int i = 0; i < 4; i++)
            mt[i] = fmaxf(fmaxf(s[i][0], s[i][1]), fmaxf(s[i][2], s[i][3]));
#pragma unroll
        for (int o = 1; o < 16; o <<= 1)
#pragma unroll
            for (int i = 0; i < 4; i++)
                mt[i] = fmaxf(mt[i], __shfl_xor_sync(0xffffffffu, mt[i], o));

        float al[4];
#pragma unroll
        for (int i = 0; i < 4; i++) {
            float mn = fmaxf(m[i], mt[i]);
            al[i] = __expf(m[i] - mn);
            m[i] = mn;
        }

        float rs[4];
#pragma unroll
        for (int i = 0; i < 4; i++) {
            rs[i] = 0.f;
#pragma unroll
            for (int j = 0; j < 4; j++) {
                float p = __expf(s[i][j] - m[i]);
                Ps[ty * 4 + i][tx * 4 + j] = p;
                rs[i] += p;
            }
        }
#pragma unroll
        for (int o = 1; o < 16; o <<= 1)
#pragma unroll
            for (int i = 0; i < 4; i++)
                rs[i] += __shfl_xor_sync(0xffffffffu, rs[i], o);

#pragma unroll
        for (int i = 0; i < 4; i++) {
            l[i] = l[i] * al[i] + rs[i];
#pragma unroll
            for (int j = 0; j < 4; j++) acc[i][j] *= al[i];
        }
        __syncthreads();   // all done reading KV(K) + Ps written

        // load V tile natural [k][d]
        {
            const int r  = tid >> 2;
            const int c0 = (tid & 3) * 16;
            const float* src = qkv + (size_t)(b * TT + kt * 64 + r) * (3 * DD) + 2 * DD + h * HD + c0;
#pragma unroll
            for (int c = 0; c < 16; c += 4)
                *(float4*)&KV[r][c0 + c] = *(const float4*)(src + c);
        }
        __syncthreads();

        // O += P V
#pragma unroll 8
        for (int k = 0; k < 64; k++) {
            float a[4], bb[4];
#pragma unroll
            for (int i = 0; i < 4; i++) a[i] = Ps[ty * 4 + i][k];
#pragma unroll
            for (int j = 0; j < 4; j++) bb[j] = KV[k][tx * 4 + j];
#pragma unroll
            for (int i = 0; i < 4; i++)
#pragma unroll
                for (int j = 0; j < 4; j++) acc[i][j] += a[i] * bb[j];
        }
        __syncthreads();
    }

    // normalize + write: out[(b*T + q)*D + h*64 + d]
#pragma unroll
    for (int i = 0; i < 4; i++) {
        float inv = 1.f / l[i];
        float4 v = make_float4(acc[i][0] * inv, acc[i][1] * inv, acc[i][2] * inv, acc[i][3] * inv);
        *(float4*)(out + (size_t)(b * TT + q0 + ty * 4 + i) * DD + h * HD + tx * 4) = v;
    }
}

// ---------------- per-row masked cross entropy (logsumexp - target logit) ----------------
__global__ void __launch_bounds__(256) rowloss_kernel(const float* __restrict__ big,
                                                      const int* __restrict__ tgt,
                                                      const unsigned* __restrict__ mask,
                                                      const int* __restrict__ lens,
                                                      float* __restrict__ ent,
                                                      float* __restrict__ act)
{
    const int n = blockIdx.x;
    const int b = n >> 10;
    const int t = n & 1023;
    const bool active = (t < lens[b]) && (mask[n] != 0u);
    if (!active) {
        if (threadIdx.x == 0) { ent[n] = 0.f; act[n] = 0.f; }
        return;
    }
    const float* row = big + (size_t)n * VV;
    const int tid = threadIdx.x;
    float mx = -1e30f;
    for (int v = tid; v < VV; v += 256) mx = fmaxf(mx, row[v]);
    __shared__ float sm[256];
    sm[tid] = mx;
    __syncthreads();
    for (int o = 128; o > 0; o >>= 1) {
        if (tid < o) sm[tid] = fmaxf(sm[tid], sm[tid + o]);
        __syncthreads();
    }
    mx = sm[0];
    __syncthreads();
    float s = 0.f;
    for (int v = tid; v < VV; v += 256) s += __expf(row[v] - mx);
    sm[tid] = s;
    __syncthreads();
    for (int o = 128; o > 0; o >>= 1) {
        if (tid < o) sm[tid] += sm[tid + o];
        __syncthreads();
    }
    if (tid == 0) {
        float lse = mx + logf(sm[0]);
        ent[n] = lse - row[tgt[n]];
        act[n] = 1.f;
    }
}

// ---------------- deterministic final reduction ----------------
__global__ void __launch_bounds__(1024) finalize_kernel(const float* __restrict__ ent,
                                                        const float* __restrict__ act,
                                                        float* __restrict__ out)
{
    const int tid = threadIdx.x;
    float s = 0.f, c = 0.f;
    for (int n = tid; n < NTOK; n += 1024) { s += ent[n]; c += act[n]; }
    __shared__ float ss[1024], cc[1024];
    ss[tid] = s; cc[tid] = c;
    __syncthreads();
    for (int o = 512; o > 0; o >>= 1) {
        if (tid < o) { ss[tid] += ss[tid + o]; cc[tid] += cc[tid + o]; }
        __syncthreads();
    }
    if (tid == 0) out[0] = ss[0] / cc[0];   // NC == 1
}

// ---------------- host orchestration ----------------
extern "C" void kernel_launch(void* const* d_in, const int* in_sizes, int n_in,
                              void* d_out, int out_size)
{
    (void)in_sizes; (void)n_in; (void)out_size;
    const float*    xs     = (const float*)d_in[0];
    const int*      lens   = (const int*)d_in[1];
    const unsigned* mask   = (const unsigned*)d_in[2];   // bool -> 32-bit (int32/float32): !=0 works for both
    const float*    W_emb  = (const float*)d_in[3];
    const float*    ln1_s  = (const float*)d_in[4];
    const float*    ln1_b  = (const float*)d_in[5];
    const float*    Wqkv   = (const float*)d_in[6];
    const float*    Wo     = (const float*)d_in[7];
    const float*    ln2_s  = (const float*)d_in[8];
    const float*    ln2_b  = (const float*)d_in[9];
    const float*    W1     = (const float*)d_in[10];
    const float*    W2     = (const float*)d_in[11];
    const float*    an_s   = (const float*)d_in[12];
    const float*    an_b   = (const float*)d_in[13];
    const float*    iln_s  = (const float*)d_in[14];
    const float*    iln_b  = (const float*)d_in[15];
    const float*    memb   = (const float*)d_in[16];
    const float*    top    = (const float*)d_in[17];
    const float*    proj   = (const float*)d_in[18];
    const float*    emb    = (const float*)d_in[19];

    float *px, *pres, *ph, *pz, *pqkv, *pattn, *pffn, *pbig, *penorm, *pent, *pact;
    int* ptgt;
    cudaGetSymbolAddress((void**)&px,    g_x);
    cudaGetSymbolAddress((void**)&pres,  g_res);
    cudaGetSymbolAddress((void**)&ph,    g_h);
    cudaGetSymbolAddress((void**)&pz,    g_z);
    cudaGetSymbolAddress((void**)&pqkv,  g_qkv);
    cudaGetSymbolAddress((void**)&pattn, g_attn);
    cudaGetSymbolAddress((void**)&pffn,  g_ffn);
    cudaGetSymbolAddress((void**)&pbig,  g_big);
    cudaGetSymbolAddress((void**)&penorm,g_enorm);
    cudaGetSymbolAddress((void**)&pent,  g_ent);
    cudaGetSymbolAddress((void**)&pact,  g_act);
    cudaGetSymbolAddress((void**)&ptgt,  g_tgt);

    // 1. x = xs @ W_embed + PE
    sgemm_kernel<0><<<dim3(DD / BN, NTOK / BM), 256>>>(NTOK, DD, DD, xs, W_emb, px);
    pe_add_kernel<<<NTOK, 256>>>(px);

    // 2. target ids: ln -> proj -> z@emb -> argmin(|e|^2 - 2 z.e)
    ln_kernel<<<NTOK, 256>>>(px, ph, iln_s, iln_b);
    sgemm_kernel<0><<<dim3(DD / BN, NTOK / BM), 256>>>(NTOK, DD, DD, ph, proj, pz);
    sgemm_kernel<0><<<dim3(VV / BN, NTOK / BM), 256>>>(NTOK, VV, DD, pz, emb, pbig);
    enorm_kernel<<<VV / 256, 256>>>(emb, penorm);
    argmin_kernel<<<NTOK, 256>>>(pbig, penorm, ptgt);

    // 3. masked stream
    maskmix_kernel<<<(NTOK * DD) / 256, 256>>>(px, mask, memb, pres);

    // 4. encoder layers
    for (int l = 0; l < LL; l++) {
        ln_kernel<<<NTOK, 256>>>(pres, ph, ln1_s + l * DD, ln1_b + l * DD);
        sgemm_kernel<0><<<dim3((3 * DD) / BN, NTOK / BM), 256>>>(NTOK, 3 * DD, DD,
                ph, Wqkv + (size_t)l * DD * 3 * DD, pqkv);
        attn_kernel<<<dim3(TT / 64, HH, BB), 256>>>(pqkv, lens, pattn);
        sgemm_kernel<1><<<dim3(DD / BN, NTOK / BM), 256>>>(NTOK, DD, DD,
                pattn, Wo + (size_t)l * DD * DD, pres);
        ln_kernel<<<NTOK, 256>>>(pres, ph, ln2_s + l * DD, ln2_b + l * DD);
        sgemm_kernel<2><<<dim3(FF / BN, NTOK / BM), 256>>>(NTOK, FF, DD,
                ph, W1 + (size_t)l * DD * FF, pffn);
        sgemm_kernel<1><<<dim3(DD / BN, NTOK / BM), 256>>>(NTOK, DD, FF,
                pffn, W2 + (size_t)l * FF * DD, pres);
    }

    // 5. final LN + logits + masked CE
    ln_kernel<<<NTOK, 256>>>(pres, ph, an_s, an_b);
    sgemm_kernel<0><<<dim3(VV / BN, NTOK / BM), 256>>>(NTOK, VV, DD, ph, top, pbig);
    rowloss_kernel<<<NTOK, 256>>>(pbig, ptgt, mask, lens, pent, pact);
    finalize_kernel<<<1, 1024>>>(pent, pact, (float*)d_out);
}

// round 6
// speedup vs baseline: 2.5253x; 2.5253x over previous
#include <cuda_runtime.h>
#include <cuda_bf16.h>
#include <math.h>
#include <stdint.h>

// ---------------- model dims ----------------
#define NTOK 8192
#define TT   1024
#define DD   512
#define FF   2048
#define VV   8192
#define HH   8
#define HD   64
#define LL   6
#define KSP  1536   // 3*DD split-K for hi/lo distance GEMM

// ---------------- scratch (device globals) ----------------
__device__ float g_x   [NTOK * DD];
__device__ float g_res [NTOK * DD];
__device__ float g_h   [NTOK * DD];
__device__ float g_z   [NTOK * DD];
__device__ float g_qkv [NTOK * 3 * DD];
__device__ float g_big [(size_t)NTOK * VV];
__device__ float g_enorm[VV];
__device__ int   g_tgt [NTOK];
__device__ float g_ent [NTOK];
__device__ float g_act [NTOK];
__device__ __nv_bfloat16 g_hb   [NTOK * DD];
__device__ __nv_bfloat16 g_attnb[NTOK * DD];
__device__ __nv_bfloat16 g_ffnb [NTOK * FF];
__device__ __nv_bfloat16 g_zs   [(size_t)NTOK * KSP];
__device__ __nv_bfloat16 g_embt [(size_t)VV * KSP];
__device__ __nv_bfloat16 g_wqkvt[LL * 3 * DD * DD];
__device__ __nv_bfloat16 g_wot  [LL * DD * DD];
__device__ __nv_bfloat16 g_w1t  [LL * FF * DD];
__device__ __nv_bfloat16 g_w2t  [LL * DD * FF];
__device__ __nv_bfloat16 g_topt [VV * DD];

// ---------------- helpers ----------------
__device__ __forceinline__ uint32_t smem_u32(const void* p) {
    uint32_t a;
    asm("{ .reg .u64 t; cvta.to.shared.u64 t, %1; cvt.u32.u64 %0, t; }" : "=r"(a) : "l"(p));
    return a;
}
__device__ __forceinline__ void cp16(uint32_t dst, const void* src) {
    asm volatile("cp.async.cg.shared.global [%0], [%1], 16;" :: "r"(dst), "l"(src));
}
__device__ __forceinline__ void ldsm_x4(uint32_t& r0, uint32_t& r1, uint32_t& r2, uint32_t& r3, uint32_t addr) {
    asm volatile("ldmatrix.sync.aligned.m8n8.x4.shared.b16 {%0,%1,%2,%3}, [%4];"
                 : "=r"(r0), "=r"(r1), "=r"(r2), "=r"(r3) : "r"(addr));
}
__device__ __forceinline__ void mma16816(float* d, const uint32_t* a, const uint32_t* b) {
    asm volatile("mma.sync.aligned.m16n8k16.row.col.f32.bf16.bf16.f32 "
                 "{%0,%1,%2,%3}, {%4,%5,%6,%7}, {%8,%9}, {%0,%1,%2,%3};"
                 : "+f"(d[0]), "+f"(d[1]), "+f"(d[2]), "+f"(d[3])
                 : "r"(a[0]), "r"(a[1]), "r"(a[2]), "r"(a[3]), "r"(b[0]), "r"(b[1]));
}
#define SWZ(o) ((o) ^ (((o) >> 3) & 0x70))

// =======================================================================
// bf16 HMMA GEMM: C[M,N] = A[M,K] @ Bt[N,K]^T  (Bt row-major [N,K])
// MODE 0: store fp32; MODE 1: Cf += result; MODE 2: Cb = bf16(relu(result))
// CTA tile 128x128, 8 warps (2x4 -> 64x32/warp), K chunks of 64, double-buffered
// =======================================================================
#define HG_SMEM (2 * 32768)

template <int MODE>
__global__ void __launch_bounds__(256) hgemm_kernel(int M, int N, int K,
                                                    const __nv_bfloat16* __restrict__ A,
                                                    const __nv_bfloat16* __restrict__ Bt,
                                                    float* __restrict__ Cf,
                                                    __nv_bfloat16* __restrict__ Cb)
{
    extern __shared__ char smem[];
    const uint32_t sb = smem_u32(smem);
    const int tid  = threadIdx.x;
    const int wid  = tid >> 5, lane = tid & 31;
    const int wm   = wid >> 2;      // 0..1  (64 rows)
    const int wn   = wid & 3;       // 0..3  (32 cols)
    const int bm   = blockIdx.y * 128, bn = blockIdx.x * 128;
    const int nch  = K >> 6;

    auto load_chunk = [&](int ci) {
        uint32_t buf = sb + (uint32_t)(ci & 1) * 32768u;
        const __nv_bfloat16* ap = A  + (size_t)bm * K + (size_t)ci * 64;
        const __nv_bfloat16* bp = Bt + (size_t)bn * K + (size_t)ci * 64;
#pragma unroll
        for (int c = 0; c < 4; c++) {
            int idx = tid * 4 + c;            // 0..1023
            int row = idx >> 3, seg = idx & 7;
            uint32_t off = SWZ((uint32_t)(row * 128 + seg * 16));
            cp16(buf + off,          ap + (size_t)row * K + seg * 8);
            cp16(buf + 16384u + off, bp + (size_t)row * K + seg * 8);
        }
        asm volatile("cp.async.commit_group;");
    };

    load_chunk(0);
    if (nch > 1) load_chunk(1);

    float acc[4][4][4];
#pragma unroll
    for (int mi = 0; mi < 4; mi++)
#pragma unroll
        for (int ni = 0; ni < 4; ni++)
#pragma unroll
            for (int q = 0; q < 4; q++) acc[mi][ni][q] = 0.f;

    for (int ci = 0; ci < nch; ci++) {
        if (ci + 1 < nch) asm volatile("cp.async.wait_group 1;");
        else              asm volatile("cp.async.wait_group 0;");
        __syncthreads();

        uint32_t ab = sb + (uint32_t)(ci & 1) * 32768u;
        uint32_t bb = ab + 16384u;
#pragma unroll
        for (int ks = 0; ks < 4; ks++) {
            uint32_t af[4][4], bf[4][2];
#pragma unroll
            for (int mi = 0; mi < 4; mi++) {
                int row = wm * 64 + mi * 16 + (lane & 15);
                uint32_t addr = ab + SWZ((uint32_t)(row * 128 + ks * 32 + ((lane >> 4) << 4)));
                ldsm_x4(af[mi][0], af[mi][1], af[mi][2], af[mi][3], addr);
            }
#pragma unroll
            for (int p = 0; p < 2; p++) {
                int nr = wn * 32 + p * 16 + ((lane >> 4) << 3) + (lane & 7);
                uint32_t addr = bb + SWZ((uint32_t)(nr * 128 + ks * 32 + (((lane >> 3) & 1) << 4)));
                ldsm_x4(bf[p * 2][0], bf[p * 2][1], bf[p * 2 + 1][0], bf[p * 2 + 1][1], addr);
            }
#pragma unroll
            for (int mi = 0; mi < 4; mi++)
#pragma unroll
                for (int ni = 0; ni < 4; ni++)
                    mma16816(acc[mi][ni], af[mi], bf[ni]);
        }
        __syncthreads();
        if (ci + 2 < nch) load_chunk(ci + 2);
    }

    // epilogue
    const int g = lane >> 2, tig = lane & 3;
#pragma unroll
    for (int mi = 0; mi < 4; mi++) {
#pragma unroll
        for (int ni = 0; ni < 4; ni++) {
            int r0 = bm + wm * 64 + mi * 16 + g;
            int c0 = bn + wn * 32 + ni * 8 + tig * 2;
            float* a4 = acc[mi][ni];
            if (MODE == 0) {
                *(float2*)(Cf + (size_t)r0 * N + c0)       = make_float2(a4[0], a4[1]);
                *(float2*)(Cf + (size_t)(r0 + 8) * N + c0) = make_float2(a4[2], a4[3]);
            } else if (MODE == 1) {
                float2* d0 = (float2*)(Cf + (size_t)r0 * N + c0);
                float2* d1 = (float2*)(Cf + (size_t)(r0 + 8) * N + c0);
                float2 o0 = *d0, o1 = *d1;
                o0.x += a4[0]; o0.y += a4[1];
                o1.x += a4[2]; o1.y += a4[3];
                *d0 = o0; *d1 = o1;
            } else {
                *(__nv_bfloat162*)(Cb + (size_t)r0 * N + c0) =
                    __nv_bfloat162(__float2bfloat16(fmaxf(a4[0], 0.f)), __float2bfloat16(fmaxf(a4[1], 0.f)));
                *(__nv_bfloat162*)(Cb + (size_t)(r0 + 8) * N + c0) =
                    __nv_bfloat162(__float2bfloat16(fmaxf(a4[2], 0.f)), __float2bfloat16(fmaxf(a4[3], 0.f)));
            }
        }
    }
}

// ---------------- fp32 SGEMM (embed + projection; feeds argmin path) ----------------
#define BM 128
#define BN 128
#define BK 8
__global__ void __launch_bounds__(256) sgemm_kernel(int M, int N, int K,
                                                    const float* __restrict__ A,
                                                    const float* __restrict__ B,
                                                    float* __restrict__ C)
{
    __shared__ float As[BK][BM];
    __shared__ float Bs[BK][BN];
    const int tid = threadIdx.x;
    const int bm = blockIdx.y * BM, bn = blockIdx.x * BN;
    const int tx = tid & 15, ty = tid >> 4;
    float acc[8][8];
#pragma unroll
    for (int i = 0; i < 8; i++)
#pragma unroll
        for (int j = 0; j < 8; j++) acc[i][j] = 0.f;
    const int aRow = tid >> 1, aCol = (tid & 1) * 4;
    const int bRow = tid >> 5, bCol = (tid & 31) * 4;
    const float* Aptr = A + (size_t)(bm + aRow) * K + aCol;
    const float* Bptr = B + (size_t)bRow * N + bn + bCol;
    for (int k0 = 0; k0 < K; k0 += BK) {
        float4 av = *(const float4*)(Aptr + k0);
        float4 bv = *(const float4*)(Bptr + (size_t)k0 * N);
        As[aCol + 0][aRow] = av.x; As[aCol + 1][aRow] = av.y;
        As[aCol + 2][aRow] = av.z; As[aCol + 3][aRow] = av.w;
        *(float4*)&Bs[bRow][bCol] = bv;
        __syncthreads();
#pragma unroll
        for (int k = 0; k < BK; k++) {
            float a[8], b[8];
#pragma unroll
            for (int i = 0; i < 8; i++) a[i] = As[k][ty * 8 + i];
#pragma unroll
            for (int j = 0; j < 8; j++) b[j] = Bs[k][tx * 8 + j];
#pragma unroll
            for (int i = 0; i < 8; i++)
#pragma unroll
                for (int j = 0; j < 8; j++) acc[i][j] += a[i] * b[j];
        }
        __syncthreads();
    }
#pragma unroll
    for (int i = 0; i < 8; i++) {
        float* crow = C + (size_t)(bm + ty * 8 + i) * N + bn + tx * 8;
#pragma unroll
        for (int j = 0; j < 8; j += 4)
            *(float4*)(crow + j) = make_float4(acc[i][j], acc[i][j + 1], acc[i][j + 2], acc[i][j + 3]);
    }
}

// ---------------- PE add (fp64 trig) ----------------
__global__ void __launch_bounds__(256) pe_add_kernel(float* __restrict__ x)
{
    const int n = blockIdx.x;
    const int j = threadIdx.x;
    const int t = n & (TT - 1);
    double freq = exp(-(double)j * (9.210340371976184 / 256.0));
    double ang = (double)t * freq;
    float* p = x + (size_t)n * DD + 2 * j;
    p[0] += (float)sin(ang);
    p[1] += (float)cos(ang);
}

// ---------------- layernorm, templated output ----------------
template <typename T>
__global__ void __launch_bounds__(256) ln_kernel(const float* __restrict__ in,
                                                 T* __restrict__ out,
                                                 const float* __restrict__ gam,
                                                 const float* __restrict__ bet)
{
    const int n = blockIdx.x;
    const int t = threadIdx.x;
    const float* row = in + (size_t)n * DD;
    float x0 = row[t], x1 = row[t + 256];
    __shared__ float s1[256], s2[256];
    s1[t] = x0 + x1;
    s2[t] = x0 * x0 + x1 * x1;
    __syncthreads();
    for (int o = 128; o > 0; o >>= 1) {
        if (t < o) { s1[t] += s1[t + o]; s2[t] += s2[t + o]; }
        __syncthreads();
    }
    float mean = s1[0] * (1.f / DD);
    float var = s2[0] * (1.f / DD) - mean * mean;
    float r = rsqrtf(var + 1e-5f);
    T* orow = out + (size_t)n * DD;
    orow[t]       = (T)((x0 - mean) * r * gam[t] + bet[t]);
    orow[t + 256] = (T)((x1 - mean) * r * gam[t + 256] + bet[t + 256]);
}

// ---------------- mask mix ----------------
__global__ void __launch_bounds__(256) maskmix_kernel(const float* __restrict__ x,
                                                      const unsigned* __restrict__ mask,
                                                      const float* __restrict__ memb,
                                                      float* __restrict__ out)
{
    int idx = blockIdx.x * 256 + threadIdx.x;
    int n = idx >> 9, d = idx & 511;
    out[idx] = (mask[n] != 0u) ? memb[d] : x[idx];
}

// ---------------- codebook column norms (exact fp32) ----------------
__global__ void __launch_bounds__(256) enorm_kernel(const float* __restrict__ emb,
                                                    float* __restrict__ enorm)
{
    int v = blockIdx.x * 256 + threadIdx.x;
    float s = 0.f;
    for (int e = 0; e < DD; e++) {
        float x = emb[(size_t)e * VV + v];
        s += x * x;
    }
    enorm[v] = s;
}

// ---------------- argmin over (|e|^2 - 2 z.e) ----------------
__global__ void __launch_bounds__(256) argmin_kernel(const float* __restrict__ big,
                                                     const float* __restrict__ enorm,
                                                     int* __restrict__ tgt)
{
    const int n = blockIdx.x;
    const float* row = big + (size_t)n * VV;
    const int tid = threadIdx.x;
    float best = 3.4e38f;
    int bi = 0;
    for (int v = tid; v < VV; v += 256) {
        float sc = enorm[v] - 2.f * row[v];
        if (sc < best) { best = sc; bi = v; }
    }
    __shared__ float bv[256];
    __shared__ int bix[256];
    bv[tid] = best; bix[tid] = bi;
    __syncthreads();
    for (int o = 128; o > 0; o >>= 1) {
        if (tid < o) {
            if (bv[tid + o] < bv[tid] || (bv[tid + o] == bv[tid] && bix[tid + o] < bix[tid])) {
                bv[tid] = bv[tid + o]; bix[tid] = bix[tid + o];
            }
        }
        __syncthreads();
    }
    if (tid == 0) tgt[n] = bix[0];
}

// ---------------- weight transpose-convert: W[K,N] f32 -> Wt[N,K] bf16 ----------------
__global__ void __launch_bounds__(256) tconv_kernel(const float* __restrict__ W,
                                                    __nv_bfloat16* __restrict__ Wt,
                                                    int K, int N)
{
    W  += (size_t)blockIdx.z * K * N;
    Wt += (size_t)blockIdx.z * K * N;
    __shared__ float tile[32][33];
    int n0 = blockIdx.x * 32, k0 = blockIdx.y * 32;
    int tx = threadIdx.x & 31, ty = threadIdx.x >> 5;   // 32 x 8
#pragma unroll
    for (int i = 0; i < 32; i += 8)
        tile[ty + i][tx] = W[(size_t)(k0 + ty + i) * N + n0 + tx];
    __syncthreads();
#pragma unroll
    for (int i = 0; i < 32; i += 8)
        Wt[(size_t)(n0 + ty + i) * K + k0 + tx] = __float2bfloat16(tile[tx][ty + i]);
}

// ---------------- embedding transpose + hi/lo split: emb[E,V] -> embt[V, 3E] (hi|lo|hi) ----------------
__global__ void __launch_bounds__(256) embsplit_kernel(const float* __restrict__ emb,
                                                       __nv_bfloat16* __restrict__ embt)
{
    __shared__ float tile[32][33];
    int v0 = blockIdx.x * 32, e0 = blockIdx.y * 32;
    int tx = threadIdx.x & 31, ty = threadIdx.x >> 5;
#pragma unroll
    for (int i = 0; i < 32; i += 8)
        tile[ty + i][tx] = emb[(size_t)(e0 + ty + i) * VV + v0 + tx];
    __syncthreads();
#pragma unroll
    for (int i = 0; i < 32; i += 8) {
        float a = tile[tx][ty + i];
        int v = v0 + ty + i, e = e0 + tx;
        __nv_bfloat16 hi = __float2bfloat16(a);
        __nv_bfloat16 lo = __float2bfloat16(a - __bfloat162float(hi));
        size_t base = (size_t)v * KSP;
        embt[base + e] = hi;
        embt[base + DD + e] = lo;
        embt[base + 2 * DD + e] = hi;
    }
}

// ---------------- z hi/lo split: z[N,E] f32 -> zs[N, 3E] (hi|hi|lo) ----------------
__global__ void __launch_bounds__(256) zsplit_kernel(const float* __restrict__ z,
                                                     __nv_bfloat16* __restrict__ zs)
{
    int idx = blockIdx.x * 256 + threadIdx.x;
    int n = idx >> 9, e = idx & 511;
    float a = z[idx];
    __nv_bfloat16 hi = __float2bfloat16(a);
    __nv_bfloat16 lo = __float2bfloat16(a - __bfloat162float(hi));
    size_t base = (size_t)n * KSP;
    zs[base + e] = hi;
    zs[base + DD + e] = hi;
    zs[base + 2 * DD + e] = lo;
}

// ---------------- fused attention (fp32 math, bf16 out) ----------------
__global__ void __launch_bounds__(256) attn_kernel(const float* __restrict__ qkv,
                                                   const int* __restrict__ lens,
                                                   __nv_bfloat16* __restrict__ out)
{
    const int b = blockIdx.z, h = blockIdx.y, q0 = blockIdx.x * 64;
    const int tid = threadIdx.x;
    const int tx = tid & 15, ty = tid >> 4;
    const int len = lens[b];

    __shared__ __align__(16) float Qs[64][64];
    __shared__ __align__(16) float KV[64][64];
    __shared__ __align__(16) float Ps[64][64];

    {
        const int r = tid >> 2, c0 = (tid & 3) * 16;
        const float* src = qkv + (size_t)(b * TT + q0 + r) * (3 * DD) + h * HD + c0;
#pragma unroll
        for (int c = 0; c < 16; c += 4)
            *(float4*)&Qs[r][c0 + c] = *(const float4*)(src + c);
    }

    float m[4], l[4], acc[4][4];
#pragma unroll
    for (int i = 0; i < 4; i++) {
        m[i] = -1e30f; l[i] = 0.f;
#pragma unroll
        for (int j = 0; j < 4; j++) acc[i][j] = 0.f;
    }

    for (int kt = 0; kt < 16; kt++) {
        {
            const int r = tid >> 2, c0 = (tid & 3) * 16;
            const float* src = qkv + (size_t)(b * TT + kt * 64 + r) * (3 * DD) + DD + h * HD + c0;
#pragma unroll
            for (int c = 0; c < 16; c += 4) {
                float4 v = *(const float4*)(src + c);
                KV[c0 + c + 0][r] = v.x; KV[c0 + c + 1][r] = v.y;
                KV[c0 + c + 2][r] = v.z; KV[c0 + c + 3][r] = v.w;
            }
        }
        __syncthreads();

        float s[4][4];
#pragma unroll
        for (int i = 0; i < 4; i++)
#pragma unroll
            for (int j = 0; j < 4; j++) s[i][j] = 0.f;
#pragma unroll 8
        for (int d = 0; d < 64; d++) {
            float a[4], bb[4];
#pragma unroll
            for (int i = 0; i < 4; i++) a[i] = Qs[ty * 4 + i][d];
#pragma unroll
            for (int j = 0; j < 4; j++) bb[j] = KV[d][tx * 4 + j];
#pragma unroll
            for (int i = 0; i < 4; i++)
#pragma unroll
                for (int j = 0; j < 4; j++) s[i][j] += a[i] * bb[j];
        }

        const int kb = kt * 64 + tx * 4;
        float bias[4];
#pragma unroll
        for (int j = 0; j < 4; j++) bias[j] = (kb + j < len) ? 0.f : -1e9f;
#pragma unroll
        for (int i = 0; i < 4; i++)
#pragma unroll
            for (int j = 0; j < 4; j++) s[i][j] = s[i][j] * 0.125f + bias[j];

        float mt[4];
#pragma unroll
        for (int i = 0; i < 4; i++)
            mt[i] = fmaxf(fmaxf(s[i][0], s[i][1]), fmaxf(s[i][2], s[i][3]));
#pragma unroll
        for (int o = 1; o < 16; o <<= 1)
#pragma unroll
            for (int i = 0; i < 4; i++)
                mt[i] = fmaxf(mt[i], __shfl_xor_sync(0xffffffffu, mt[i], o));

        float al[4];
#pragma unroll
        for (int i = 0; i < 4; i++) {
            float mn = fmaxf(m[i], mt[i]);
            al[i] = __expf(m[i] - mn);
            m[i] = mn;
        }
        float rs[4];
#pragma unroll
        for (int i = 0; i < 4; i++) {
            rs[i] = 0.f;
#pragma unroll
            for (int j = 0; j < 4; j++) {
                float p = __expf(s[i][j] - m[i]);
                Ps[ty * 4 + i][tx * 4 + j] = p;
                rs[i] += p;
            }
        }
#pragma unroll
        for (int o = 1; o < 16; o <<= 1)
#pragma unroll
            for (int i = 0; i < 4; i++)
                rs[i] += __shfl_xor_sync(0xffffffffu, rs[i], o);
#pragma unroll
        for (int i = 0; i < 4; i++) {
            l[i] = l[i] * al[i] + rs[i];
#pragma unroll
            for (int j = 0; j < 4; j++) acc[i][j] *= al[i];
        }
        __syncthreads();

        {
            const int r = tid >> 2, c0 = (tid & 3) * 16;
            const float* src = qkv + (size_t)(b * TT + kt * 64 + r) * (3 * DD) + 2 * DD + h * HD + c0;
#pragma unroll
            for (int c = 0; c < 16; c += 4)
                *(float4*)&KV[r][c0 + c] = *(const float4*)(src + c);
        }
        __syncthreads();

#pragma unroll 8
        for (int k = 0; k < 64; k++) {
            float a[4], bb[4];
#pragma unroll
            for (int i = 0; i < 4; i++) a[i] = Ps[ty * 4 + i][k];
#pragma unroll
            for (int j = 0; j < 4; j++) bb[j] = KV[k][tx * 4 + j];
#pragma unroll
            for (int i = 0; i < 4; i++)
#pragma unroll
                for (int j = 0; j < 4; j++) acc[i][j] += a[i] * bb[j];
        }
        __syncthreads();
    }

#pragma unroll
    for (int i = 0; i < 4; i++) {
        float inv = 1.f / l[i];
        __nv_bfloat162* dst = (__nv_bfloat162*)(out + (size_t)(b * TT + q0 + ty * 4 + i) * DD + h * HD + tx * 4);
        dst[0] = __nv_bfloat162(__float2bfloat16(acc[i][0] * inv), __float2bfloat16(acc[i][1] * inv));
        dst[1] = __nv_bfloat162(__float2bfloat16(acc[i][2] * inv), __float2bfloat16(acc[i][3] * inv));
    }
}

// ---------------- per-row masked cross entropy ----------------
__global__ void __launch_bounds__(256) rowloss_kernel(const float* __restrict__ big,
                                                      const int* __restrict__ tgt,
                                                      const unsigned* __restrict__ mask,
                                                      const int* __restrict__ lens,
                                                      float* __restrict__ ent,
                                                      float* __restrict__ act)
{
    const int n = blockIdx.x;
    const int b = n >> 10, t = n & 1023;
    const bool active = (t < lens[b]) && (mask[n] != 0u);
    if (!active) {
        if (threadIdx.x == 0) { ent[n] = 0.f; act[n] = 0.f; }
        return;
    }
    const float* row = big + (size_t)n * VV;
    const int tid = threadIdx.x;
    float mx = -1e30f;
    for (int v = tid; v < VV; v += 256) mx = fmaxf(mx, row[v]);
    __shared__ float sm[256];
    sm[tid] = mx;
    __syncthreads();
    for (int o = 128; o > 0; o >>= 1) {
        if (tid < o) sm[tid] = fmaxf(sm[tid], sm[tid + o]);
        __syncthreads();
    }
    mx = sm[0];
    __syncthreads();
    float s = 0.f;
    for (int v = tid; v < VV; v += 256) s += __expf(row[v] - mx);
    sm[tid] = s;
    __syncthreads();
    for (int o = 128; o > 0; o >>= 1) {
        if (tid < o) sm[tid] += sm[tid + o];
        __syncthreads();
    }
    if (tid == 0) {
        ent[n] = mx + logf(sm[0]) - row[tgt[n]];
        act[n] = 1.f;
    }
}

__global__ void __launch_bounds__(1024) finalize_kernel(const float* __restrict__ ent,
                                                        const float* __restrict__ act,
                                                        float* __restrict__ out)
{
    const int tid = threadIdx.x;
    float s = 0.f, c = 0.f;
    for (int n = tid; n < NTOK; n += 1024) { s += ent[n]; c += act[n]; }
    __shared__ float ss[1024], cc[1024];
    ss[tid] = s; cc[tid] = c;
    __syncthreads();
    for (int o = 512; o > 0; o >>= 1) {
        if (tid < o) { ss[tid] += ss[tid + o]; cc[tid] += cc[tid + o]; }
        __syncthreads();
    }
    if (tid == 0) out[0] = ss[0] / cc[0];
}

// ---------------- host ----------------
extern "C" void kernel_launch(void* const* d_in, const int* in_sizes, int n_in,
                              void* d_out, int out_size)
{
    (void)in_sizes; (void)n_in; (void)out_size;
    const float*    xs    = (const float*)d_in[0];
    const int*      lens  = (const int*)d_in[1];
    const unsigned* mask  = (const unsigned*)d_in[2];
    const float*    W_emb = (const float*)d_in[3];
    const float*    ln1_s = (const float*)d_in[4];
    const float*    ln1_b = (const float*)d_in[5];
    const float*    Wqkv  = (const float*)d_in[6];
    const float*    Wo    = (const float*)d_in[7];
    const float*    ln2_s = (const float*)d_in[8];
    const float*    ln2_b = (const float*)d_in[9];
    const float*    W1    = (const float*)d_in[10];
    const float*    W2    = (const float*)d_in[11];
    const float*    an_s  = (const float*)d_in[12];
    const float*    an_b  = (const float*)d_in[13];
    const float*    iln_s = (const float*)d_in[14];
    const float*    iln_b = (const float*)d_in[15];
    const float*    memb  = (const float*)d_in[16];
    const float*    top   = (const float*)d_in[17];
    const float*    proj  = (const float*)d_in[18];
    const float*    emb   = (const float*)d_in[19];

    float *px, *pres, *ph, *pz, *pqkv, *pbig, *penorm, *pent, *pact;
    int* ptgt;
    __nv_bfloat16 *phb, *pattnb, *pffnb, *pzs, *pembt, *pwqkvt, *pwot, *pw1t, *pw2t, *ptopt;
    cudaGetSymbolAddress((void**)&px, g_x);
    cudaGetSymbolAddress((void**)&pres, g_res);
    cudaGetSymbolAddress((void**)&ph, g_h);
    cudaGetSymbolAddress((void**)&pz, g_z);
    cudaGetSymbolAddress((void**)&pqkv, g_qkv);
    cudaGetSymbolAddress((void**)&pbig, g_big);
    cudaGetSymbolAddress((void**)&penorm, g_enorm);
    cudaGetSymbolAddress((void**)&pent, g_ent);
    cudaGetSymbolAddress((void**)&pact, g_act);
    cudaGetSymbolAddress((void**)&ptgt, g_tgt);
    cudaGetSymbolAddress((void**)&phb, g_hb);
    cudaGetSymbolAddress((void**)&pattnb, g_attnb);
    cudaGetSymbolAddress((void**)&pffnb, g_ffnb);
    cudaGetSymbolAddress((void**)&pzs, g_zs);
    cudaGetSymbolAddress((void**)&pembt, g_embt);
    cudaGetSymbolAddress((void**)&pwqkvt, g_wqkvt);
    cudaGetSymbolAddress((void**)&pwot, g_wot);
    cudaGetSymbolAddress((void**)&pw1t, g_w1t);
    cudaGetSymbolAddress((void**)&pw2t, g_w2t);
    cudaGetSymbolAddress((void**)&ptopt, g_topt);

    cudaFuncSetAttribute(hgemm_kernel<0>, cudaFuncAttributeMaxDynamicSharedMemorySize, HG_SMEM);
    cudaFuncSetAttribute(hgemm_kernel<1>, cudaFuncAttributeMaxDynamicSharedMemorySize, HG_SMEM);
    cudaFuncSetAttribute(hgemm_kernel<2>, cudaFuncAttributeMaxDynamicSharedMemorySize, HG_SMEM);

    dim3 tb(256);

    // ---- weight prep (bf16 transposed) ----
    tconv_kernel<<<dim3(3 * DD / 32, DD / 32, LL), tb>>>(Wqkv, pwqkvt, DD, 3 * DD);
    tconv_kernel<<<dim3(DD / 32, DD / 32, LL), tb>>>(Wo, pwot, DD, DD);
    tconv_kernel<<<dim3(FF / 32, DD / 32, LL), tb>>>(W1, pw1t, DD, FF);
    tconv_kernel<<<dim3(DD / 32, FF / 32, LL), tb>>>(W2, pw2t, FF, DD);
    tconv_kernel<<<dim3(VV / 32, DD / 32, 1), tb>>>(top, ptopt, DD, VV);
    embsplit_kernel<<<dim3(VV / 32, DD / 32), tb>>>(emb, pembt);
    enorm_kernel<<<VV / 256, tb>>>(emb, penorm);

    // ---- 1. embed (fp32) + PE ----
    sgemm_kernel<<<dim3(DD / BN, NTOK / BM), tb>>>(NTOK, DD, DD, xs, W_emb, px);
    pe_add_kernel<<<NTOK, tb>>>(px);

    // ---- 2. targets: ln -> proj (fp32) -> split-bf16 distance GEMM -> argmin ----
    ln_kernel<float><<<NTOK, tb>>>(px, ph, iln_s, iln_b);
    sgemm_kernel<<<dim3(DD / BN, NTOK / BM), tb>>>(NTOK, DD, DD, ph, proj, pz);
    zsplit_kernel<<<(NTOK * DD) / 256, tb>>>(pz, pzs);
    hgemm_kernel<0><<<dim3(VV / 128, NTOK / 128), 256, HG_SMEM>>>(NTOK, VV, KSP, pzs, pembt, pbig, nullptr);
    argmin_kernel<<<NTOK, tb>>>(pbig, penorm, ptgt);

    // ---- 3. masked stream ----
    maskmix_kernel<<<(NTOK * DD) / 256, tb>>>(px, mask, memb, pres);

    // ---- 4. encoder layers (bf16 HMMA GEMMs) ----
    for (int l = 0; l < LL; l++) {
        ln_kernel<__nv_bfloat16><<<NTOK, tb>>>(pres, phb, ln1_s + l * DD, ln1_b + l * DD);
        hgemm_kernel<0><<<dim3(3 * DD / 128, NTOK / 128), 256, HG_SMEM>>>(NTOK, 3 * DD, DD,
                phb, pwqkvt + (size_t)l * 3 * DD * DD, pqkv, nullptr);
        attn_kernel<<<dim3(TT / 64, HH, 8), tb>>>(pqkv, lens, pattnb);
        hgemm_kernel<1><<<dim3(DD / 128, NTOK / 128), 256, HG_SMEM>>>(NTOK, DD, DD,
                pattnb, pwot + (size_t)l * DD * DD, pres, nullptr);
        ln_kernel<__nv_bfloat16><<<NTOK, tb>>>(pres, phb, ln2_s + l * DD, ln2_b + l * DD);
        hgemm_kernel<2><<<dim3(FF / 128, NTOK / 128), 256, HG_SMEM>>>(NTOK, FF, DD,
                phb, pw1t + (size_t)l * FF * DD, nullptr, pffnb);
        hgemm_kernel<1><<<dim3(DD / 128, NTOK / 128), 256, HG_SMEM>>>(NTOK, DD, FF,
                pffnb, pw2t + (size_t)l * DD * FF, pres, nullptr);
    }

    // ---- 5. final LN + logits + loss ----
    ln_kernel<__nv_bfloat16><<<NTOK, tb>>>(pres, phb, an_s, an_b);
    hgemm_kernel<0><<<dim3(VV / 128, NTOK / 128), 256, HG_SMEM>>>(NTOK, VV, DD, phb, ptopt, pbig, nullptr);
    rowloss_kernel<<<NTOK, tb>>>(pbig, ptgt, mask, lens, pent, pact);
    finalize_kernel<<<1, 1024>>>(pent, pact, (float*)d_out);
}

// round 9
// speedup vs baseline: 5.7568x; 2.2796x over previous
#include <cuda_runtime.h>
#include <cuda_bf16.h>
#include <math.h>
#include <stdint.h>

// ---------------- model dims ----------------
#define NTOK 8192
#define TT   1024
#define DD   512
#define FF   2048
#define VV   8192
#define HH   8
#define HD   64
#define LL   6
#define KSP  1536

// ---------------- scratch ----------------
__device__ float g_x   [NTOK * DD];
__device__ float g_res [NTOK * DD];
__device__ float g_h   [NTOK * DD];        // compact fp32 LN rows (dist path)
__device__ float g_z   [NTOK * DD];        // compact projected z
__device__ float g_big [(size_t)NTOK * VV];
__device__ float g_enorm[VV];
__device__ int   g_tgt [NTOK];             // compact targets
__device__ float g_ent [NTOK];             // compact entropies
__device__ int   g_actidx[NTOK];
__device__ int   g_nact;
__device__ int   g_nactpad;
__device__ __nv_bfloat16 g_hb   [NTOK * DD];
__device__ __nv_bfloat16 g_qkvb [NTOK * 3 * DD];
__device__ __nv_bfloat16 g_attnb[NTOK * DD];
__device__ __nv_bfloat16 g_ffnb [NTOK * FF];
__device__ __nv_bfloat16 g_zs   [(size_t)NTOK * KSP];
__device__ __nv_bfloat16 g_embt [(size_t)VV * KSP];
__device__ __nv_bfloat16 g_wqkvt[LL * 3 * DD * DD];
__device__ __nv_bfloat16 g_wot  [LL * DD * DD];
__device__ __nv_bfloat16 g_w1t  [LL * FF * DD];
__device__ __nv_bfloat16 g_w2t  [LL * DD * FF];
__device__ __nv_bfloat16 g_topt [VV * DD];

// ---------------- helpers ----------------
__device__ __forceinline__ uint32_t smem_u32(const void* p) {
    uint32_t a;
    asm("{ .reg .u64 t; cvta.to.shared.u64 t, %1; cvt.u32.u64 %0, t; }" : "=r"(a) : "l"(p));
    return a;
}
__device__ __forceinline__ void cp16(uint32_t dst, const void* src) {
    asm volatile("cp.async.cg.shared.global [%0], [%1], 16;" :: "r"(dst), "l"(src));
}
__device__ __forceinline__ void ldsm_x4(uint32_t& r0, uint32_t& r1, uint32_t& r2, uint32_t& r3, uint32_t addr) {
    asm volatile("ldmatrix.sync.aligned.m8n8.x4.shared.b16 {%0,%1,%2,%3}, [%4];"
                 : "=r"(r0), "=r"(r1), "=r"(r2), "=r"(r3) : "r"(addr));
}
__device__ __forceinline__ void mma16816(float* d, const uint32_t* a, const uint32_t* b) {
    asm volatile("mma.sync.aligned.m16n8k16.row.col.f32.bf16.bf16.f32 "
                 "{%0,%1,%2,%3}, {%4,%5,%6,%7}, {%8,%9}, {%0,%1,%2,%3};"
                 : "+f"(d[0]), "+f"(d[1]), "+f"(d[2]), "+f"(d[3])
                 : "r"(a[0]), "r"(a[1]), "r"(a[2]), "r"(a[3]), "r"(b[0]), "r"(b[1]));
}
__device__ __forceinline__ uint32_t packbf(float a, float b) {
    __nv_bfloat162 t(__float2bfloat16(a), __float2bfloat16(b));
    return *(uint32_t*)&t;
}
#define SWZ(o) ((o) ^ (((o) >> 3) & 0x70))

// =======================================================================
// bf16 HMMA GEMM. MODE 0: fp32 store; 1: fp32 +=; 2: bf16 relu; 3: bf16 store
// =======================================================================
#define HG_SMEM (2 * 32768)

template <int MODE>
__global__ void __launch_bounds__(256) hgemm_kernel(int M, int N, int K,
                                                    const __nv_bfloat16* __restrict__ A,
                                                    const __nv_bfloat16* __restrict__ Bt,
                                                    float* __restrict__ Cf,
                                                    __nv_bfloat16* __restrict__ Cb,
                                                    const int* __restrict__ rowlim)
{
    if (rowlim && (int)(blockIdx.y * 128) >= *rowlim) return;
    extern __shared__ char smem[];
    const uint32_t sb = smem_u32(smem);
    const int tid  = threadIdx.x;
    const int wid  = tid >> 5, lane = tid & 31;
    const int wm   = wid >> 2;
    const int wn   = wid & 3;
    const int bm   = blockIdx.y * 128, bn = blockIdx.x * 128;
    const int nch  = K >> 6;

    auto load_chunk = [&](int ci) {
        uint32_t buf = sb + (uint32_t)(ci & 1) * 32768u;
        const __nv_bfloat16* ap = A  + (size_t)bm * K + (size_t)ci * 64;
        const __nv_bfloat16* bp = Bt + (size_t)bn * K + (size_t)ci * 64;
#pragma unroll
        for (int c = 0; c < 4; c++) {
            int idx = tid * 4 + c;
            int row = idx >> 3, seg = idx & 7;
            uint32_t off = SWZ((uint32_t)(row * 128 + seg * 16));
            cp16(buf + off,          ap + (size_t)row * K + seg * 8);
            cp16(buf + 16384u + off, bp + (size_t)row * K + seg * 8);
        }
        asm volatile("cp.async.commit_group;");
    };

    load_chunk(0);
    if (nch > 1) load_chunk(1);

    float acc[4][4][4];
#pragma unroll
    for (int mi = 0; mi < 4; mi++)
#pragma unroll
        for (int ni = 0; ni < 4; ni++)
#pragma unroll
            for (int q = 0; q < 4; q++) acc[mi][ni][q] = 0.f;

    for (int ci = 0; ci < nch; ci++) {
        if (ci + 1 < nch) asm volatile("cp.async.wait_group 1;");
        else              asm volatile("cp.async.wait_group 0;");
        __syncthreads();

        uint32_t ab = sb + (uint32_t)(ci & 1) * 32768u;
        uint32_t bb = ab + 16384u;
#pragma unroll
        for (int ks = 0; ks < 4; ks++) {
            uint32_t af[4][4], bf[4][2];
#pragma unroll
            for (int mi = 0; mi < 4; mi++) {
                int row = wm * 64 + mi * 16 + (lane & 15);
                uint32_t addr = ab + SWZ((uint32_t)(row * 128 + ks * 32 + ((lane >> 4) << 4)));
                ldsm_x4(af[mi][0], af[mi][1], af[mi][2], af[mi][3], addr);
            }
#pragma unroll
            for (int p = 0; p < 2; p++) {
                int nr = wn * 32 + p * 16 + ((lane >> 4) << 3) + (lane & 7);
                uint32_t addr = bb + SWZ((uint32_t)(nr * 128 + ks * 32 + (((lane >> 3) & 1) << 4)));
                ldsm_x4(bf[p * 2][0], bf[p * 2][1], bf[p * 2 + 1][0], bf[p * 2 + 1][1], addr);
            }
#pragma unroll
            for (int mi = 0; mi < 4; mi++)
#pragma unroll
                for (int ni = 0; ni < 4; ni++)
                    mma16816(acc[mi][ni], af[mi], bf[ni]);
        }
        __syncthreads();
        if (ci + 2 < nch) load_chunk(ci + 2);
    }

    const int g = lane >> 2, tig = lane & 3;
#pragma unroll
    for (int mi = 0; mi < 4; mi++) {
#pragma unroll
        for (int ni = 0; ni < 4; ni++) {
            int r0 = bm + wm * 64 + mi * 16 + g;
            int c0 = bn + wn * 32 + ni * 8 + tig * 2;
            float* a4 = acc[mi][ni];
            if (MODE == 0) {
                *(float2*)(Cf + (size_t)r0 * N + c0)       = make_float2(a4[0], a4[1]);
                *(float2*)(Cf + (size_t)(r0 + 8) * N + c0) = make_float2(a4[2], a4[3]);
            } else if (MODE == 1) {
                float2* d0 = (float2*)(Cf + (size_t)r0 * N + c0);
                float2* d1 = (float2*)(Cf + (size_t)(r0 + 8) * N + c0);
                float2 o0 = *d0, o1 = *d1;
                o0.x += a4[0]; o0.y += a4[1];
                o1.x += a4[2]; o1.y += a4[3];
                *d0 = o0; *d1 = o1;
            } else if (MODE == 2) {
                *(__nv_bfloat162*)(Cb + (size_t)r0 * N + c0) =
                    __nv_bfloat162(__float2bfloat16(fmaxf(a4[0], 0.f)), __float2bfloat16(fmaxf(a4[1], 0.f)));
                *(__nv_bfloat162*)(Cb + (size_t)(r0 + 8) * N + c0) =
                    __nv_bfloat162(__float2bfloat16(fmaxf(a4[2], 0.f)), __float2bfloat16(fmaxf(a4[3], 0.f)));
            } else {
                *(__nv_bfloat162*)(Cb + (size_t)r0 * N + c0) =
                    __nv_bfloat162(__float2bfloat16(a4[0]), __float2bfloat16(a4[1]));
                *(__nv_bfloat162*)(Cb + (size_t)(r0 + 8) * N + c0) =
                    __nv_bfloat162(__float2bfloat16(a4[2]), __float2bfloat16(a4[3]));
            }
        }
    }
}

// ---------------- fp32 SGEMM ----------------
#define BM 128
#define BN 128
#define BK 8
__global__ void __launch_bounds__(256) sgemm_kernel(int M, int N, int K,
                                                    const float* __restrict__ A,
                                                    const float* __restrict__ B,
                                                    float* __restrict__ C,
                                                    const int* __restrict__ rowlim)
{
    if (rowlim && (int)(blockIdx.y * BM) >= *rowlim) return;
    __shared__ float As[BK][BM];
    __shared__ float Bs[BK][BN];
    const int tid = threadIdx.x;
    const int bm = blockIdx.y * BM, bn = blockIdx.x * BN;
    const int tx = tid & 15, ty = tid >> 4;
    float acc[8][8];
#pragma unroll
    for (int i = 0; i < 8; i++)
#pragma unroll
        for (int j = 0; j < 8; j++) acc[i][j] = 0.f;
    const int aRow = tid >> 1, aCol = (tid & 1) * 4;
    const int bRow = tid >> 5, bCol = (tid & 31) * 4;
    const float* Aptr = A + (size_t)(bm + aRow) * K + aCol;
    const float* Bptr = B + (size_t)bRow * N + bn + bCol;
    for (int k0 = 0; k0 < K; k0 += BK) {
        float4 av = *(const float4*)(Aptr + k0);
        float4 bv = *(const float4*)(Bptr + (size_t)k0 * N);
        As[aCol + 0][aRow] = av.x; As[aCol + 1][aRow] = av.y;
        As[aCol + 2][aRow] = av.z; As[aCol + 3][aRow] = av.w;
        *(float4*)&Bs[bRow][bCol] = bv;
        __syncthreads();
#pragma unroll
        for (int k = 0; k < BK; k++) {
            float a[8], b[8];
#pragma unroll
            for (int i = 0; i < 8; i++) a[i] = As[k][ty * 8 + i];
#pragma unroll
            for (int j = 0; j < 8; j++) b[j] = Bs[k][tx * 8 + j];
#pragma unroll
            for (int i = 0; i < 8; i++)
#pragma unroll
                for (int j = 0; j < 8; j++) acc[i][j] += a[i] * b[j];
        }
        __syncthreads();
    }
#pragma unroll
    for (int i = 0; i < 8; i++) {
        float* crow = C + (size_t)(bm + ty * 8 + i) * N + bn + tx * 8;
#pragma unroll
        for (int j = 0; j < 8; j += 4)
            *(float4*)(crow + j) = make_float4(acc[i][j], acc[i][j + 1], acc[i][j + 2], acc[i][j + 3]);
    }
}

// ---------------- PE add ----------------
__global__ void __launch_bounds__(256) pe_add_kernel(float* __restrict__ x)
{
    const int n = blockIdx.x;
    const int j = threadIdx.x;
    const int t = n & (TT - 1);
    double freq = exp(-(double)j * (9.210340371976184 / 256.0));
    double ang = (double)t * freq;
    float* p = x + (size_t)n * DD + 2 * j;
    p[0] += (float)sin(ang);
    p[1] += (float)cos(ang);
}

// ---------------- layernorm (full, templated out) ----------------
template <typename T>
__global__ void __launch_bounds__(256) ln_kernel(const float* __restrict__ in,
                                                 T* __restrict__ out,
                                                 const float* __restrict__ gam,
                                                 const float* __restrict__ bet)
{
    const int n = blockIdx.x;
    const int t = threadIdx.x;
    const float* row = in + (size_t)n * DD;
    float x0 = row[t], x1 = row[t + 256];
    __shared__ float s1[256], s2[256];
    s1[t] = x0 + x1;
    s2[t] = x0 * x0 + x1 * x1;
    __syncthreads();
    for (int o = 128; o > 0; o >>= 1) {
        if (t < o) { s1[t] += s1[t + o]; s2[t] += s2[t + o]; }
        __syncthreads();
    }
    float mean = s1[0] * (1.f / DD);
    float var = s2[0] * (1.f / DD) - mean * mean;
    float r = rsqrtf(var + 1e-5f);
    T* orow = out + (size_t)n * DD;
    orow[t]       = (T)((x0 - mean) * r * gam[t] + bet[t]);
    orow[t + 256] = (T)((x1 - mean) * r * gam[t + 256] + bet[t + 256]);
}

// ---------------- gathered layernorm over compact active rows ----------------
template <typename T>
__global__ void __launch_bounds__(256) gathln_kernel(const float* __restrict__ in,
                                                     T* __restrict__ out,
                                                     const float* __restrict__ gam,
                                                     const float* __restrict__ bet,
                                                     const int* __restrict__ actidx,
                                                     const int* __restrict__ nact,
                                                     const int* __restrict__ nactpad)
{
    const int i = blockIdx.x;
    if (i >= *nactpad) return;
    const int src = (i < *nact) ? actidx[i] : actidx[0];
    const int t = threadIdx.x;
    const float* row = in + (size_t)src * DD;
    float x0 = row[t], x1 = row[t + 256];
    __shared__ float s1[256], s2[256];
    s1[t] = x0 + x1;
    s2[t] = x0 * x0 + x1 * x1;
    __syncthreads();
    for (int o = 128; o > 0; o >>= 1) {
        if (t < o) { s1[t] += s1[t + o]; s2[t] += s2[t + o]; }
        __syncthreads();
    }
    float mean = s1[0] * (1.f / DD);
    float var = s2[0] * (1.f / DD) - mean * mean;
    float r = rsqrtf(var + 1e-5f);
    T* orow = out + (size_t)i * DD;
    orow[t]       = (T)((x0 - mean) * r * gam[t] + bet[t]);
    orow[t + 256] = (T)((x1 - mean) * r * gam[t + 256] + bet[t + 256]);
}

// ---------------- active-row scan (deterministic, one block) ----------------
__global__ void __launch_bounds__(1024) scan_kernel(const unsigned* __restrict__ mask,
                                                    const int* __restrict__ lens,
                                                    int* __restrict__ actidx,
                                                    int* __restrict__ nact,
                                                    int* __restrict__ nactpad)
{
    const int t = threadIdx.x;
    bool f[8];
    int cnt = 0;
#pragma unroll
    for (int j = 0; j < 8; j++) {
        int n = t * 8 + j;
        int b = n >> 10, tt = n & 1023;
        f[j] = (tt < lens[b]) && (mask[n] != 0u);
        cnt += f[j] ? 1 : 0;
    }
    __shared__ int sc[1024];
    sc[t] = cnt;
    __syncthreads();
    for (int o = 1; o < 1024; o <<= 1) {
        int v = (t >= o) ? sc[t - o] : 0;
        __syncthreads();
        sc[t] += v;
        __syncthreads();
    }
    int pos = sc[t] - cnt;
#pragma unroll
    for (int j = 0; j < 8; j++)
        if (f[j]) actidx[pos++] = t * 8 + j;
    if (t == 1023) {
        int tot = sc[1023];
        *nact = tot;
        int pad = (tot + 127) & ~127;
        if (pad == 0) pad = 128;
        *nactpad = pad;
    }
}

// ---------------- mask mix ----------------
__global__ void __launch_bounds__(256) maskmix_kernel(const float* __restrict__ x,
                                                      const unsigned* __restrict__ mask,
                                                      const float* __restrict__ memb,
                                                      float* __restrict__ out)
{
    int idx = blockIdx.x * 256 + threadIdx.x;
    int n = idx >> 9, d = idx & 511;
    out[idx] = (mask[n] != 0u) ? memb[d] : x[idx];
}

// ---------------- codebook column norms ----------------
__global__ void __launch_bounds__(256) enorm_kernel(const float* __restrict__ emb,
                                                    float* __restrict__ enorm)
{
    int v = blockIdx.x * 256 + threadIdx.x;
    float s = 0.f;
    for (int e = 0; e < DD; e++) {
        float x = emb[(size_t)e * VV + v];
        s += x * x;
    }
    enorm[v] = s;
}

// ---------------- argmin over compact rows ----------------
__global__ void __launch_bounds__(256) argmin_kernel(const float* __restrict__ big,
                                                     const float* __restrict__ enorm,
                                                     int* __restrict__ tgt,
                                                     const int* __restrict__ nact)
{
    const int n = blockIdx.x;
    if (n >= *nact) return;
    const float* row = big + (size_t)n * VV;
    const int tid = threadIdx.x;
    float best = 3.4e38f;
    int bi = 0;
    for (int v = tid; v < VV; v += 256) {
        float sc = enorm[v] - 2.f * row[v];
        if (sc < best) { best = sc; bi = v; }
    }
    __shared__ float bv[256];
    __shared__ int bix[256];
    bv[tid] = best; bix[tid] = bi;
    __syncthreads();
    for (int o = 128; o > 0; o >>= 1) {
        if (tid < o) {
            if (bv[tid + o] < bv[tid] || (bv[tid + o] == bv[tid] && bix[tid + o] < bix[tid])) {
                bv[tid] = bv[tid + o]; bix[tid] = bix[tid + o];
            }
        }
        __syncthreads();
    }
    if (tid == 0) tgt[n] = bix[0];
}

// ---------------- weight transpose-convert ----------------
__global__ void __launch_bounds__(256) tconv_kernel(const float* __restrict__ W,
                                                    __nv_bfloat16* __restrict__ Wt,
                                                    int K, int N)
{
    W  += (size_t)blockIdx.z * K * N;
    Wt += (size_t)blockIdx.z * K * N;
    __shared__ float tile[32][33];
    int n0 = blockIdx.x * 32, k0 = blockIdx.y * 32;
    int tx = threadIdx.x & 31, ty = threadIdx.x >> 5;
#pragma unroll
    for (int i = 0; i < 32; i += 8)
        tile[ty + i][tx] = W[(size_t)(k0 + ty + i) * N + n0 + tx];
    __syncthreads();
#pragma unroll
    for (int i = 0; i < 32; i += 8)
        Wt[(size_t)(n0 + ty + i) * K + k0 + tx] = __float2bfloat16(tile[tx][ty + i]);
}

// ---------------- embedding transpose + hi/lo split ----------------
__global__ void __launch_bounds__(256) embsplit_kernel(const float* __restrict__ emb,
                                                       __nv_bfloat16* __restrict__ embt)
{
    __shared__ float tile[32][33];
    int v0 = blockIdx.x * 32, e0 = blockIdx.y * 32;
    int tx = threadIdx.x & 31, ty = threadIdx.x >> 5;
#pragma unroll
    for (int i = 0; i < 32; i += 8)
        tile[ty + i][tx] = emb[(size_t)(e0 + ty + i) * VV + v0 + tx];
    __syncthreads();
#pragma unroll
    for (int i = 0; i < 32; i += 8) {
        float a = tile[tx][ty + i];
        int v = v0 + ty + i, e = e0 + tx;
        __nv_bfloat16 hi = __float2bfloat16(a);
        __nv_bfloat16 lo = __float2bfloat16(a - __bfloat162float(hi));
        size_t base = (size_t)v * KSP;
        embt[base + e] = hi;
        embt[base + DD + e] = lo;
        embt[base + 2 * DD + e] = hi;
    }
}

// ---------------- z hi/lo split (compact rows) ----------------
__global__ void __launch_bounds__(256) zsplit_kernel(const float* __restrict__ z,
                                                     __nv_bfloat16* __restrict__ zs,
                                                     const int* __restrict__ nactpad)
{
    int idx = blockIdx.x * 256 + threadIdx.x;
    int n = idx >> 9, e = idx & 511;
    if (n >= *nactpad) return;
    float a = z[idx];
    __nv_bfloat16 hi = __float2bfloat16(a);
    __nv_bfloat16 lo = __float2bfloat16(a - __bfloat162float(hi));
    size_t base = (size_t)n * KSP;
    zs[base + e] = hi;
    zs[base + DD + e] = hi;
    zs[base + 2 * DD + e] = lo;
}

// =======================================================================
// bf16 HMMA flash attention: block = (b, h, 64-q tile), 4 warps
// qkvb layout: [tok][1536] = Q|K|V, each head h at offset h*64 (+0/512/1024)
// =======================================================================
__global__ void __launch_bounds__(128) attnmma_kernel(const __nv_bfloat16* __restrict__ qkvb,
                                                      const int* __restrict__ lens,
                                                      __nv_bfloat16* __restrict__ out)
{
    const int b = blockIdx.z, h = blockIdx.y, q0 = blockIdx.x * 64;
    const int tid = threadIdx.x;
    const int wid = tid >> 5, lane = tid & 31;
    const int len = lens[b];
    const int ktmax = (len + 63) >> 6;

    __shared__ __align__(128) __nv_bfloat16 Qs[64 * 64];
    __shared__ __align__(128) __nv_bfloat16 Ks[64 * 64];
    __shared__ __align__(128) __nv_bfloat16 Vt[64 * 64];   // [d][key]
    const uint32_t sq = smem_u32(Qs), sk = smem_u32(Ks), sv = smem_u32(Vt);

    // load Q tile (64 rows x 128B)
    {
        const __nv_bfloat16* base = qkvb + (size_t)(b * TT + q0) * (3 * DD) + h * HD;
#pragma unroll
        for (int c = 0; c < 4; c++) {
            int idx = tid * 4 + c;              // 0..511
            int row = idx >> 3, seg = idx & 7;
            cp16(sq + SWZ((uint32_t)(row * 128 + seg * 16)), base + (size_t)row * (3 * DD) + seg * 8);
        }
        asm volatile("cp.async.commit_group;");
        asm volatile("cp.async.wait_group 0;");
        __syncthreads();
    }

    // Q fragments: warp owns rows wid*16..+15
    uint32_t af[4][4];
#pragma unroll
    for (int ks = 0; ks < 4; ks++) {
        int row = wid * 16 + (lane & 15);
        uint32_t addr = sq + SWZ((uint32_t)(row * 128 + ks * 32 + ((lane >> 4) << 4)));
        ldsm_x4(af[ks][0], af[ks][1], af[ks][2], af[ks][3], addr);
    }

    float m0 = -1e30f, m1 = -1e30f, l0 = 0.f, l1 = 0.f;
    float oacc[8][4];
#pragma unroll
    for (int nb = 0; nb < 8; nb++)
#pragma unroll
        for (int q = 0; q < 4; q++) oacc[nb][q] = 0.f;

    const int g = lane >> 2, tq = lane & 3;

    for (int kt = 0; kt < ktmax; kt++) {
        __syncthreads();   // previous iteration done with Ks/Vt
        // load K tile
        {
            const __nv_bfloat16* base = qkvb + (size_t)(b * TT + kt * 64) * (3 * DD) + DD + h * HD;
#pragma unroll
            for (int c = 0; c < 4; c++) {
                int idx = tid * 4 + c;
                int row = idx >> 3, seg = idx & 7;
                cp16(sk + SWZ((uint32_t)(row * 128 + seg * 16)), base + (size_t)row * (3 * DD) + seg * 8);
            }
            asm volatile("cp.async.commit_group;");
        }
        // load V tile transposed -> Vt[d][key]
        {
            const __nv_bfloat16* base = qkvb + (size_t)(b * TT + kt * 64) * (3 * DD) + 2 * DD + h * HD;
#pragma unroll
            for (int c = 0; c < 4; c++) {
                int idx = tid * 4 + c;
                int key = idx >> 3, dseg = idx & 7;
                uint4 v = *(const uint4*)(base + (size_t)key * (3 * DD) + dseg * 8);
                const __nv_bfloat16* e = (const __nv_bfloat16*)&v;
#pragma unroll
                for (int j = 0; j < 8; j++) {
                    int d = dseg * 8 + j;
                    *(__nv_bfloat16*)((char*)Vt + SWZ((uint32_t)(d * 128 + key * 2))) = e[j];
                }
            }
        }
        asm volatile("cp.async.wait_group 0;");
        __syncthreads();

        // S = Q @ K^T   (16 q x 64 keys per warp)
        float s[8][4];
#pragma unroll
        for (int nb = 0; nb < 8; nb++)
#pragma unroll
            for (int q = 0; q < 4; q++) s[nb][q] = 0.f;
#pragma unroll
        for (int ks = 0; ks < 4; ks++) {
            uint32_t bf[8][2];
#pragma unroll
            for (int p = 0; p < 4; p++) {
                int nr = p * 16 + ((lane >> 4) << 3) + (lane & 7);
                uint32_t addr = sk + SWZ((uint32_t)(nr * 128 + ks * 32 + (((lane >> 3) & 1) << 4)));
                ldsm_x4(bf[p * 2][0], bf[p * 2][1], bf[p * 2 + 1][0], bf[p * 2 + 1][1], addr);
            }
#pragma unroll
            for (int nb = 0; nb < 8; nb++)
                mma16816(s[nb], af[ks], bf[nb]);
        }

        // scale + key mask
#pragma unroll
        for (int nb = 0; nb < 8; nb++) {
            int k0c = kt * 64 + nb * 8 + tq * 2;
            float ba = (k0c < len) ? 0.f : -1e9f;
            float bb2 = (k0c + 1 < len) ? 0.f : -1e9f;
            s[nb][0] = s[nb][0] * 0.125f + ba;
            s[nb][1] = s[nb][1] * 0.125f + bb2;
            s[nb][2] = s[nb][2] * 0.125f + ba;
            s[nb][3] = s[nb][3] * 0.125f + bb2;
        }

        // row maxes (rows g and g+8)
        float mt0 = -1e30f, mt1 = -1e30f;
#pragma unroll
        for (int nb = 0; nb < 8; nb++) {
            mt0 = fmaxf(mt0, fmaxf(s[nb][0], s[nb][1]));
            mt1 = fmaxf(mt1, fmaxf(s[nb][2], s[nb][3]));
        }
        mt0 = fmaxf(mt0, __shfl_xor_sync(0xffffffffu, mt0, 1));
        mt0 = fmaxf(mt0, __shfl_xor_sync(0xffffffffu, mt0, 2));
        mt1 = fmaxf(mt1, __shfl_xor_sync(0xffffffffu, mt1, 1));
        mt1 = fmaxf(mt1, __shfl_xor_sync(0xffffffffu, mt1, 2));

        float mn0 = fmaxf(m0, mt0), mn1 = fmaxf(m1, mt1);
        float a0 = __expf(m0 - mn0), a1 = __expf(m1 - mn1);
        m0 = mn0; m1 = mn1;

        float r0 = 0.f, r1 = 0.f;
#pragma unroll
        for (int nb = 0; nb < 8; nb++) {
            s[nb][0] = __expf(s[nb][0] - m0);
            s[nb][1] = __expf(s[nb][1] - m0);
            s[nb][2] = __expf(s[nb][2] - m1);
            s[nb][3] = __expf(s[nb][3] - m1);
            r0 += s[nb][0] + s[nb][1];
            r1 += s[nb][2] + s[nb][3];
        }
        r0 += __shfl_xor_sync(0xffffffffu, r0, 1);
        r0 += __shfl_xor_sync(0xffffffffu, r0, 2);
        r1 += __shfl_xor_sync(0xffffffffu, r1, 1);
        r1 += __shfl_xor_sync(0xffffffffu, r1, 2);
        l0 = l0 * a0 + r0;
        l1 = l1 * a1 + r1;

        // rescale O
#pragma unroll
        for (int nb = 0; nb < 8; nb++) {
            oacc[nb][0] *= a0; oacc[nb][1] *= a0;
            oacc[nb][2] *= a1; oacc[nb][3] *= a1;
        }

        // repack P to A-fragments (k = keys)
        uint32_t ap[4][4];
#pragma unroll
        for (int kk = 0; kk < 4; kk++) {
            ap[kk][0] = packbf(s[2 * kk][0],     s[2 * kk][1]);
            ap[kk][1] = packbf(s[2 * kk][2],     s[2 * kk][3]);
            ap[kk][2] = packbf(s[2 * kk + 1][0], s[2 * kk + 1][1]);
            ap[kk][3] = packbf(s[2 * kk + 1][2], s[2 * kk + 1][3]);
        }

        // O += P @ V   (Vt as Bt[n=d][k=key])
#pragma unroll
        for (int kk = 0; kk < 4; kk++) {
            uint32_t bfv[8][2];
#pragma unroll
            for (int p = 0; p < 4; p++) {
                int nr = p * 16 + ((lane >> 4) << 3) + (lane & 7);
                uint32_t addr = sv + SWZ((uint32_t)(nr * 128 + kk * 32 + (((lane >> 3) & 1) << 4)));
                ldsm_x4(bfv[p * 2][0], bfv[p * 2][1], bfv[p * 2 + 1][0], bfv[p * 2 + 1][1], addr);
            }
#pragma unroll
            for (int nb = 0; nb < 8; nb++)
                mma16816(oacc[nb], ap[kk], bfv[nb]);
        }
    }

    // write out
    float i0 = 1.f / l0, i1 = 1.f / l1;
    int row0 = b * TT + q0 + wid * 16 + g;
#pragma unroll
    for (int nb = 0; nb < 8; nb++) {
        int col = h * HD + nb * 8 + tq * 2;
        *(__nv_bfloat162*)(out + (size_t)row0 * DD + col) =
            __nv_bfloat162(__float2bfloat16(oacc[nb][0] * i0), __float2bfloat16(oacc[nb][1] * i0));
        *(__nv_bfloat162*)(out + (size_t)(row0 + 8) * DD + col) =
            __nv_bfloat162(__float2bfloat16(oacc[nb][2] * i1), __float2bfloat16(oacc[nb][3] * i1));
    }
}

// ---------------- compact row loss ----------------
__global__ void __launch_bounds__(256) rowloss_kernel(const float* __restrict__ big,
                                                      const int* __restrict__ tgt,
                                                      const int* __restrict__ nact,
                                                      float* __restrict__ ent)
{
    const int n = blockIdx.x;
    if (n >= *nact) return;
    const float* row = big + (size_t)n * VV;
    const int tid = threadIdx.x;
    float mx = -1e30f;
    for (int v = tid; v < VV; v += 256) mx = fmaxf(mx, row[v]);
    __shared__ float sm[256];
    sm[tid] = mx;
    __syncthreads();
    for (int o = 128; o > 0; o >>= 1) {
        if (tid < o) sm[tid] = fmaxf(sm[tid], sm[tid + o]);
        __syncthreads();
    }
    mx = sm[0];
    __syncthreads();
    float s = 0.f;
    for (int v = tid; v < VV; v += 256) s += __expf(row[v] - mx);
    sm[tid] = s;
    __syncthreads();
    for (int o = 128; o > 0; o >>= 1) {
        if (tid < o) sm[tid] += sm[tid + o];
        __syncthreads();
    }
    if (tid == 0) ent[n] = mx + logf(sm[0]) - row[tgt[n]];
}

__global__ void __launch_bounds__(1024) finalize_kernel(const float* __restrict__ ent,
                                                        const int* __restrict__ nact,
                                                        float* __restrict__ out)
{
    const int tid = threadIdx.x;
    const int N = *nact;
    float s = 0.f;
    for (int n = tid; n < N; n += 1024) s += ent[n];
    __shared__ float ss[1024];
    ss[tid] = s;
    __syncthreads();
    for (int o = 512; o > 0; o >>= 1) {
        if (tid < o) ss[tid] += ss[tid + o];
        __syncthreads();
    }
    if (tid == 0) out[0] = ss[0] / (float)N;
}

// ---------------- host ----------------
extern "C" void kernel_launch(void* const* d_in, const int* in_sizes, int n_in,
                              void* d_out, int out_size)
{
    (void)in_sizes; (void)n_in; (void)out_size;
    const float*    xs    = (const float*)d_in[0];
    const int*      lens  = (const int*)d_in[1];
    const unsigned* mask  = (const unsigned*)d_in[2];
    const float*    W_emb = (const float*)d_in[3];
    const float*    ln1_s = (const float*)d_in[4];
    const float*    ln1_b = (const float*)d_in[5];
    const float*    Wqkv  = (const float*)d_in[6];
    const float*    Wo    = (const float*)d_in[7];
    const float*    ln2_s = (const float*)d_in[8];
    const float*    ln2_b = (const float*)d_in[9];
    const float*    W1    = (const float*)d_in[10];
    const float*    W2    = (const float*)d_in[11];
    const float*    an_s  = (const float*)d_in[12];
    const float*    an_b  = (const float*)d_in[13];
    const float*    iln_s = (const float*)d_in[14];
    const float*    iln_b = (const float*)d_in[15];
    const float*    memb  = (const float*)d_in[16];
    const float*    top   = (const float*)d_in[17];
    const float*    proj  = (const float*)d_in[18];
    const float*    emb   = (const float*)d_in[19];

    float *px, *pres, *ph, *pz, *pbig, *penorm, *pent;
    int *ptgt, *pactidx, *pnact, *pnactpad;
    __nv_bfloat16 *phb, *pqkvb, *pattnb, *pffnb, *pzs, *pembt, *pwqkvt, *pwot, *pw1t, *pw2t, *ptopt;
    cudaGetSymbolAddress((void**)&px, g_x);
    cudaGetSymbolAddress((void**)&pres, g_res);
    cudaGetSymbolAddress((void**)&ph, g_h);
    cudaGetSymbolAddress((void**)&pz, g_z);
    cudaGetSymbolAddress((void**)&pbig, g_big);
    cudaGetSymbolAddress((void**)&penorm, g_enorm);
    cudaGetSymbolAddress((void**)&pent, g_ent);
    cudaGetSymbolAddress((void**)&ptgt, g_tgt);
    cudaGetSymbolAddress((void**)&pactidx, g_actidx);
    cudaGetSymbolAddress((void**)&pnact, g_nact);
    cudaGetSymbolAddress((void**)&pnactpad, g_nactpad);
    cudaGetSymbolAddress((void**)&phb, g_hb);
    cudaGetSymbolAddress((void**)&pqkvb, g_qkvb);
    cudaGetSymbolAddress((void**)&pattnb, g_attnb);
    cudaGetSymbolAddress((void**)&pffnb, g_ffnb);
    cudaGetSymbolAddress((void**)&pzs, g_zs);
    cudaGetSymbolAddress((void**)&pembt, g_embt);
    cudaGetSymbolAddress((void**)&pwqkvt, g_wqkvt);
    cudaGetSymbolAddress((void**)&pwot, g_wot);
    cudaGetSymbolAddress((void**)&pw1t, g_w1t);
    cudaGetSymbolAddress((void**)&pw2t, g_w2t);
    cudaGetSymbolAddress((void**)&ptopt, g_topt);

    cudaFuncSetAttribute(hgemm_kernel<0>, cudaFuncAttributeMaxDynamicSharedMemorySize, HG_SMEM);
    cudaFuncSetAttribute(hgemm_kernel<1>, cudaFuncAttributeMaxDynamicSharedMemorySize, HG_SMEM);
    cudaFuncSetAttribute(hgemm_kernel<2>, cudaFuncAttributeMaxDynamicSharedMemorySize, HG_SMEM);
    cudaFuncSetAttribute(hgemm_kernel<3>, cudaFuncAttributeMaxDynamicSharedMemorySize, HG_SMEM);

    dim3 tb(256);

    // ---- weight prep ----
    tconv_kernel<<<dim3(3 * DD / 32, DD / 32, LL), tb>>>(Wqkv, pwqkvt, DD, 3 * DD);
    tconv_kernel<<<dim3(DD / 32, DD / 32, LL), tb>>>(Wo, pwot, DD, DD);
    tconv_kernel<<<dim3(FF / 32, DD / 32, LL), tb>>>(W1, pw1t, DD, FF);
    tconv_kernel<<<dim3(DD / 32, FF / 32, LL), tb>>>(W2, pw2t, FF, DD);
    tconv_kernel<<<dim3(VV / 32, DD / 32, 1), tb>>>(top, ptopt, DD, VV);
    embsplit_kernel<<<dim3(VV / 32, DD / 32), tb>>>(emb, pembt);
    enorm_kernel<<<VV / 256, tb>>>(emb, penorm);

    // ---- active-row compaction ----
    scan_kernel<<<1, 1024>>>(mask, lens, pactidx, pnact, pnactpad);

    // ---- 1. embed (fp32) + PE ----
    sgemm_kernel<<<dim3(DD / BN, NTOK / BM), tb>>>(NTOK, DD, DD, xs, W_emb, px, nullptr);
    pe_add_kernel<<<NTOK, tb>>>(px);

    // ---- 2. targets on ACTIVE rows only ----
    gathln_kernel<float><<<NTOK, tb>>>(px, ph, iln_s, iln_b, pactidx, pnact, pnactpad);
    sgemm_kernel<<<dim3(DD / BN, NTOK / BM), tb>>>(NTOK, DD, DD, ph, proj, pz, pnactpad);
    zsplit_kernel<<<(NTOK * DD) / 256, tb>>>(pz, pzs, pnactpad);
    hgemm_kernel<0><<<dim3(VV / 128, NTOK / 128), 256, HG_SMEM>>>(NTOK, VV, KSP, pzs, pembt, pbig, nullptr, pnactpad);
    argmin_kernel<<<NTOK, tb>>>(pbig, penorm, ptgt, pnact);

    // ---- 3. masked stream ----
    maskmix_kernel<<<(NTOK * DD) / 256, tb>>>(px, mask, memb, pres);

    // ---- 4. encoder ----
    for (int l = 0; l < LL; l++) {
        ln_kernel<__nv_bfloat16><<<NTOK, tb>>>(pres, phb, ln1_s + l * DD, ln1_b + l * DD);
        hgemm_kernel<3><<<dim3(3 * DD / 128, NTOK / 128), 256, HG_SMEM>>>(NTOK, 3 * DD, DD,
                phb, pwqkvt + (size_t)l * 3 * DD * DD, nullptr, pqkvb, nullptr);
        attnmma_kernel<<<dim3(TT / 64, HH, 8), 128>>>(pqkvb, lens, pattnb);
        hgemm_kernel<1><<<dim3(DD / 128, NTOK / 128), 256, HG_SMEM>>>(NTOK, DD, DD,
                pattnb, pwot + (size_t)l * DD * DD, pres, nullptr, nullptr);
        ln_kernel<__nv_bfloat16><<<NTOK, tb>>>(pres, phb, ln2_s + l * DD, ln2_b + l * DD);
        hgemm_kernel<2><<<dim3(FF / 128, NTOK / 128), 256, HG_SMEM>>>(NTOK, FF, DD,
                phb, pw1t + (size_t)l * FF * DD, nullptr, pffnb, nullptr);
        hgemm_kernel<1><<<dim3(DD / 128, NTOK / 128), 256, HG_SMEM>>>(NTOK, DD, FF,
                pffnb, pw2t + (size_t)l * DD * FF, pres, nullptr, nullptr);
    }

    // ---- 5. final LN + logits + loss on ACTIVE rows only ----
    gathln_kernel<__nv_bfloat16><<<NTOK, tb>>>(pres, phb, an_s, an_b, pactidx, pnact, pnactpad);
    hgemm_kernel<0><<<dim3(VV / 128, NTOK / 128), 256, HG_SMEM>>>(NTOK, VV, DD, phb, ptopt, pbig, nullptr, pnactpad);
    rowloss_kernel<<<NTOK, tb>>>(pbig, ptgt, pnact, pent);
    finalize_kernel<<<1, 1024>>>(pent, pnact, (float*)d_out);
}

// round 10
// speedup vs baseline: 5.7756x; 1.0033x over previous
#include <cuda_runtime.h>
#include <cuda_bf16.h>
#include <math.h>
#include <stdint.h>

// ---------------- model dims ----------------
#define NTOK 8192
#define TT   1024
#define DD   512
#define FF   2048
#define VV   8192
#define HH   8
#define HD   64
#define LL   6
#define KSP  1536

// ---------------- scratch ----------------
__device__ float g_x   [NTOK * DD];
__device__ float g_res [NTOK * DD];
__device__ float g_h   [NTOK * DD];
__device__ float g_z   [NTOK * DD];
__device__ float g_big [(size_t)NTOK * VV];
__device__ float g_enorm[VV];
__device__ int   g_tgt [NTOK];
__device__ float g_ent [NTOK];
__device__ int   g_actidx[NTOK];
__device__ int   g_nact;
__device__ int   g_nactpad;
__device__ __nv_bfloat16 g_hb   [NTOK * DD];
__device__ __nv_bfloat16 g_qkvb [NTOK * 3 * DD];
__device__ __nv_bfloat16 g_attnb[NTOK * DD];
__device__ __nv_bfloat16 g_ffnb [NTOK * FF];
__device__ __nv_bfloat16 g_zs   [(size_t)NTOK * KSP];
__device__ __nv_bfloat16 g_embt [(size_t)VV * KSP];
__device__ __nv_bfloat16 g_wqkvt[LL * 3 * DD * DD];
__device__ __nv_bfloat16 g_wot  [LL * DD * DD];
__device__ __nv_bfloat16 g_w1t  [LL * FF * DD];
__device__ __nv_bfloat16 g_w2t  [LL * DD * FF];
__device__ __nv_bfloat16 g_topt [VV * DD];

// ---------------- helpers ----------------
__device__ __forceinline__ uint32_t smem_u32(const void* p) {
    uint32_t a;
    asm("{ .reg .u64 t; cvta.to.shared.u64 t, %1; cvt.u32.u64 %0, t; }" : "=r"(a) : "l"(p));
    return a;
}
__device__ __forceinline__ void cp16(uint32_t dst, const void* src) {
    asm volatile("cp.async.cg.shared.global [%0], [%1], 16;" :: "r"(dst), "l"(src));
}
__device__ __forceinline__ void ldsm_x4(uint32_t& r0, uint32_t& r1, uint32_t& r2, uint32_t& r3, uint32_t addr) {
    asm volatile("ldmatrix.sync.aligned.m8n8.x4.shared.b16 {%0,%1,%2,%3}, [%4];"
                 : "=r"(r0), "=r"(r1), "=r"(r2), "=r"(r3) : "r"(addr));
}
__device__ __forceinline__ void ldsm_x4_t(uint32_t& r0, uint32_t& r1, uint32_t& r2, uint32_t& r3, uint32_t addr) {
    asm volatile("ldmatrix.sync.aligned.m8n8.x4.trans.shared.b16 {%0,%1,%2,%3}, [%4];"
                 : "=r"(r0), "=r"(r1), "=r"(r2), "=r"(r3) : "r"(addr));
}
__device__ __forceinline__ void mma16816(float* d, const uint32_t* a, const uint32_t* b) {
    asm volatile("mma.sync.aligned.m16n8k16.row.col.f32.bf16.bf16.f32 "
                 "{%0,%1,%2,%3}, {%4,%5,%6,%7}, {%8,%9}, {%0,%1,%2,%3};"
                 : "+f"(d[0]), "+f"(d[1]), "+f"(d[2]), "+f"(d[3])
                 : "r"(a[0]), "r"(a[1]), "r"(a[2]), "r"(a[3]), "r"(b[0]), "r"(b[1]));
}
__device__ __forceinline__ uint32_t packbf(float a, float b) {
    __nv_bfloat162 t(__float2bfloat16(a), __float2bfloat16(b));
    return *(uint32_t*)&t;
}
#define SWZ(o) ((o) ^ (((o) >> 3) & 0x70))

// =======================================================================
// bf16 HMMA GEMM, 3-stage cp.async pipeline.
// MODE 0: fp32 store; 1: fp32 +=; 2: bf16 relu; 3: bf16 store
// =======================================================================
#define HG_SMEM (3 * 32768)

template <int MODE>
__global__ void __launch_bounds__(256) hgemm_kernel(int M, int N, int K,
                                                    const __nv_bfloat16* __restrict__ A,
                                                    const __nv_bfloat16* __restrict__ Bt,
                                                    float* __restrict__ Cf,
                                                    __nv_bfloat16* __restrict__ Cb,
                                                    const int* __restrict__ rowlim)
{
    if (rowlim && (int)(blockIdx.y * 128) >= *rowlim) return;
    extern __shared__ char smem[];
    const uint32_t sb = smem_u32(smem);
    const int tid  = threadIdx.x;
    const int wid  = tid >> 5, lane = tid & 31;
    const int wm   = wid >> 2;
    const int wn   = wid & 3;
    const int bm   = blockIdx.y * 128, bn = blockIdx.x * 128;
    const int nch  = K >> 6;

    auto load_chunk = [&](int ci) {
        uint32_t buf = sb + (uint32_t)(ci % 3) * 32768u;
        const __nv_bfloat16* ap = A  + (size_t)bm * K + (size_t)ci * 64;
        const __nv_bfloat16* bp = Bt + (size_t)bn * K + (size_t)ci * 64;
#pragma unroll
        for (int c = 0; c < 4; c++) {
            int idx = tid * 4 + c;
            int row = idx >> 3, seg = idx & 7;
            uint32_t off = SWZ((uint32_t)(row * 128 + seg * 16));
            cp16(buf + off,          ap + (size_t)row * K + seg * 8);
            cp16(buf + 16384u + off, bp + (size_t)row * K + seg * 8);
        }
        asm volatile("cp.async.commit_group;");
    };

    load_chunk(0);
    if (nch > 1) load_chunk(1);
    if (nch > 2) load_chunk(2);

    float acc[4][4][4];
#pragma unroll
    for (int mi = 0; mi < 4; mi++)
#pragma unroll
        for (int ni = 0; ni < 4; ni++)
#pragma unroll
            for (int q = 0; q < 4; q++) acc[mi][ni][q] = 0.f;

    for (int ci = 0; ci < nch; ci++) {
        if (ci + 3 <= nch)      asm volatile("cp.async.wait_group 2;");
        else if (ci + 2 == nch) asm volatile("cp.async.wait_group 1;");
        else                    asm volatile("cp.async.wait_group 0;");
        __syncthreads();

        uint32_t ab = sb + (uint32_t)(ci % 3) * 32768u;
        uint32_t bb = ab + 16384u;
#pragma unroll
        for (int ks = 0; ks < 4; ks++) {
            uint32_t af[4][4], bf[4][2];
#pragma unroll
            for (int mi = 0; mi < 4; mi++) {
                int row = wm * 64 + mi * 16 + (lane & 15);
                uint32_t addr = ab + SWZ((uint32_t)(row * 128 + ks * 32 + ((lane >> 4) << 4)));
                ldsm_x4(af[mi][0], af[mi][1], af[mi][2], af[mi][3], addr);
            }
#pragma unroll
            for (int p = 0; p < 2; p++) {
                int nr = wn * 32 + p * 16 + ((lane >> 4) << 3) + (lane & 7);
                uint32_t addr = bb + SWZ((uint32_t)(nr * 128 + ks * 32 + (((lane >> 3) & 1) << 4)));
                ldsm_x4(bf[p * 2][0], bf[p * 2][1], bf[p * 2 + 1][0], bf[p * 2 + 1][1], addr);
            }
#pragma unroll
            for (int mi = 0; mi < 4; mi++)
#pragma unroll
                for (int ni = 0; ni < 4; ni++)
                    mma16816(acc[mi][ni], af[mi], bf[ni]);
        }
        __syncthreads();
        if (ci + 3 < nch) load_chunk(ci + 3);
    }

    const int g = lane >> 2, tig = lane & 3;
#pragma unroll
    for (int mi = 0; mi < 4; mi++) {
#pragma unroll
        for (int ni = 0; ni < 4; ni++) {
            int r0 = bm + wm * 64 + mi * 16 + g;
            int c0 = bn + wn * 32 + ni * 8 + tig * 2;
            float* a4 = acc[mi][ni];
            if (MODE == 0) {
                *(float2*)(Cf + (size_t)r0 * N + c0)       = make_float2(a4[0], a4[1]);
                *(float2*)(Cf + (size_t)(r0 + 8) * N + c0) = make_float2(a4[2], a4[3]);
            } else if (MODE == 1) {
                float2* d0 = (float2*)(Cf + (size_t)r0 * N + c0);
                float2* d1 = (float2*)(Cf + (size_t)(r0 + 8) * N + c0);
                float2 o0 = *d0, o1 = *d1;
                o0.x += a4[0]; o0.y += a4[1];
                o1.x += a4[2]; o1.y += a4[3];
                *d0 = o0; *d1 = o1;
            } else if (MODE == 2) {
                *(__nv_bfloat162*)(Cb + (size_t)r0 * N + c0) =
                    __nv_bfloat162(__float2bfloat16(fmaxf(a4[0], 0.f)), __float2bfloat16(fmaxf(a4[1], 0.f)));
                *(__nv_bfloat162*)(Cb + (size_t)(r0 + 8) * N + c0) =
                    __nv_bfloat162(__float2bfloat16(fmaxf(a4[2], 0.f)), __float2bfloat16(fmaxf(a4[3], 0.f)));
            } else {
                *(__nv_bfloat162*)(Cb + (size_t)r0 * N + c0) =
                    __nv_bfloat162(__float2bfloat16(a4[0]), __float2bfloat16(a4[1]));
                *(__nv_bfloat162*)(Cb + (size_t)(r0 + 8) * N + c0) =
                    __nv_bfloat162(__float2bfloat16(a4[2]), __float2bfloat16(a4[3]));
            }
        }
    }
}

// ---------------- fp32 SGEMM ----------------
#define BM 128
#define BN 128
#define BK 8
__global__ void __launch_bounds__(256) sgemm_kernel(int M, int N, int K,
                                                    const float* __restrict__ A,
                                                    const float* __restrict__ B,
                                                    float* __restrict__ C,
                                                    const int* __restrict__ rowlim)
{
    if (rowlim && (int)(blockIdx.y * BM) >= *rowlim) return;
    __shared__ float As[BK][BM];
    __shared__ float Bs[BK][BN];
    const int tid = threadIdx.x;
    const int bm = blockIdx.y * BM, bn = blockIdx.x * BN;
    const int tx = tid & 15, ty = tid >> 4;
    float acc[8][8];
#pragma unroll
    for (int i = 0; i < 8; i++)
#pragma unroll
        for (int j = 0; j < 8; j++) acc[i][j] = 0.f;
    const int aRow = tid >> 1, aCol = (tid & 1) * 4;
    const int bRow = tid >> 5, bCol = (tid & 31) * 4;
    const float* Aptr = A + (size_t)(bm + aRow) * K + aCol;
    const float* Bptr = B + (size_t)bRow * N + bn + bCol;
    for (int k0 = 0; k0 < K; k0 += BK) {
        float4 av = *(const float4*)(Aptr + k0);
        float4 bv = *(const float4*)(Bptr + (size_t)k0 * N);
        As[aCol + 0][aRow] = av.x; As[aCol + 1][aRow] = av.y;
        As[aCol + 2][aRow] = av.z; As[aCol + 3][aRow] = av.w;
        *(float4*)&Bs[bRow][bCol] = bv;
        __syncthreads();
#pragma unroll
        for (int k = 0; k < BK; k++) {
            float a[8], b[8];
#pragma unroll
            for (int i = 0; i < 8; i++) a[i] = As[k][ty * 8 + i];
#pragma unroll
            for (int j = 0; j < 8; j++) b[j] = Bs[k][tx * 8 + j];
#pragma unroll
            for (int i = 0; i < 8; i++)
#pragma unroll
                for (int j = 0; j < 8; j++) acc[i][j] += a[i] * b[j];
        }
        __syncthreads();
    }
#pragma unroll
    for (int i = 0; i < 8; i++) {
        float* crow = C + (size_t)(bm + ty * 8 + i) * N + bn + tx * 8;
#pragma unroll
        for (int j = 0; j < 8; j += 4)
            *(float4*)(crow + j) = make_float4(acc[i][j], acc[i][j + 1], acc[i][j + 2], acc[i][j + 3]);
    }
}

// ---------------- PE add ----------------
__global__ void __launch_bounds__(256) pe_add_kernel(float* __restrict__ x)
{
    const int n = blockIdx.x;
    const int j = threadIdx.x;
    const int t = n & (TT - 1);
    double freq = exp(-(double)j * (9.210340371976184 / 256.0));
    double ang = (double)t * freq;
    float* p = x + (size_t)n * DD + 2 * j;
    p[0] += (float)sin(ang);
    p[1] += (float)cos(ang);
}

// ---------------- layernorm ----------------
template <typename T>
__global__ void __launch_bounds__(256) ln_kernel(const float* __restrict__ in,
                                                 T* __restrict__ out,
                                                 const float* __restrict__ gam,
                                                 const float* __restrict__ bet)
{
    const int n = blockIdx.x;
    const int t = threadIdx.x;
    const float* row = in + (size_t)n * DD;
    float x0 = row[t], x1 = row[t + 256];
    __shared__ float s1[256], s2[256];
    s1[t] = x0 + x1;
    s2[t] = x0 * x0 + x1 * x1;
    __syncthreads();
    for (int o = 128; o > 0; o >>= 1) {
        if (t < o) { s1[t] += s1[t + o]; s2[t] += s2[t + o]; }
        __syncthreads();
    }
    float mean = s1[0] * (1.f / DD);
    float var = s2[0] * (1.f / DD) - mean * mean;
    float r = rsqrtf(var + 1e-5f);
    T* orow = out + (size_t)n * DD;
    orow[t]       = (T)((x0 - mean) * r * gam[t] + bet[t]);
    orow[t + 256] = (T)((x1 - mean) * r * gam[t + 256] + bet[t + 256]);
}

// ---------------- gathered layernorm (compact rows) ----------------
template <typename T>
__global__ void __launch_bounds__(256) gathln_kernel(const float* __restrict__ in,
                                                     T* __restrict__ out,
                                                     const float* __restrict__ gam,
                                                     const float* __restrict__ bet,
                                                     const int* __restrict__ actidx,
                                                     const int* __restrict__ nact,
                                                     const int* __restrict__ nactpad)
{
    const int i = blockIdx.x;
    if (i >= *nactpad) return;
    const int src = (i < *nact) ? actidx[i] : actidx[0];
    const int t = threadIdx.x;
    const float* row = in + (size_t)src * DD;
    float x0 = row[t], x1 = row[t + 256];
    __shared__ float s1[256], s2[256];
    s1[t] = x0 + x1;
    s2[t] = x0 * x0 + x1 * x1;
    __syncthreads();
    for (int o = 128; o > 0; o >>= 1) {
        if (t < o) { s1[t] += s1[t + o]; s2[t] += s2[t + o]; }
        __syncthreads();
    }
    float mean = s1[0] * (1.f / DD);
    float var = s2[0] * (1.f / DD) - mean * mean;
    float r = rsqrtf(var + 1e-5f);
    T* orow = out + (size_t)i * DD;
    orow[t]       = (T)((x0 - mean) * r * gam[t] + bet[t]);
    orow[t + 256] = (T)((x1 - mean) * r * gam[t + 256] + bet[t + 256]);
}

// ---------------- active-row scan ----------------
__global__ void __launch_bounds__(1024) scan_kernel(const unsigned* __restrict__ mask,
                                                    const int* __restrict__ lens,
                                                    int* __restrict__ actidx,
                                                    int* __restrict__ nact,
                                                    int* __restrict__ nactpad)
{
    const int t = threadIdx.x;
    bool f[8];
    int cnt = 0;
#pragma unroll
    for (int j = 0; j < 8; j++) {
        int n = t * 8 + j;
        int b = n >> 10, tt = n & 1023;
        f[j] = (tt < lens[b]) && (mask[n] != 0u);
        cnt += f[j] ? 1 : 0;
    }
    __shared__ int sc[1024];
    sc[t] = cnt;
    __syncthreads();
    for (int o = 1; o < 1024; o <<= 1) {
        int v = (t >= o) ? sc[t - o] : 0;
        __syncthreads();
        sc[t] += v;
        __syncthreads();
    }
    int pos = sc[t] - cnt;
#pragma unroll
    for (int j = 0; j < 8; j++)
        if (f[j]) actidx[pos++] = t * 8 + j;
    if (t == 1023) {
        int tot = sc[1023];
        *nact = tot;
        int pad = (tot + 127) & ~127;
        if (pad == 0) pad = 128;
        *nactpad = pad;
    }
}

// ---------------- mask mix ----------------
__global__ void __launch_bounds__(256) maskmix_kernel(const float* __restrict__ x,
                                                      const unsigned* __restrict__ mask,
                                                      const float* __restrict__ memb,
                                                      float* __restrict__ out)
{
    int idx = blockIdx.x * 256 + threadIdx.x;
    int n = idx >> 9, d = idx & 511;
    out[idx] = (mask[n] != 0u) ? memb[d] : x[idx];
}

// ---------------- codebook column norms ----------------
__global__ void __launch_bounds__(256) enorm_kernel(const float* __restrict__ emb,
                                                    float* __restrict__ enorm)
{
    int v = blockIdx.x * 256 + threadIdx.x;
    float s = 0.f;
    for (int e = 0; e < DD; e++) {
        float x = emb[(size_t)e * VV + v];
        s += x * x;
    }
    enorm[v] = s;
}

// ---------------- argmin (compact rows) ----------------
__global__ void __launch_bounds__(256) argmin_kernel(const float* __restrict__ big,
                                                     const float* __restrict__ enorm,
                                                     int* __restrict__ tgt,
                                                     const int* __restrict__ nact)
{
    const int n = blockIdx.x;
    if (n >= *nact) return;
    const float* row = big + (size_t)n * VV;
    const int tid = threadIdx.x;
    float best = 3.4e38f;
    int bi = 0;
    for (int v = tid; v < VV; v += 256) {
        float sc = enorm[v] - 2.f * row[v];
        if (sc < best) { best = sc; bi = v; }
    }
    __shared__ float bv[256];
    __shared__ int bix[256];
    bv[tid] = best; bix[tid] = bi;
    __syncthreads();
    for (int o = 128; o > 0; o >>= 1) {
        if (tid < o) {
            if (bv[tid + o] < bv[tid] || (bv[tid + o] == bv[tid] && bix[tid + o] < bix[tid])) {
                bv[tid] = bv[tid + o]; bix[tid] = bix[tid + o];
            }
        }
        __syncthreads();
    }
    if (tid == 0) tgt[n] = bix[0];
}

// ---------------- weight transpose-convert ----------------
__global__ void __launch_bounds__(256) tconv_kernel(const float* __restrict__ W,
                                                    __nv_bfloat16* __restrict__ Wt,
                                                    int K, int N)
{
    W  += (size_t)blockIdx.z * K * N;
    Wt += (size_t)blockIdx.z * K * N;
    __shared__ float tile[32][33];
    int n0 = blockIdx.x * 32, k0 = blockIdx.y * 32;
    int tx = threadIdx.x & 31, ty = threadIdx.x >> 5;
#pragma unroll
    for (int i = 0; i < 32; i += 8)
        tile[ty + i][tx] = W[(size_t)(k0 + ty + i) * N + n0 + tx];
    __syncthreads();
#pragma unroll
    for (int i = 0; i < 32; i += 8)
        Wt[(size_t)(n0 + ty + i) * K + k0 + tx] = __float2bfloat16(tile[tx][ty + i]);
}

// ---------------- embedding transpose + hi/lo split ----------------
__global__ void __launch_bounds__(256) embsplit_kernel(const float* __restrict__ emb,
                                                       __nv_bfloat16* __restrict__ embt)
{
    __shared__ float tile[32][33];
    int v0 = blockIdx.x * 32, e0 = blockIdx.y * 32;
    int tx = threadIdx.x & 31, ty = threadIdx.x >> 5;
#pragma unroll
    for (int i = 0; i < 32; i += 8)
        tile[ty + i][tx] = emb[(size_t)(e0 + ty + i) * VV + v0 + tx];
    __syncthreads();
#pragma unroll
    for (int i = 0; i < 32; i += 8) {
        float a = tile[tx][ty + i];
        int v = v0 + ty + i, e = e0 + tx;
        __nv_bfloat16 hi = __float2bfloat16(a);
        __nv_bfloat16 lo = __float2bfloat16(a - __bfloat162float(hi));
        size_t base = (size_t)v * KSP;
        embt[base + e] = hi;
        embt[base + DD + e] = lo;
        embt[base + 2 * DD + e] = hi;
    }
}

// ---------------- z hi/lo split (compact rows) ----------------
__global__ void __launch_bounds__(256) zsplit_kernel(const float* __restrict__ z,
                                                     __nv_bfloat16* __restrict__ zs,
                                                     const int* __restrict__ nactpad)
{
    int idx = blockIdx.x * 256 + threadIdx.x;
    int n = idx >> 9, e = idx & 511;
    if (n >= *nactpad) return;
    float a = z[idx];
    __nv_bfloat16 hi = __float2bfloat16(a);
    __nv_bfloat16 lo = __float2bfloat16(a - __bfloat162float(hi));
    size_t base = (size_t)n * KSP;
    zs[base + e] = hi;
    zs[base + DD + e] = hi;
    zs[base + 2 * DD + e] = lo;
}

// =======================================================================
// bf16 HMMA flash attention, double-buffered K/V, ldmatrix.trans for V.
// block = (b, h, 64-q tile), 4 warps.
// =======================================================================
__global__ void __launch_bounds__(128) attnmma_kernel(const __nv_bfloat16* __restrict__ qkvb,
                                                      const int* __restrict__ lens,
                                                      __nv_bfloat16* __restrict__ out)
{
    const int b = blockIdx.z, h = blockIdx.y, q0 = blockIdx.x * 64;
    const int tid = threadIdx.x;
    const int wid = tid >> 5, lane = tid & 31;
    const int len = lens[b];
    const int ktmax = (len + 63) >> 6;

    __shared__ __align__(128) __nv_bfloat16 Qs[64 * 64];
    __shared__ __align__(128) __nv_bfloat16 KB[2][64 * 64];
    __shared__ __align__(128) __nv_bfloat16 VB[2][64 * 64];   // natural [key][d]
    const uint32_t sq = smem_u32(Qs);
    const uint32_t skb[2] = { smem_u32(KB[0]), smem_u32(KB[1]) };
    const uint32_t svb[2] = { smem_u32(VB[0]), smem_u32(VB[1]) };

    auto load_kv = [&](int kt) {
        const __nv_bfloat16* kbase = qkvb + (size_t)(b * TT + kt * 64) * (3 * DD) + DD + h * HD;
        const __nv_bfloat16* vbase = qkvb + (size_t)(b * TT + kt * 64) * (3 * DD) + 2 * DD + h * HD;
        uint32_t dk = skb[kt & 1], dv = svb[kt & 1];
#pragma unroll
        for (int c = 0; c < 4; c++) {
            int idx = tid * 4 + c;
            int row = idx >> 3, seg = idx & 7;
            uint32_t off = SWZ((uint32_t)(row * 128 + seg * 16));
            cp16(dk + off, kbase + (size_t)row * (3 * DD) + seg * 8);
            cp16(dv + off, vbase + (size_t)row * (3 * DD) + seg * 8);
        }
        asm volatile("cp.async.commit_group;");
    };

    // prologue: Q + (K,V)0
    {
        const __nv_bfloat16* base = qkvb + (size_t)(b * TT + q0) * (3 * DD) + h * HD;
#pragma unroll
        for (int c = 0; c < 4; c++) {
            int idx = tid * 4 + c;
            int row = idx >> 3, seg = idx & 7;
            cp16(sq + SWZ((uint32_t)(row * 128 + seg * 16)), base + (size_t)row * (3 * DD) + seg * 8);
        }
        asm volatile("cp.async.commit_group;");
    }
    load_kv(0);
    asm volatile("cp.async.wait_group 0;");
    __syncthreads();

    // Q fragments: warp owns rows wid*16..+15
    uint32_t af[4][4];
#pragma unroll
    for (int ks = 0; ks < 4; ks++) {
        int row = wid * 16 + (lane & 15);
        uint32_t addr = sq + SWZ((uint32_t)(row * 128 + ks * 32 + ((lane >> 4) << 4)));
        ldsm_x4(af[ks][0], af[ks][1], af[ks][2], af[ks][3], addr);
    }

    float m0 = -1e30f, m1 = -1e30f, l0 = 0.f, l1 = 0.f;
    float oacc[8][4];
#pragma unroll
    for (int nb = 0; nb < 8; nb++)
#pragma unroll
        for (int q = 0; q < 4; q++) oacc[nb][q] = 0.f;

    const int g = lane >> 2, tq = lane & 3;

    for (int kt = 0; kt < ktmax; kt++) {
        // prefetch next tile (overlaps this tile's compute)
        if (kt + 1 < ktmax) load_kv(kt + 1);

        const uint32_t sk = skb[kt & 1], sv = svb[kt & 1];

        // S = Q @ K^T
        float s[8][4];
#pragma unroll
        for (int nb = 0; nb < 8; nb++)
#pragma unroll
            for (int q = 0; q < 4; q++) s[nb][q] = 0.f;
#pragma unroll
        for (int ks = 0; ks < 4; ks++) {
            uint32_t bf[8][2];
#pragma unroll
            for (int p = 0; p < 4; p++) {
                int nr = p * 16 + ((lane >> 4) << 3) + (lane & 7);
                uint32_t addr = sk + SWZ((uint32_t)(nr * 128 + ks * 32 + (((lane >> 3) & 1) << 4)));
                ldsm_x4(bf[p * 2][0], bf[p * 2][1], bf[p * 2 + 1][0], bf[p * 2 + 1][1], addr);
            }
#pragma unroll
            for (int nb = 0; nb < 8; nb++)
                mma16816(s[nb], af[ks], bf[nb]);
        }

        // scale + key mask
#pragma unroll
        for (int nb = 0; nb < 8; nb++) {
            int k0c = kt * 64 + nb * 8 + tq * 2;
            float ba = (k0c < len) ? 0.f : -1e9f;
            float bb2 = (k0c + 1 < len) ? 0.f : -1e9f;
            s[nb][0] = s[nb][0] * 0.125f + ba;
            s[nb][1] = s[nb][1] * 0.125f + bb2;
            s[nb][2] = s[nb][2] * 0.125f + ba;
            s[nb][3] = s[nb][3] * 0.125f + bb2;
        }

        // online softmax (rows g and g+8)
        float mt0 = -1e30f, mt1 = -1e30f;
#pragma unroll
        for (int nb = 0; nb < 8; nb++) {
            mt0 = fmaxf(mt0, fmaxf(s[nb][0], s[nb][1]));
            mt1 = fmaxf(mt1, fmaxf(s[nb][2], s[nb][3]));
        }
        mt0 = fmaxf(mt0, __shfl_xor_sync(0xffffffffu, mt0, 1));
        mt0 = fmaxf(mt0, __shfl_xor_sync(0xffffffffu, mt0, 2));
        mt1 = fmaxf(mt1, __shfl_xor_sync(0xffffffffu, mt1, 1));
        mt1 = fmaxf(mt1, __shfl_xor_sync(0xffffffffu, mt1, 2));

        float mn0 = fmaxf(m0, mt0), mn1 = fmaxf(m1, mt1);
        float a0 = __expf(m0 - mn0), a1 = __expf(m1 - mn1);
        m0 = mn0; m1 = mn1;

        float r0 = 0.f, r1 = 0.f;
#pragma unroll
        for (int nb = 0; nb < 8; nb++) {
            s[nb][0] = __expf(s[nb][0] - m0);
            s[nb][1] = __expf(s[nb][1] - m0);
            s[nb][2] = __expf(s[nb][2] - m1);
            s[nb][3] = __expf(s[nb][3] - m1);
            r0 += s[nb][0] + s[nb][1];
            r1 += s[nb][2] + s[nb][3];
        }
        r0 += __shfl_xor_sync(0xffffffffu, r0, 1);
        r0 += __shfl_xor_sync(0xffffffffu, r0, 2);
        r1 += __shfl_xor_sync(0xffffffffu, r1, 1);
        r1 += __shfl_xor_sync(0xffffffffu, r1, 2);
        l0 = l0 * a0 + r0;
        l1 = l1 * a1 + r1;

#pragma unroll
        for (int nb = 0; nb < 8; nb++) {
            oacc[nb][0] *= a0; oacc[nb][1] *= a0;
            oacc[nb][2] *= a1; oacc[nb][3] *= a1;
        }

        // repack P -> A fragments
        uint32_t ap[4][4];
#pragma unroll
        for (int kk = 0; kk < 4; kk++) {
            ap[kk][0] = packbf(s[2 * kk][0],     s[2 * kk][1]);
            ap[kk][1] = packbf(s[2 * kk][2],     s[2 * kk][3]);
            ap[kk][2] = packbf(s[2 * kk + 1][0], s[2 * kk + 1][1]);
            ap[kk][3] = packbf(s[2 * kk + 1][2], s[2 * kk + 1][3]);
        }

        // O += P @ V via ldmatrix.trans on natural V[key][d]
#pragma unroll
        for (int kk = 0; kk < 4; kk++) {
            uint32_t bfv[8][2];
#pragma unroll
            for (int p = 0; p < 4; p++) {
                int key = kk * 16 + ((lane >> 3) & 1) * 8 + (lane & 7);
                uint32_t dbyte = (uint32_t)(p * 32 + ((lane >> 4) & 1) * 16);
                uint32_t addr = sv + SWZ((uint32_t)(key * 128) + dbyte);
                ldsm_x4_t(bfv[p * 2][0], bfv[p * 2][1], bfv[p * 2 + 1][0], bfv[p * 2 + 1][1], addr);
            }
#pragma unroll
            for (int nb = 0; nb < 8; nb++)
                mma16816(oacc[nb], ap[kk], bfv[nb]);
        }

        // retire prefetch; barrier guards next iteration's buffer overwrite
        if (kt + 1 < ktmax) {
            asm volatile("cp.async.wait_group 0;");
            __syncthreads();
        }
    }

    // write out
    float i0 = 1.f / l0, i1 = 1.f / l1;
    int row0 = b * TT + q0 + wid * 16 + g;
#pragma unroll
    for (int nb = 0; nb < 8; nb++) {
        int col = h * HD + nb * 8 + tq * 2;
        *(__nv_bfloat162*)(out + (size_t)row0 * DD + col) =
            __nv_bfloat162(__float2bfloat16(oacc[nb][0] * i0), __float2bfloat16(oacc[nb][1] * i0));
        *(__nv_bfloat162*)(out + (size_t)(row0 + 8) * DD + col) =
            __nv_bfloat162(__float2bfloat16(oacc[nb][2] * i1), __float2bfloat16(oacc[nb][3] * i1));
    }
}

// ---------------- compact row loss ----------------
__global__ void __launch_bounds__(256) rowloss_kernel(const float* __restrict__ big,
                                                      const int* __restrict__ tgt,
                                                      const int* __restrict__ nact,
                                                      float* __restrict__ ent)
{
    const int n = blockIdx.x;
    if (n >= *nact) return;
    const float* row = big + (size_t)n * VV;
    const int tid = threadIdx.x;
    float mx = -1e30f;
    for (int v = tid; v < VV; v += 256) mx = fmaxf(mx, row[v]);
    __shared__ float sm[256];
    sm[tid] = mx;
    __syncthreads();
    for (int o = 128; o > 0; o >>= 1) {
        if (tid < o) sm[tid] = fmaxf(sm[tid], sm[tid + o]);
        __syncthreads();
    }
    mx = sm[0];
    __syncthreads();
    float s = 0.f;
    for (int v = tid; v < VV; v += 256) s += __expf(row[v] - mx);
    sm[tid] = s;
    __syncthreads();
    for (int o = 128; o > 0; o >>= 1) {
        if (tid < o) sm[tid] += sm[tid + o];
        __syncthreads();
    }
    if (tid == 0) ent[n] = mx + logf(sm[0]) - row[tgt[n]];
}

__global__ void __launch_bounds__(1024) finalize_kernel(const float* __restrict__ ent,
                                                        const int* __restrict__ nact,
                                                        float* __restrict__ out)
{
    const int tid = threadIdx.x;
    const int N = *nact;
    float s = 0.f;
    for (int n = tid; n < N; n += 1024) s += ent[n];
    __shared__ float ss[1024];
    ss[tid] = s;
    __syncthreads();
    for (int o = 512; o > 0; o >>= 1) {
        if (tid < o) ss[tid] += ss[tid + o];
        __syncthreads();
    }
    if (tid == 0) out[0] = ss[0] / (float)N;
}

// ---------------- host ----------------
extern "C" void kernel_launch(void* const* d_in, const int* in_sizes, int n_in,
                              void* d_out, int out_size)
{
    (void)in_sizes; (void)n_in; (void)out_size;
    const float*    xs    = (const float*)d_in[0];
    const int*      lens  = (const int*)d_in[1];
    const unsigned* mask  = (const unsigned*)d_in[2];
    const float*    W_emb = (const float*)d_in[3];
    const float*    ln1_s = (const float*)d_in[4];
    const float*    ln1_b = (const float*)d_in[5];
    const float*    Wqkv  = (const float*)d_in[6];
    const float*    Wo    = (const float*)d_in[7];
    const float*    ln2_s = (const float*)d_in[8];
    const float*    ln2_b = (const float*)d_in[9];
    const float*    W1    = (const float*)d_in[10];
    const float*    W2    = (const float*)d_in[11];
    const float*    an_s  = (const float*)d_in[12];
    const float*    an_b  = (const float*)d_in[13];
    const float*    iln_s = (const float*)d_in[14];
    const float*    iln_b = (const float*)d_in[15];
    const float*    memb  = (const float*)d_in[16];
    const float*    top   = (const float*)d_in[17];
    const float*    proj  = (const float*)d_in[18];
    const float*    emb   = (const float*)d_in[19];

    float *px, *pres, *ph, *pz, *pbig, *penorm, *pent;
    int *ptgt, *pactidx, *pnact, *pnactpad;
    __nv_bfloat16 *phb, *pqkvb, *pattnb, *pffnb, *pzs, *pembt, *pwqkvt, *pwot, *pw1t, *pw2t, *ptopt;
    cudaGetSymbolAddress((void**)&px, g_x);
    cudaGetSymbolAddress((void**)&pres, g_res);
    cudaGetSymbolAddress((void**)&ph, g_h);
    cudaGetSymbolAddress((void**)&pz, g_z);
    cudaGetSymbolAddress((void**)&pbig, g_big);
    cudaGetSymbolAddress((void**)&penorm, g_enorm);
    cudaGetSymbolAddress((void**)&pent, g_ent);
    cudaGetSymbolAddress((void**)&ptgt, g_tgt);
    cudaGetSymbolAddress((void**)&pactidx, g_actidx);
    cudaGetSymbolAddress((void**)&pnact, g_nact);
    cudaGetSymbolAddress((void**)&pnactpad, g_nactpad);
    cudaGetSymbolAddress((void**)&phb, g_hb);
    cudaGetSymbolAddress((void**)&pqkvb, g_qkvb);
    cudaGetSymbolAddress((void**)&pattnb, g_attnb);
    cudaGetSymbolAddress((void**)&pffnb, g_ffnb);
    cudaGetSymbolAddress((void**)&pzs, g_zs);
    cudaGetSymbolAddress((void**)&pembt, g_embt);
    cudaGetSymbolAddress((void**)&pwqkvt, g_wqkvt);
    cudaGetSymbolAddress((void**)&pwot, g_wot);
    cudaGetSymbolAddress((void**)&pw1t, g_w1t);
    cudaGetSymbolAddress((void**)&pw2t, g_w2t);
    cudaGetSymbolAddress((void**)&ptopt, g_topt);

    cudaFuncSetAttribute(hgemm_kernel<0>, cudaFuncAttributeMaxDynamicSharedMemorySize, HG_SMEM);
    cudaFuncSetAttribute(hgemm_kernel<1>, cudaFuncAttributeMaxDynamicSharedMemorySize, HG_SMEM);
    cudaFuncSetAttribute(hgemm_kernel<2>, cudaFuncAttributeMaxDynamicSharedMemorySize, HG_SMEM);
    cudaFuncSetAttribute(hgemm_kernel<3>, cudaFuncAttributeMaxDynamicSharedMemorySize, HG_SMEM);

    dim3 tb(256);

    // ---- weight prep ----
    tconv_kernel<<<dim3(3 * DD / 32, DD / 32, LL), tb>>>(Wqkv, pwqkvt, DD, 3 * DD);
    tconv_kernel<<<dim3(DD / 32, DD / 32, LL), tb>>>(Wo, pwot, DD, DD);
    tconv_kernel<<<dim3(FF / 32, DD / 32, LL), tb>>>(W1, pw1t, DD, FF);
    tconv_kernel<<<dim3(DD / 32, FF / 32, LL), tb>>>(W2, pw2t, FF, DD);
    tconv_kernel<<<dim3(VV / 32, DD / 32, 1), tb>>>(top, ptopt, DD, VV);
    embsplit_kernel<<<dim3(VV / 32, DD / 32), tb>>>(emb, pembt);
    enorm_kernel<<<VV / 256, tb>>>(emb, penorm);

    // ---- active-row compaction ----
    scan_kernel<<<1, 1024>>>(mask, lens, pactidx, pnact, pnactpad);

    // ---- 1. embed (fp32) + PE ----
    sgemm_kernel<<<dim3(DD / BN, NTOK / BM), tb>>>(NTOK, DD, DD, xs, W_emb, px, nullptr);
    pe_add_kernel<<<NTOK, tb>>>(px);

    // ---- 2. targets on ACTIVE rows only ----
    gathln_kernel<float><<<NTOK, tb>>>(px, ph, iln_s, iln_b, pactidx, pnact, pnactpad);
    sgemm_kernel<<<dim3(DD / BN, NTOK / BM), tb>>>(NTOK, DD, DD, ph, proj, pz, pnactpad);
    zsplit_kernel<<<(NTOK * DD) / 256, tb>>>(pz, pzs, pnactpad);
    hgemm_kernel<0><<<dim3(VV / 128, NTOK / 128), 256, HG_SMEM>>>(NTOK, VV, KSP, pzs, pembt, pbig, nullptr, pnactpad);
    argmin_kernel<<<NTOK, tb>>>(pbig, penorm, ptgt, pnact);

    // ---- 3. masked stream ----
    maskmix_kernel<<<(NTOK * DD) / 256, tb>>>(px, mask, memb, pres);

    // ---- 4. encoder ----
    for (int l = 0; l < LL; l++) {
        ln_kernel<__nv_bfloat16><<<NTOK, tb>>>(pres, phb, ln1_s + l * DD, ln1_b + l * DD);
        hgemm_kernel<3><<<dim3(3 * DD / 128, NTOK / 128), 256, HG_SMEM>>>(NTOK, 3 * DD, DD,
                phb, pwqkvt + (size_t)l * 3 * DD * DD, nullptr, pqkvb, nullptr);
        attnmma_kernel<<<dim3(TT / 64, HH, 8), 128>>>(pqkvb, lens, pattnb);
        hgemm_kernel<1><<<dim3(DD / 128, NTOK / 128), 256, HG_SMEM>>>(NTOK, DD, DD,
                pattnb, pwot + (size_t)l * DD * DD, pres, nullptr, nullptr);
        ln_kernel<__nv_bfloat16><<<NTOK, tb>>>(pres, phb, ln2_s + l * DD, ln2_b + l * DD);
        hgemm_kernel<2><<<dim3(FF / 128, NTOK / 128), 256, HG_SMEM>>>(NTOK, FF, DD,
                phb, pw1t + (size_t)l * FF * DD, nullptr, pffnb, nullptr);
        hgemm_kernel<1><<<dim3(DD / 128, NTOK / 128), 256, HG_SMEM>>>(NTOK, DD, FF,
                pffnb, pw2t + (size_t)l * DD * FF, pres, nullptr, nullptr);
    }

    // ---- 5. final LN + logits + loss on ACTIVE rows only ----
    gathln_kernel<__nv_bfloat16><<<NTOK, tb>>>(pres, phb, an_s, an_b, pactidx, pnact, pnactpad);
    hgemm_kernel<0><<<dim3(VV / 128, NTOK / 128), 256, HG_SMEM>>>(NTOK, VV, DD, phb, ptopt, pbig, nullptr, pnactpad);
    rowloss_kernel<<<NTOK, tb>>>(pbig, ptgt, pnact, pent);
    finalize_kernel<<<1, 1024>>>(pent, pnact, (float*)d_out);
}

// round 11
// speedup vs baseline: 6.2323x; 1.0791x over previous
#include <cuda_runtime.h>
#include <cuda_bf16.h>
#include <math.h>
#include <stdint.h>

// ---------------- model dims ----------------
#define NTOK 8192
#define TT   1024
#define DD   512
#define FF   2048
#define VV   8192
#define HH   8
#define HD   64
#define LL   6
#define KSP  1536

// ---------------- scratch ----------------
__device__ float g_x   [NTOK * DD];
__device__ float g_res [NTOK * DD];
__device__ float g_h   [NTOK * DD];
__device__ float g_z   [NTOK * DD];
__device__ float g_big [(size_t)NTOK * VV];
__device__ float g_enorm[VV];
__device__ int   g_tgt [NTOK];
__device__ float g_ent [NTOK];
__device__ int   g_actidx[NTOK];
__device__ int   g_nact;
__device__ int   g_nactpad;
__device__ __nv_bfloat16 g_hb   [NTOK * DD];
__device__ __nv_bfloat16 g_qkvb [NTOK * 3 * DD];
__device__ __nv_bfloat16 g_attnb[NTOK * DD];
__device__ __nv_bfloat16 g_ffnb [NTOK * FF];
__device__ __nv_bfloat16 g_zs   [(size_t)NTOK * KSP];
__device__ __nv_bfloat16 g_embt [(size_t)VV * KSP];
__device__ __nv_bfloat16 g_wqkvt[LL * 3 * DD * DD];
__device__ __nv_bfloat16 g_wot  [LL * DD * DD];
__device__ __nv_bfloat16 g_w1t  [LL * FF * DD];
__device__ __nv_bfloat16 g_w2t  [LL * DD * FF];
__device__ __nv_bfloat16 g_topt [VV * DD];

// ---------------- helpers ----------------
__device__ __forceinline__ uint32_t smem_u32(const void* p) {
    uint32_t a;
    asm("{ .reg .u64 t; cvta.to.shared.u64 t, %1; cvt.u32.u64 %0, t; }" : "=r"(a) : "l"(p));
    return a;
}
__device__ __forceinline__ void cp16(uint32_t dst, const void* src) {
    asm volatile("cp.async.cg.shared.global [%0], [%1], 16;" :: "r"(dst), "l"(src));
}
__device__ __forceinline__ void ldsm_x4(uint32_t& r0, uint32_t& r1, uint32_t& r2, uint32_t& r3, uint32_t addr) {
    asm volatile("ldmatrix.sync.aligned.m8n8.x4.shared.b16 {%0,%1,%2,%3}, [%4];"
                 : "=r"(r0), "=r"(r1), "=r"(r2), "=r"(r3) : "r"(addr));
}
__device__ __forceinline__ void ldsm_x4_t(uint32_t& r0, uint32_t& r1, uint32_t& r2, uint32_t& r3, uint32_t addr) {
    asm volatile("ldmatrix.sync.aligned.m8n8.x4.trans.shared.b16 {%0,%1,%2,%3}, [%4];"
                 : "=r"(r0), "=r"(r1), "=r"(r2), "=r"(r3) : "r"(addr));
}
__device__ __forceinline__ void mma16816(float* d, const uint32_t* a, const uint32_t* b) {
    asm volatile("mma.sync.aligned.m16n8k16.row.col.f32.bf16.bf16.f32 "
                 "{%0,%1,%2,%3}, {%4,%5,%6,%7}, {%8,%9}, {%0,%1,%2,%3};"
                 : "+f"(d[0]), "+f"(d[1]), "+f"(d[2]), "+f"(d[3])
                 : "r"(a[0]), "r"(a[1]), "r"(a[2]), "r"(a[3]), "r"(b[0]), "r"(b[1]));
}
__device__ __forceinline__ uint32_t packbf(float a, float b) {
    __nv_bfloat162 t(__float2bfloat16(a), __float2bfloat16(b));
    return *(uint32_t*)&t;
}
#define SWZ(o) ((o) ^ (((o) >> 3) & 0x70))

// =======================================================================
// bf16 HMMA GEMM, 3-stage cp.async pipeline.
// MODE 0: fp32 store; 1: fp32 +=; 2: bf16 relu; 3: bf16 store
// rowlim: skip blocks with bm >= *rowlim (compact-row GEMMs)
// blens:  skip blocks with (bm%1024) >= blens[bm/1024] (per-batch length)
// =======================================================================
#define HG_SMEM (3 * 32768)

template <int MODE>
__global__ void __launch_bounds__(256) hgemm_kernel(int M, int N, int K,
                                                    const __nv_bfloat16* __restrict__ A,
                                                    const __nv_bfloat16* __restrict__ Bt,
                                                    float* __restrict__ Cf,
                                                    __nv_bfloat16* __restrict__ Cb,
                                                    const int* __restrict__ rowlim,
                                                    const int* __restrict__ blens)
{
    const int bm = blockIdx.y * 128, bn = blockIdx.x * 128;
    if (rowlim && bm >= *rowlim) return;
    if (blens && (bm & 1023) >= blens[bm >> 10]) return;
    extern __shared__ char smem[];
    const uint32_t sb = smem_u32(smem);
    const int tid  = threadIdx.x;
    const int wid  = tid >> 5, lane = tid & 31;
    const int wm   = wid >> 2;
    const int wn   = wid & 3;
    const int nch  = K >> 6;

    auto load_chunk = [&](int ci) {
        uint32_t buf = sb + (uint32_t)(ci % 3) * 32768u;
        const __nv_bfloat16* ap = A  + (size_t)bm * K + (size_t)ci * 64;
        const __nv_bfloat16* bp = Bt + (size_t)bn * K + (size_t)ci * 64;
#pragma unroll
        for (int c = 0; c < 4; c++) {
            int idx = tid * 4 + c;
            int row = idx >> 3, seg = idx & 7;
            uint32_t off = SWZ((uint32_t)(row * 128 + seg * 16));
            cp16(buf + off,          ap + (size_t)row * K + seg * 8);
            cp16(buf + 16384u + off, bp + (size_t)row * K + seg * 8);
        }
        asm volatile("cp.async.commit_group;");
    };

    load_chunk(0);
    if (nch > 1) load_chunk(1);
    if (nch > 2) load_chunk(2);

    float acc[4][4][4];
#pragma unroll
    for (int mi = 0; mi < 4; mi++)
#pragma unroll
        for (int ni = 0; ni < 4; ni++)
#pragma unroll
            for (int q = 0; q < 4; q++) acc[mi][ni][q] = 0.f;

    for (int ci = 0; ci < nch; ci++) {
        if (ci + 3 <= nch)      asm volatile("cp.async.wait_group 2;");
        else if (ci + 2 == nch) asm volatile("cp.async.wait_group 1;");
        else                    asm volatile("cp.async.wait_group 0;");
        __syncthreads();

        uint32_t ab = sb + (uint32_t)(ci % 3) * 32768u;
        uint32_t bb = ab + 16384u;
#pragma unroll
        for (int ks = 0; ks < 4; ks++) {
            uint32_t af[4][4], bf[4][2];
#pragma unroll
            for (int mi = 0; mi < 4; mi++) {
                int row = wm * 64 + mi * 16 + (lane & 15);
                uint32_t addr = ab + SWZ((uint32_t)(row * 128 + ks * 32 + ((lane >> 4) << 4)));
                ldsm_x4(af[mi][0], af[mi][1], af[mi][2], af[mi][3], addr);
            }
#pragma unroll
            for (int p = 0; p < 2; p++) {
                int nr = wn * 32 + p * 16 + ((lane >> 4) << 3) + (lane & 7);
                uint32_t addr = bb + SWZ((uint32_t)(nr * 128 + ks * 32 + (((lane >> 3) & 1) << 4)));
                ldsm_x4(bf[p * 2][0], bf[p * 2][1], bf[p * 2 + 1][0], bf[p * 2 + 1][1], addr);
            }
#pragma unroll
            for (int mi = 0; mi < 4; mi++)
#pragma unroll
                for (int ni = 0; ni < 4; ni++)
                    mma16816(acc[mi][ni], af[mi], bf[ni]);
        }
        __syncthreads();
        if (ci + 3 < nch) load_chunk(ci + 3);
    }

    const int g = lane >> 2, tig = lane & 3;
#pragma unroll
    for (int mi = 0; mi < 4; mi++) {
#pragma unroll
        for (int ni = 0; ni < 4; ni++) {
            int r0 = bm + wm * 64 + mi * 16 + g;
            int c0 = bn + wn * 32 + ni * 8 + tig * 2;
            float* a4 = acc[mi][ni];
            if (MODE == 0) {
                *(float2*)(Cf + (size_t)r0 * N + c0)       = make_float2(a4[0], a4[1]);
                *(float2*)(Cf + (size_t)(r0 + 8) * N + c0) = make_float2(a4[2], a4[3]);
            } else if (MODE == 1) {
                float2* d0 = (float2*)(Cf + (size_t)r0 * N + c0);
                float2* d1 = (float2*)(Cf + (size_t)(r0 + 8) * N + c0);
                float2 o0 = *d0, o1 = *d1;
                o0.x += a4[0]; o0.y += a4[1];
                o1.x += a4[2]; o1.y += a4[3];
                *d0 = o0; *d1 = o1;
            } else if (MODE == 2) {
                *(__nv_bfloat162*)(Cb + (size_t)r0 * N + c0) =
                    __nv_bfloat162(__float2bfloat16(fmaxf(a4[0], 0.f)), __float2bfloat16(fmaxf(a4[1], 0.f)));
                *(__nv_bfloat162*)(Cb + (size_t)(r0 + 8) * N + c0) =
                    __nv_bfloat162(__float2bfloat16(fmaxf(a4[2], 0.f)), __float2bfloat16(fmaxf(a4[3], 0.f)));
            } else {
                *(__nv_bfloat162*)(Cb + (size_t)r0 * N + c0) =
                    __nv_bfloat162(__float2bfloat16(a4[0]), __float2bfloat16(a4[1]));
                *(__nv_bfloat162*)(Cb + (size_t)(r0 + 8) * N + c0) =
                    __nv_bfloat162(__float2bfloat16(a4[2]), __float2bfloat16(a4[3]));
            }
        }
    }
}

// ---------------- fp32 SGEMM ----------------
#define BM 128
#define BN 128
#define BK 8
__global__ void __launch_bounds__(256) sgemm_kernel(int M, int N, int K,
                                                    const float* __restrict__ A,
                                                    const float* __restrict__ B,
                                                    float* __restrict__ C,
                                                    const int* __restrict__ rowlim,
                                                    const int* __restrict__ blens)
{
    const int bm = blockIdx.y * BM, bn = blockIdx.x * BN;
    if (rowlim && bm >= *rowlim) return;
    if (blens && (bm & 1023) >= blens[bm >> 10]) return;
    __shared__ float As[BK][BM];
    __shared__ float Bs[BK][BN];
    const int tid = threadIdx.x;
    const int tx = tid & 15, ty = tid >> 4;
    float acc[8][8];
#pragma unroll
    for (int i = 0; i < 8; i++)
#pragma unroll
        for (int j = 0; j < 8; j++) acc[i][j] = 0.f;
    const int aRow = tid >> 1, aCol = (tid & 1) * 4;
    const int bRow = tid >> 5, bCol = (tid & 31) * 4;
    const float* Aptr = A + (size_t)(bm + aRow) * K + aCol;
    const float* Bptr = B + (size_t)bRow * N + bn + bCol;
    for (int k0 = 0; k0 < K; k0 += BK) {
        float4 av = *(const float4*)(Aptr + k0);
        float4 bv = *(const float4*)(Bptr + (size_t)k0 * N);
        As[aCol + 0][aRow] = av.x; As[aCol + 1][aRow] = av.y;
        As[aCol + 2][aRow] = av.z; As[aCol + 3][aRow] = av.w;
        *(float4*)&Bs[bRow][bCol] = bv;
        __syncthreads();
#pragma unroll
        for (int k = 0; k < BK; k++) {
            float a[8], b[8];
#pragma unroll
            for (int i = 0; i < 8; i++) a[i] = As[k][ty * 8 + i];
#pragma unroll
            for (int j = 0; j < 8; j++) b[j] = Bs[k][tx * 8 + j];
#pragma unroll
            for (int i = 0; i < 8; i++)
#pragma unroll
                for (int j = 0; j < 8; j++) acc[i][j] += a[i] * b[j];
        }
        __syncthreads();
    }
#pragma unroll
    for (int i = 0; i < 8; i++) {
        float* crow = C + (size_t)(bm + ty * 8 + i) * N + bn + tx * 8;
#pragma unroll
        for (int j = 0; j < 8; j += 4)
            *(float4*)(crow + j) = make_float4(acc[i][j], acc[i][j + 1], acc[i][j + 2], acc[i][j + 3]);
    }
}

// ---------------- PE add (lens-limited) ----------------
__global__ void __launch_bounds__(256) pe_add_kernel(float* __restrict__ x,
                                                     const int* __restrict__ lens)
{
    const int n = blockIdx.x;
    const int t = n & (TT - 1);
    if (t >= ((lens[n >> 10] + 127) & ~127)) return;
    const int j = threadIdx.x;
    double freq = exp(-(double)j * (9.210340371976184 / 256.0));
    double ang = (double)t * freq;
    float* p = x + (size_t)n * DD + 2 * j;
    p[0] += (float)sin(ang);
    p[1] += (float)cos(ang);
}

// ---------------- layernorm (lens-limited when lens!=null) ----------------
template <typename T>
__global__ void __launch_bounds__(256) ln_kernel(const float* __restrict__ in,
                                                 T* __restrict__ out,
                                                 const float* __restrict__ gam,
                                                 const float* __restrict__ bet,
                                                 const int* __restrict__ lens)
{
    const int n = blockIdx.x;
    if (lens && (n & 1023) >= ((lens[n >> 10] + 127) & ~127)) return;
    const int t = threadIdx.x;
    const float* row = in + (size_t)n * DD;
    float x0 = row[t], x1 = row[t + 256];
    __shared__ float s1[256], s2[256];
    s1[t] = x0 + x1;
    s2[t] = x0 * x0 + x1 * x1;
    __syncthreads();
    for (int o = 128; o > 0; o >>= 1) {
        if (t < o) { s1[t] += s1[t + o]; s2[t] += s2[t + o]; }
        __syncthreads();
    }
    float mean = s1[0] * (1.f / DD);
    float var = s2[0] * (1.f / DD) - mean * mean;
    float r = rsqrtf(var + 1e-5f);
    T* orow = out + (size_t)n * DD;
    orow[t]       = (T)((x0 - mean) * r * gam[t] + bet[t]);
    orow[t + 256] = (T)((x1 - mean) * r * gam[t + 256] + bet[t + 256]);
}

// ---------------- gathered layernorm (compact rows) ----------------
template <typename T>
__global__ void __launch_bounds__(256) gathln_kernel(const float* __restrict__ in,
                                                     T* __restrict__ out,
                                                     const float* __restrict__ gam,
                                                     const float* __restrict__ bet,
                                                     const int* __restrict__ actidx,
                                                     const int* __restrict__ nact,
                                                     const int* __restrict__ nactpad)
{
    const int i = blockIdx.x;
    if (i >= *nactpad) return;
    const int src = (i < *nact) ? actidx[i] : actidx[0];
    const int t = threadIdx.x;
    const float* row = in + (size_t)src * DD;
    float x0 = row[t], x1 = row[t + 256];
    __shared__ float s1[256], s2[256];
    s1[t] = x0 + x1;
    s2[t] = x0 * x0 + x1 * x1;
    __syncthreads();
    for (int o = 128; o > 0; o >>= 1) {
        if (t < o) { s1[t] += s1[t + o]; s2[t] += s2[t + o]; }
        __syncthreads();
    }
    float mean = s1[0] * (1.f / DD);
    float var = s2[0] * (1.f / DD) - mean * mean;
    float r = rsqrtf(var + 1e-5f);
    T* orow = out + (size_t)i * DD;
    orow[t]       = (T)((x0 - mean) * r * gam[t] + bet[t]);
    orow[t + 256] = (T)((x1 - mean) * r * gam[t + 256] + bet[t + 256]);
}

// ---------------- active-row scan ----------------
__global__ void __launch_bounds__(1024) scan_kernel(const unsigned* __restrict__ mask,
                                                    const int* __restrict__ lens,
                                                    int* __restrict__ actidx,
                                                    int* __restrict__ nact,
                                                    int* __restrict__ nactpad)
{
    const int t = threadIdx.x;
    bool f[8];
    int cnt = 0;
#pragma unroll
    for (int j = 0; j < 8; j++) {
        int n = t * 8 + j;
        int b = n >> 10, tt = n & 1023;
        f[j] = (tt < lens[b]) && (mask[n] != 0u);
        cnt += f[j] ? 1 : 0;
    }
    __shared__ int sc[1024];
    sc[t] = cnt;
    __syncthreads();
    for (int o = 1; o < 1024; o <<= 1) {
        int v = (t >= o) ? sc[t - o] : 0;
        __syncthreads();
        sc[t] += v;
        __syncthreads();
    }
    int pos = sc[t] - cnt;
#pragma unroll
    for (int j = 0; j < 8; j++)
        if (f[j]) actidx[pos++] = t * 8 + j;
    if (t == 1023) {
        int tot = sc[1023];
        *nact = tot;
        int pad = (tot + 127) & ~127;
        if (pad == 0) pad = 128;
        *nactpad = pad;
    }
}

// ---------------- mask mix ----------------
__global__ void __launch_bounds__(256) maskmix_kernel(const float* __restrict__ x,
                                                      const unsigned* __restrict__ mask,
                                                      const float* __restrict__ memb,
                                                      float* __restrict__ out)
{
    int idx = blockIdx.x * 256 + threadIdx.x;
    int n = idx >> 9, d = idx & 511;
    out[idx] = (mask[n] != 0u) ? memb[d] : x[idx];
}

// ---------------- codebook column norms ----------------
__global__ void __launch_bounds__(256) enorm_kernel(const float* __restrict__ emb,
                                                    float* __restrict__ enorm)
{
    int v = blockIdx.x * 256 + threadIdx.x;
    float s = 0.f;
    for (int e = 0; e < DD; e++) {
        float x = emb[(size_t)e * VV + v];
        s += x * x;
    }
    enorm[v] = s;
}

// ---------------- argmin (compact rows) ----------------
__global__ void __launch_bounds__(256) argmin_kernel(const float* __restrict__ big,
                                                     const float* __restrict__ enorm,
                                                     int* __restrict__ tgt,
                                                     const int* __restrict__ nact)
{
    const int n = blockIdx.x;
    if (n >= *nact) return;
    const float* row = big + (size_t)n * VV;
    const int tid = threadIdx.x;
    float best = 3.4e38f;
    int bi = 0;
    for (int v = tid; v < VV; v += 256) {
        float sc = enorm[v] - 2.f * row[v];
        if (sc < best) { best = sc; bi = v; }
    }
    __shared__ float bv[256];
    __shared__ int bix[256];
    bv[tid] = best; bix[tid] = bi;
    __syncthreads();
    for (int o = 128; o > 0; o >>= 1) {
        if (tid < o) {
            if (bv[tid + o] < bv[tid] || (bv[tid + o] == bv[tid] && bix[tid + o] < bix[tid])) {
                bv[tid] = bv[tid + o]; bix[tid] = bix[tid + o];
            }
        }
        __syncthreads();
    }
    if (tid == 0) tgt[n] = bix[0];
}

// ---------------- weight transpose-convert (coalesced 16B writes) ----------------
// tile 64(k) x 32(n); grid (N/32, K/64, L)
__global__ void __launch_bounds__(256) tconv_kernel(const float* __restrict__ W,
                                                    __nv_bfloat16* __restrict__ Wt,
                                                    int K, int N)
{
    W  += (size_t)blockIdx.z * K * N;
    Wt += (size_t)blockIdx.z * K * N;
    __shared__ float tile[64][33];
    int n0 = blockIdx.x * 32, k0 = blockIdx.y * 64;
    int nx = threadIdx.x & 31, ky = threadIdx.x >> 5;   // 32 x 8
#pragma unroll
    for (int i = 0; i < 64; i += 8)
        tile[ky + i][nx] = W[(size_t)(k0 + ky + i) * N + n0 + nx];
    __syncthreads();
    int n = threadIdx.x >> 3, kg = threadIdx.x & 7;
    __nv_bfloat16 v[8];
#pragma unroll
    for (int j = 0; j < 8; j++)
        v[j] = __float2bfloat16(tile[kg * 8 + j][n]);
    *(float4*)&Wt[(size_t)(n0 + n) * K + k0 + kg * 8] = *(float4*)v;
}

// ---------------- embedding transpose + hi/lo split ----------------
__global__ void __launch_bounds__(256) embsplit_kernel(const float* __restrict__ emb,
                                                       __nv_bfloat16* __restrict__ embt)
{
    __shared__ float tile[32][33];
    int v0 = blockIdx.x * 32, e0 = blockIdx.y * 32;
    int tx = threadIdx.x & 31, ty = threadIdx.x >> 5;
#pragma unroll
    for (int i = 0; i < 32; i += 8)
        tile[ty + i][tx] = emb[(size_t)(e0 + ty + i) * VV + v0 + tx];
    __syncthreads();
#pragma unroll
    for (int i = 0; i < 32; i += 8) {
        float a = tile[tx][ty + i];
        int v = v0 + ty + i, e = e0 + tx;
        __nv_bfloat16 hi = __float2bfloat16(a);
        __nv_bfloat16 lo = __float2bfloat16(a - __bfloat162float(hi));
        size_t base = (size_t)v * KSP;
        embt[base + e] = hi;
        embt[base + DD + e] = lo;
        embt[base + 2 * DD + e] = hi;
    }
}

// ---------------- z hi/lo split (compact rows) ----------------
__global__ void __launch_bounds__(256) zsplit_kernel(const float* __restrict__ z,
                                                     __nv_bfloat16* __restrict__ zs,
                                                     const int* __restrict__ nactpad)
{
    int idx = blockIdx.x * 256 + threadIdx.x;
    int n = idx >> 9, e = idx & 511;
    if (n >= *nactpad) return;
    float a = z[idx];
    __nv_bfloat16 hi = __float2bfloat16(a);
    __nv_bfloat16 lo = __float2bfloat16(a - __bfloat162float(hi));
    size_t base = (size_t)n * KSP;
    zs[base + e] = hi;
    zs[base + DD + e] = hi;
    zs[base + 2 * DD + e] = lo;
}

// =======================================================================
// bf16 HMMA flash attention, double-buffered K/V, ldmatrix.trans for V.
// Skips q-tiles and key-tiles beyond lens[b].
// =======================================================================
__global__ void __launch_bounds__(128) attnmma_kernel(const __nv_bfloat16* __restrict__ qkvb,
                                                      const int* __restrict__ lens,
                                                      __nv_bfloat16* __restrict__ out)
{
    const int b = blockIdx.z, h = blockIdx.y, q0 = blockIdx.x * 64;
    const int len = lens[b];
    if (q0 >= len) return;
    const int tid = threadIdx.x;
    const int wid = tid >> 5, lane = tid & 31;
    const int ktmax = (len + 63) >> 6;

    __shared__ __align__(128) __nv_bfloat16 Qs[64 * 64];
    __shared__ __align__(128) __nv_bfloat16 KB[2][64 * 64];
    __shared__ __align__(128) __nv_bfloat16 VB[2][64 * 64];
    const uint32_t sq = smem_u32(Qs);
    const uint32_t skb[2] = { smem_u32(KB[0]), smem_u32(KB[1]) };
    const uint32_t svb[2] = { smem_u32(VB[0]), smem_u32(VB[1]) };

    auto load_kv = [&](int kt) {
        const __nv_bfloat16* kbase = qkvb + (size_t)(b * TT + kt * 64) * (3 * DD) + DD + h * HD;
        const __nv_bfloat16* vbase = qkvb + (size_t)(b * TT + kt * 64) * (3 * DD) + 2 * DD + h * HD;
        uint32_t dk = skb[kt & 1], dv = svb[kt & 1];
#pragma unroll
        for (int c = 0; c < 4; c++) {
            int idx = tid * 4 + c;
            int row = idx >> 3, seg = idx & 7;
            uint32_t off = SWZ((uint32_t)(row * 128 + seg * 16));
            cp16(dk + off, kbase + (size_t)row * (3 * DD) + seg * 8);
            cp16(dv + off, vbase + (size_t)row * (3 * DD) + seg * 8);
        }
        asm volatile("cp.async.commit_group;");
    };

    {
        const __nv_bfloat16* base = qkvb + (size_t)(b * TT + q0) * (3 * DD) + h * HD;
#pragma unroll
        for (int c = 0; c < 4; c++) {
            int idx = tid * 4 + c;
            int row = idx >> 3, seg = idx & 7;
            cp16(sq + SWZ((uint32_t)(row * 128 + seg * 16)), base + (size_t)row * (3 * DD) + seg * 8);
        }
        asm volatile("cp.async.commit_group;");
    }
    load_kv(0);
    asm volatile("cp.async.wait_group 0;");
    __syncthreads();

    uint32_t af[4][4];
#pragma unroll
    for (int ks = 0; ks < 4; ks++) {
        int row = wid * 16 + (lane & 15);
        uint32_t addr = sq + SWZ((uint32_t)(row * 128 + ks * 32 + ((lane >> 4) << 4)));
        ldsm_x4(af[ks][0], af[ks][1], af[ks][2], af[ks][3], addr);
    }

    float m0 = -1e30f, m1 = -1e30f, l0 = 0.f, l1 = 0.f;
    float oacc[8][4];
#pragma unroll
    for (int nb = 0; nb < 8; nb++)
#pragma unroll
        for (int q = 0; q < 4; q++) oacc[nb][q] = 0.f;

    const int g = lane >> 2, tq = lane & 3;

    for (int kt = 0; kt < ktmax; kt++) {
        if (kt + 1 < ktmax) load_kv(kt + 1);

        const uint32_t sk = skb[kt & 1], sv = svb[kt & 1];

        float s[8][4];
#pragma unroll
        for (int nb = 0; nb < 8; nb++)
#pragma unroll
            for (int q = 0; q < 4; q++) s[nb][q] = 0.f;
#pragma unroll
        for (int ks = 0; ks < 4; ks++) {
            uint32_t bf[8][2];
#pragma unroll
            for (int p = 0; p < 4; p++) {
                int nr = p * 16 + ((lane >> 4) << 3) + (lane & 7);
                uint32_t addr = sk + SWZ((uint32_t)(nr * 128 + ks * 32 + (((lane >> 3) & 1) << 4)));
                ldsm_x4(bf[p * 2][0], bf[p * 2][1], bf[p * 2 + 1][0], bf[p * 2 + 1][1], addr);
            }
#pragma unroll
            for (int nb = 0; nb < 8; nb++)
                mma16816(s[nb], af[ks], bf[nb]);
        }

#pragma unroll
        for (int nb = 0; nb < 8; nb++) {
            int k0c = kt * 64 + nb * 8 + tq * 2;
            float ba = (k0c < len) ? 0.f : -1e9f;
            float bb2 = (k0c + 1 < len) ? 0.f : -1e9f;
            s[nb][0] = s[nb][0] * 0.125f + ba;
            s[nb][1] = s[nb][1] * 0.125f + bb2;
            s[nb][2] = s[nb][2] * 0.125f + ba;
            s[nb][3] = s[nb][3] * 0.125f + bb2;
        }

        float mt0 = -1e30f, mt1 = -1e30f;
#pragma unroll
        for (int nb = 0; nb < 8; nb++) {
            mt0 = fmaxf(mt0, fmaxf(s[nb][0], s[nb][1]));
            mt1 = fmaxf(mt1, fmaxf(s[nb][2], s[nb][3]));
        }
        mt0 = fmaxf(mt0, __shfl_xor_sync(0xffffffffu, mt0, 1));
        mt0 = fmaxf(mt0, __shfl_xor_sync(0xffffffffu, mt0, 2));
        mt1 = fmaxf(mt1, __shfl_xor_sync(0xffffffffu, mt1, 1));
        mt1 = fmaxf(mt1, __shfl_xor_sync(0xffffffffu, mt1, 2));

        float mn0 = fmaxf(m0, mt0), mn1 = fmaxf(m1, mt1);
        float a0 = __expf(m0 - mn0), a1 = __expf(m1 - mn1);
        m0 = mn0; m1 = mn1;

        float r0 = 0.f, r1 = 0.f;
#pragma unroll
        for (int nb = 0; nb < 8; nb++) {
            s[nb][0] = __expf(s[nb][0] - m0);
            s[nb][1] = __expf(s[nb][1] - m0);
            s[nb][2] = __expf(s[nb][2] - m1);
            s[nb][3] = __expf(s[nb][3] - m1);
            r0 += s[nb][0] + s[nb][1];
            r1 += s[nb][2] + s[nb][3];
        }
        r0 += __shfl_xor_sync(0xffffffffu, r0, 1);
        r0 += __shfl_xor_sync(0xffffffffu, r0, 2);
        r1 += __shfl_xor_sync(0xffffffffu, r1, 1);
        r1 += __shfl_xor_sync(0xffffffffu, r1, 2);
        l0 = l0 * a0 + r0;
        l1 = l1 * a1 + r1;

#pragma unroll
        for (int nb = 0; nb < 8; nb++) {
            oacc[nb][0] *= a0; oacc[nb][1] *= a0;
            oacc[nb][2] *= a1; oacc[nb][3] *= a1;
        }

        uint32_t ap[4][4];
#pragma unroll
        for (int kk = 0; kk < 4; kk++) {
            ap[kk][0] = packbf(s[2 * kk][0],     s[2 * kk][1]);
            ap[kk][1] = packbf(s[2 * kk][2],     s[2 * kk][3]);
            ap[kk][2] = packbf(s[2 * kk + 1][0], s[2 * kk + 1][1]);
            ap[kk][3] = packbf(s[2 * kk + 1][2], s[2 * kk + 1][3]);
        }

#pragma unroll
        for (int kk = 0; kk < 4; kk++) {
            uint32_t bfv[8][2];
#pragma unroll
            for (int p = 0; p < 4; p++) {
                int key = kk * 16 + ((lane >> 3) & 1) * 8 + (lane & 7);
                uint32_t dbyte = (uint32_t)(p * 32 + ((lane >> 4) & 1) * 16);
                uint32_t addr = sv + SWZ((uint32_t)(key * 128) + dbyte);
                ldsm_x4_t(bfv[p * 2][0], bfv[p * 2][1], bfv[p * 2 + 1][0], bfv[p * 2 + 1][1], addr);
            }
#pragma unroll
            for (int nb = 0; nb < 8; nb++)
                mma16816(oacc[nb], ap[kk], bfv[nb]);
        }

        if (kt + 1 < ktmax) {
            asm volatile("cp.async.wait_group 0;");
            __syncthreads();
        }
    }

    float i0 = 1.f / l0, i1 = 1.f / l1;
    int row0 = b * TT + q0 + wid * 16 + g;
#pragma unroll
    for (int nb = 0; nb < 8; nb++) {
        int col = h * HD + nb * 8 + tq * 2;
        *(__nv_bfloat162*)(out + (size_t)row0 * DD + col) =
            __nv_bfloat162(__float2bfloat16(oacc[nb][0] * i0), __float2bfloat16(oacc[nb][1] * i0));
        *(__nv_bfloat162*)(out + (size_t)(row0 + 8) * DD + col) =
            __nv_bfloat162(__float2bfloat16(oacc[nb][2] * i1), __float2bfloat16(oacc[nb][3] * i1));
    }
}

// ---------------- compact row loss ----------------
__global__ void __launch_bounds__(256) rowloss_kernel(const float* __restrict__ big,
                                                      const int* __restrict__ tgt,
                                                      const int* __restrict__ nact,
                                                      float* __restrict__ ent)
{
    const int n = blockIdx.x;
    if (n >= *nact) return;
    const float* row = big + (size_t)n * VV;
    const int tid = threadIdx.x;
    float mx = -1e30f;
    for (int v = tid; v < VV; v += 256) mx = fmaxf(mx, row[v]);
    __shared__ float sm[256];
    sm[tid] = mx;
    __syncthreads();
    for (int o = 128; o > 0; o >>= 1) {
        if (tid < o) sm[tid] = fmaxf(sm[tid], sm[tid + o]);
        __syncthreads();
    }
    mx = sm[0];
    __syncthreads();
    float s = 0.f;
    for (int v = tid; v < VV; v += 256) s += __expf(row[v] - mx);
    sm[tid] = s;
    __syncthreads();
    for (int o = 128; o > 0; o >>= 1) {
        if (tid < o) sm[tid] += sm[tid + o];
        __syncthreads();
    }
    if (tid == 0) ent[n] = mx + logf(sm[0]) - row[tgt[n]];
}

__global__ void __launch_bounds__(1024) finalize_kernel(const float* __restrict__ ent,
                                                        const int* __restrict__ nact,
                                                        float* __restrict__ out)
{
    const int tid = threadIdx.x;
    const int N = *nact;
    float s = 0.f;
    for (int n = tid; n < N; n += 1024) s += ent[n];
    __shared__ float ss[1024];
    ss[tid] = s;
    __syncthreads();
    for (int o = 512; o > 0; o >>= 1) {
        if (tid < o) ss[tid] += ss[tid + o];
        __syncthreads();
    }
    if (tid == 0) out[0] = ss[0] / (float)N;
}

// ---------------- host ----------------
extern "C" void kernel_launch(void* const* d_in, const int* in_sizes, int n_in,
                              void* d_out, int out_size)
{
    (void)in_sizes; (void)n_in; (void)out_size;
    const float*    xs    = (const float*)d_in[0];
    const int*      lens  = (const int*)d_in[1];
    const unsigned* mask  = (const unsigned*)d_in[2];
    const float*    W_emb = (const float*)d_in[3];
    const float*    ln1_s = (const float*)d_in[4];
    const float*    ln1_b = (const float*)d_in[5];
    const float*    Wqkv  = (const float*)d_in[6];
    const float*    Wo    = (const float*)d_in[7];
    const float*    ln2_s = (const float*)d_in[8];
    const float*    ln2_b = (const float*)d_in[9];
    const float*    W1    = (const float*)d_in[10];
    const float*    W2    = (const float*)d_in[11];
    const float*    an_s  = (const float*)d_in[12];
    const float*    an_b  = (const float*)d_in[13];
    const float*    iln_s = (const float*)d_in[14];
    const float*    iln_b = (const float*)d_in[15];
    const float*    memb  = (const float*)d_in[16];
    const float*    top   = (const float*)d_in[17];
    const float*    proj  = (const float*)d_in[18];
    const float*    emb   = (const float*)d_in[19];

    float *px, *pres, *ph, *pz, *pbig, *penorm, *pent;
    int *ptgt, *pactidx, *pnact, *pnactpad;
    __nv_bfloat16 *phb, *pqkvb, *pattnb, *pffnb, *pzs, *pembt, *pwqkvt, *pwot, *pw1t, *pw2t, *ptopt;
    cudaGetSymbolAddress((void**)&px, g_x);
    cudaGetSymbolAddress((void**)&pres, g_res);
    cudaGetSymbolAddress((void**)&ph, g_h);
    cudaGetSymbolAddress((void**)&pz, g_z);
    cudaGetSymbolAddress((void**)&pbig, g_big);
    cudaGetSymbolAddress((void**)&penorm, g_enorm);
    cudaGetSymbolAddress((void**)&pent, g_ent);
    cudaGetSymbolAddress((void**)&ptgt, g_tgt);
    cudaGetSymbolAddress((void**)&pactidx, g_actidx);
    cudaGetSymbolAddress((void**)&pnact, g_nact);
    cudaGetSymbolAddress((void**)&pnactpad, g_nactpad);
    cudaGetSymbolAddress((void**)&phb, g_hb);
    cudaGetSymbolAddress((void**)&pqkvb, g_qkvb);
    cudaGetSymbolAddress((void**)&pattnb, g_attnb);
    cudaGetSymbolAddress((void**)&pffnb, g_ffnb);
    cudaGetSymbolAddress((void**)&pzs, g_zs);
    cudaGetSymbolAddress((void**)&pembt, g_embt);
    cudaGetSymbolAddress((void**)&pwqkvt, g_wqkvt);
    cudaGetSymbolAddress((void**)&pwot, g_wot);
    cudaGetSymbolAddress((void**)&pw1t, g_w1t);
    cudaGetSymbolAddress((void**)&pw2t, g_w2t);
    cudaGetSymbolAddress((void**)&ptopt, g_topt);

    cudaFuncSetAttribute(hgemm_kernel<0>, cudaFuncAttributeMaxDynamicSharedMemorySize, HG_SMEM);
    cudaFuncSetAttribute(hgemm_kernel<1>, cudaFuncAttributeMaxDynamicSharedMemorySize, HG_SMEM);
    cudaFuncSetAttribute(hgemm_kernel<2>, cudaFuncAttributeMaxDynamicSharedMemorySize, HG_SMEM);
    cudaFuncSetAttribute(hgemm_kernel<3>, cudaFuncAttributeMaxDynamicSharedMemorySize, HG_SMEM);

    dim3 tb(256);

    // ---- weight prep ----
    tconv_kernel<<<dim3(3 * DD / 32, DD / 64, LL), tb>>>(Wqkv, pwqkvt, DD, 3 * DD);
    tconv_kernel<<<dim3(DD / 32, DD / 64, LL), tb>>>(Wo, pwot, DD, DD);
    tconv_kernel<<<dim3(FF / 32, DD / 64, LL), tb>>>(W1, pw1t, DD, FF);
    tconv_kernel<<<dim3(DD / 32, FF / 64, LL), tb>>>(W2, pw2t, FF, DD);
    tconv_kernel<<<dim3(VV / 32, DD / 64, 1), tb>>>(top, ptopt, DD, VV);
    embsplit_kernel<<<dim3(VV / 32, DD / 32), tb>>>(emb, pembt);
    enorm_kernel<<<VV / 256, tb>>>(emb, penorm);

    // ---- active-row compaction ----
    scan_kernel<<<1, 1024>>>(mask, lens, pactidx, pnact, pnactpad);

    // ---- 1. embed (fp32, lens-limited) + PE ----
    sgemm_kernel<<<dim3(DD / BN, NTOK / BM), tb>>>(NTOK, DD, DD, xs, W_emb, px, nullptr, lens);
    pe_add_kernel<<<NTOK, tb>>>(px, lens);

    // ---- 2. targets on ACTIVE rows only ----
    gathln_kernel<float><<<NTOK, tb>>>(px, ph, iln_s, iln_b, pactidx, pnact, pnactpad);
    sgemm_kernel<<<dim3(DD / BN, NTOK / BM), tb>>>(NTOK, DD, DD, ph, proj, pz, pnactpad, nullptr);
    zsplit_kernel<<<(NTOK * DD) / 256, tb>>>(pz, pzs, pnactpad);
    hgemm_kernel<0><<<dim3(VV / 128, NTOK / 128), 256, HG_SMEM>>>(NTOK, VV, KSP, pzs, pembt, pbig, nullptr, pnactpad, nullptr);
    argmin_kernel<<<NTOK, tb>>>(pbig, penorm, ptgt, pnact);

    // ---- 3. masked stream ----
    maskmix_kernel<<<(NTOK * DD) / 256, tb>>>(px, mask, memb, pres);

    // ---- 4. encoder (lens-limited everywhere) ----
    for (int l = 0; l < LL; l++) {
        ln_kernel<__nv_bfloat16><<<NTOK, tb>>>(pres, phb, ln1_s + l * DD, ln1_b + l * DD, lens);
        hgemm_kernel<3><<<dim3(3 * DD / 128, NTOK / 128), 256, HG_SMEM>>>(NTOK, 3 * DD, DD,
                phb, pwqkvt + (size_t)l * 3 * DD * DD, nullptr, pqkvb, nullptr, lens);
        attnmma_kernel<<<dim3(TT / 64, HH, 8), 128>>>(pqkvb, lens, pattnb);
        hgemm_kernel<1><<<dim3(DD / 128, NTOK / 128), 256, HG_SMEM>>>(NTOK, DD, DD,
                pattnb, pwot + (size_t)l * DD * DD, pres, nullptr, nullptr, lens);
        ln_kernel<__nv_bfloat16><<<NTOK, tb>>>(pres, phb, ln2_s + l * DD, ln2_b + l * DD, lens);
        hgemm_kernel<2><<<dim3(FF / 128, NTOK / 128), 256, HG_SMEM>>>(NTOK, FF, DD,
                phb, pw1t + (size_t)l * FF * DD, nullptr, pffnb, nullptr, lens);
        hgemm_kernel<1><<<dim3(DD / 128, NTOK / 128), 256, HG_SMEM>>>(NTOK, DD, FF,
                pffnb, pw2t + (size_t)l * DD * FF, pres, nullptr, nullptr, lens);
    }

    // ---- 5. final LN + logits + loss on ACTIVE rows only ----
    gathln_kernel<__nv_bfloat16><<<NTOK, tb>>>(pres, phb, an_s, an_b, pactidx, pnact, pnactpad);
    hgemm_kernel<0><<<dim3(VV / 128, NTOK / 128), 256, HG_SMEM>>>(NTOK, VV, DD, phb, ptopt, pbig, nullptr, pnactpad, nullptr);
    rowloss_kernel<<<NTOK, tb>>>(pbig, ptgt, pnact, pent);
    finalize_kernel<<<1, 1024>>>(pent, pnact, (float*)d_out);
}

// round 13
// speedup vs baseline: 6.6740x; 1.0709x over previous
#include <cuda_runtime.h>
#include <cuda_bf16.h>
#include <math.h>
#include <stdint.h>

// ---------------- model dims ----------------
#define NTOK 8192
#define TT   1024
#define DD   512
#define FF   2048
#define VV   8192
#define HH   8
#define HD   64
#define LL   6
#define KSP  1536

// ---------------- scratch ----------------
__device__ float g_x   [NTOK * DD];
__device__ float g_res [NTOK * DD];
__device__ float g_h   [NTOK * DD];        // dist-path LN rows; later compact residual
__device__ float g_z   [NTOK * DD];
__device__ float g_big [(size_t)NTOK * VV];
__device__ float g_enorm[VV];
__device__ int   g_tgt [NTOK];
__device__ float g_ent [NTOK];
__device__ int   g_actidx[NTOK];
__device__ int   g_nact;
__device__ int   g_nactpad;
__device__ __nv_bfloat16 g_hb   [NTOK * DD];
__device__ __nv_bfloat16 g_qkvb [NTOK * 3 * DD];
__device__ __nv_bfloat16 g_attnb[NTOK * DD];
__device__ __nv_bfloat16 g_ffnb [NTOK * FF];
__device__ __nv_bfloat16 g_zs   [(size_t)NTOK * KSP];
__device__ __nv_bfloat16 g_embt [(size_t)VV * KSP];
__device__ __nv_bfloat16 g_wqkvt[LL * 3 * DD * DD];
__device__ __nv_bfloat16 g_wot  [LL * DD * DD];
__device__ __nv_bfloat16 g_w1t  [LL * FF * DD];
__device__ __nv_bfloat16 g_w2t  [LL * DD * FF];
__device__ __nv_bfloat16 g_topt [VV * DD];

// ---------------- helpers ----------------
__device__ __forceinline__ uint32_t smem_u32(const void* p) {
    uint32_t a;
    asm("{ .reg .u64 t; cvta.to.shared.u64 t, %1; cvt.u32.u64 %0, t; }" : "=r"(a) : "l"(p));
    return a;
}
__device__ __forceinline__ void cp16(uint32_t dst, const void* src) {
    asm volatile("cp.async.cg.shared.global [%0], [%1], 16;" :: "r"(dst), "l"(src));
}
__device__ __forceinline__ void ldsm_x4(uint32_t& r0, uint32_t& r1, uint32_t& r2, uint32_t& r3, uint32_t addr) {
    asm volatile("ldmatrix.sync.aligned.m8n8.x4.shared.b16 {%0,%1,%2,%3}, [%4];"
                 : "=r"(r0), "=r"(r1), "=r"(r2), "=r"(r3) : "r"(addr));
}
__device__ __forceinline__ void ldsm_x4_t(uint32_t& r0, uint32_t& r1, uint32_t& r2, uint32_t& r3, uint32_t addr) {
    asm volatile("ldmatrix.sync.aligned.m8n8.x4.trans.shared.b16 {%0,%1,%2,%3}, [%4];"
                 : "=r"(r0), "=r"(r1), "=r"(r2), "=r"(r3) : "r"(addr));
}
__device__ __forceinline__ void mma16816(float* d, const uint32_t* a, const uint32_t* b) {
    asm volatile("mma.sync.aligned.m16n8k16.row.col.f32.bf16.bf16.f32 "
                 "{%0,%1,%2,%3}, {%4,%5,%6,%7}, {%8,%9}, {%0,%1,%2,%3};"
                 : "+f"(d[0]), "+f"(d[1]), "+f"(d[2]), "+f"(d[3])
                 : "r"(a[0]), "r"(a[1]), "r"(a[2]), "r"(a[3]), "r"(b[0]), "r"(b[1]));
}
__device__ __forceinline__ uint32_t packbf(float a, float b) {
    __nv_bfloat162 t(__float2bfloat16(a), __float2bfloat16(b));
    return *(uint32_t*)&t;
}
#define SWZ(o) ((o) ^ (((o) >> 3) & 0x70))

// =======================================================================
// bf16 HMMA GEMM, 3-stage cp.async pipeline.
// MODE 0: fp32 store; 1: fp32 +=; 2: bf16 relu; 3: bf16 store
// rowlim: skip blocks with bm >= *rowlim
// blens:  skip blocks with (bm%1024) >= blens[bm/1024]
// agidx:  if non-null, A rows are gathered via agidx[bm+row]; C rows compact
// =======================================================================
#define HG_SMEM (3 * 32768)

template <int MODE>
__global__ void __launch_bounds__(256) hgemm_kernel(int M, int N, int K,
                                                    const __nv_bfloat16* __restrict__ A,
                                                    const __nv_bfloat16* __restrict__ Bt,
                                                    float* __restrict__ Cf,
                                                    __nv_bfloat16* __restrict__ Cb,
                                                    const int* __restrict__ rowlim,
                                                    const int* __restrict__ blens,
                                                    const int* __restrict__ agidx)
{
    const int bm = blockIdx.y * 128, bn = blockIdx.x * 128;
    if (rowlim && bm >= *rowlim) return;
    if (blens && (bm & 1023) >= blens[bm >> 10]) return;
    extern __shared__ char smem[];
    const uint32_t sb = smem_u32(smem);
    const int tid  = threadIdx.x;
    const int wid  = tid >> 5, lane = tid & 31;
    const int wm   = wid >> 2;
    const int wn   = wid & 3;
    const int nch  = K >> 6;

    auto load_chunk = [&](int ci) {
        uint32_t buf = sb + (uint32_t)(ci % 3) * 32768u;
        const __nv_bfloat16* bp = Bt + (size_t)bn * K + (size_t)ci * 64;
#pragma unroll
        for (int c = 0; c < 4; c++) {
            int idx = tid * 4 + c;
            int row = idx >> 3, seg = idx & 7;
            uint32_t off = SWZ((uint32_t)(row * 128 + seg * 16));
            int ra = agidx ? agidx[bm + row] : (bm + row);
            cp16(buf + off,          A + (size_t)ra * K + (size_t)ci * 64 + seg * 8);
            cp16(buf + 16384u + off, bp + (size_t)row * K + seg * 8);
        }
        asm volatile("cp.async.commit_group;");
    };

    load_chunk(0);
    if (nch > 1) load_chunk(1);
    if (nch > 2) load_chunk(2);

    float acc[4][4][4];
#pragma unroll
    for (int mi = 0; mi < 4; mi++)
#pragma unroll
        for (int ni = 0; ni < 4; ni++)
#pragma unroll
            for (int q = 0; q < 4; q++) acc[mi][ni][q] = 0.f;

    for (int ci = 0; ci < nch; ci++) {
        if (ci + 3 <= nch)      asm volatile("cp.async.wait_group 2;");
        else if (ci + 2 == nch) asm volatile("cp.async.wait_group 1;");
        else                    asm volatile("cp.async.wait_group 0;");
        __syncthreads();

        uint32_t ab = sb + (uint32_t)(ci % 3) * 32768u;
        uint32_t bb = ab + 16384u;
#pragma unroll
        for (int ks = 0; ks < 4; ks++) {
            uint32_t af[4][4], bf[4][2];
#pragma unroll
            for (int mi = 0; mi < 4; mi++) {
                int row = wm * 64 + mi * 16 + (lane & 15);
                uint32_t addr = ab + SWZ((uint32_t)(row * 128 + ks * 32 + ((lane >> 4) << 4)));
                ldsm_x4(af[mi][0], af[mi][1], af[mi][2], af[mi][3], addr);
            }
#pragma unroll
            for (int p = 0; p < 2; p++) {
                int nr = wn * 32 + p * 16 + ((lane >> 4) << 3) + (lane & 7);
                uint32_t addr = bb + SWZ((uint32_t)(nr * 128 + ks * 32 + (((lane >> 3) & 1) << 4)));
                ldsm_x4(bf[p * 2][0], bf[p * 2][1], bf[p * 2 + 1][0], bf[p * 2 + 1][1], addr);
            }
#pragma unroll
            for (int mi = 0; mi < 4; mi++)
#pragma unroll
                for (int ni = 0; ni < 4; ni++)
                    mma16816(acc[mi][ni], af[mi], bf[ni]);
        }
        __syncthreads();
        if (ci + 3 < nch) load_chunk(ci + 3);
    }

    const int g = lane >> 2, tig = lane & 3;
#pragma unroll
    for (int mi = 0; mi < 4; mi++) {
#pragma unroll
        for (int ni = 0; ni < 4; ni++) {
            int r0 = bm + wm * 64 + mi * 16 + g;
            int c0 = bn + wn * 32 + ni * 8 + tig * 2;
            float* a4 = acc[mi][ni];
            if (MODE == 0) {
                *(float2*)(Cf + (size_t)r0 * N + c0)       = make_float2(a4[0], a4[1]);
                *(float2*)(Cf + (size_t)(r0 + 8) * N + c0) = make_float2(a4[2], a4[3]);
            } else if (MODE == 1) {
                float2* d0 = (float2*)(Cf + (size_t)r0 * N + c0);
                float2* d1 = (float2*)(Cf + (size_t)(r0 + 8) * N + c0);
                float2 o0 = *d0, o1 = *d1;
                o0.x += a4[0]; o0.y += a4[1];
                o1.x += a4[2]; o1.y += a4[3];
                *d0 = o0; *d1 = o1;
            } else if (MODE == 2) {
                *(__nv_bfloat162*)(Cb + (size_t)r0 * N + c0) =
                    __nv_bfloat162(__float2bfloat16(fmaxf(a4[0], 0.f)), __float2bfloat16(fmaxf(a4[1], 0.f)));
                *(__nv_bfloat162*)(Cb + (size_t)(r0 + 8) * N + c0) =
                    __nv_bfloat162(__float2bfloat16(fmaxf(a4[2], 0.f)), __float2bfloat16(fmaxf(a4[3], 0.f)));
            } else {
                *(__nv_bfloat162*)(Cb + (size_t)r0 * N + c0) =
                    __nv_bfloat162(__float2bfloat16(a4[0]), __float2bfloat16(a4[1]));
                *(__nv_bfloat162*)(Cb + (size_t)(r0 + 8) * N + c0) =
                    __nv_bfloat162(__float2bfloat16(a4[2]), __float2bfloat16(a4[3]));
            }
        }
    }
}

// ---------------- fp32 SGEMM ----------------
#define BM 128
#define BN 128
#define BK 8
__global__ void __launch_bounds__(256) sgemm_kernel(int M, int N, int K,
                                                    const float* __restrict__ A,
                                                    const float* __restrict__ B,
                                                    float* __restrict__ C,
                                                    const int* __restrict__ rowlim,
                                                    const int* __restrict__ blens)
{
    const int bm = blockIdx.y * BM, bn = blockIdx.x * BN;
    if (rowlim && bm >= *rowlim) return;
    if (blens && (bm & 1023) >= blens[bm >> 10]) return;
    __shared__ float As[BK][BM];
    __shared__ float Bs[BK][BN];
    const int tid = threadIdx.x;
    const int tx = tid & 15, ty = tid >> 4;
    float acc[8][8];
#pragma unroll
    for (int i = 0; i < 8; i++)
#pragma unroll
        for (int j = 0; j < 8; j++) acc[i][j] = 0.f;
    const int aRow = tid >> 1, aCol = (tid & 1) * 4;
    const int bRow = tid >> 5, bCol = (tid & 31) * 4;
    const float* Aptr = A + (size_t)(bm + aRow) * K + aCol;
    const float* Bptr = B + (size_t)bRow * N + bn + bCol;
    for (int k0 = 0; k0 < K; k0 += BK) {
        float4 av = *(const float4*)(Aptr + k0);
        float4 bv = *(const float4*)(Bptr + (size_t)k0 * N);
        As[aCol + 0][aRow] = av.x; As[aCol + 1][aRow] = av.y;
        As[aCol + 2][aRow] = av.z; As[aCol + 3][aRow] = av.w;
        *(float4*)&Bs[bRow][bCol] = bv;
        __syncthreads();
#pragma unroll
        for (int k = 0; k < BK; k++) {
            float a[8], b[8];
#pragma unroll
            for (int i = 0; i < 8; i++) a[i] = As[k][ty * 8 + i];
#pragma unroll
            for (int j = 0; j < 8; j++) b[j] = Bs[k][tx * 8 + j];
#pragma unroll
            for (int i = 0; i < 8; i++)
#pragma unroll
                for (int j = 0; j < 8; j++) acc[i][j] += a[i] * b[j];
        }
        __syncthreads();
    }
#pragma unroll
    for (int i = 0; i < 8; i++) {
        float* crow = C + (size_t)(bm + ty * 8 + i) * N + bn + tx * 8;
#pragma unroll
        for (int j = 0; j < 8; j += 4)
            *(float4*)(crow + j) = make_float4(acc[i][j], acc[i][j + 1], acc[i][j + 2], acc[i][j + 3]);
    }
}

// ---------------- PE add (lens-limited) ----------------
__global__ void __launch_bounds__(256) pe_add_kernel(float* __restrict__ x,
                                                     const int* __restrict__ lens)
{
    const int n = blockIdx.x;
    const int t = n & (TT - 1);
    if (t >= ((lens[n >> 10] + 127) & ~127)) return;
    const int j = threadIdx.x;
    double freq = exp(-(double)j * (9.210340371976184 / 256.0));
    double ang = (double)t * freq;
    float* p = x + (size_t)n * DD + 2 * j;
    p[0] += (float)sin(ang);
    p[1] += (float)cos(ang);
}

// ---------------- warp-per-row layernorm ----------------
template <typename T, bool GATHER>
__global__ void __launch_bounds__(256) lnw_kernel(const float* __restrict__ in,
                                                  T* __restrict__ out,
                                                  const float* __restrict__ gam,
                                                  const float* __restrict__ bet,
                                                  const int* __restrict__ lens,
                                                  const int* __restrict__ rowlim,
                                                  const int* __restrict__ actidx)
{
    const int w = (blockIdx.x * 256 + threadIdx.x) >> 5;
    const int lane = threadIdx.x & 31;
    if (rowlim && w >= *rowlim) return;
    if (lens && (w & 1023) >= ((lens[w >> 10] + 127) & ~127)) return;
    const int src = GATHER ? actidx[w] : w;
    const float* row = in + (size_t)src * DD;
    float v[16];
    float s = 0.f, s2 = 0.f;
#pragma unroll
    for (int k = 0; k < 4; k++) {
        float4 t = *(const float4*)(row + k * 128 + lane * 4);
        v[k * 4 + 0] = t.x; v[k * 4 + 1] = t.y; v[k * 4 + 2] = t.z; v[k * 4 + 3] = t.w;
        s  += t.x + t.y + t.z + t.w;
        s2 += t.x * t.x + t.y * t.y + t.z * t.z + t.w * t.w;
    }
#pragma unroll
    for (int o = 16; o > 0; o >>= 1) {
        s  += __shfl_xor_sync(0xffffffffu, s, o);
        s2 += __shfl_xor_sync(0xffffffffu, s2, o);
    }
    const float mean = s * (1.f / DD);
    const float var = s2 * (1.f / DD) - mean * mean;
    const float r = rsqrtf(var + 1e-5f);
#pragma unroll
    for (int k = 0; k < 4; k++) {
        const int c = k * 128 + lane * 4;
        float o0 = (v[k * 4 + 0] - mean) * r * gam[c + 0] + bet[c + 0];
        float o1 = (v[k * 4 + 1] - mean) * r * gam[c + 1] + bet[c + 1];
        float o2 = (v[k * 4 + 2] - mean) * r * gam[c + 2] + bet[c + 2];
        float o3 = (v[k * 4 + 3] - mean) * r * gam[c + 3] + bet[c + 3];
        if (sizeof(T) == 4) {
            *(float4*)((float*)out + (size_t)w * DD + c) = make_float4(o0, o1, o2, o3);
        } else {
            uint2 pk;
            pk.x = packbf(o0, o1);
            pk.y = packbf(o2, o3);
            *(uint2*)((__nv_bfloat16*)out + (size_t)w * DD + c) = pk;
        }
    }
}

// ---------------- row gather (fp32, compact) ----------------
__global__ void __launch_bounds__(128) gather_kernel(const float* __restrict__ in,
                                                     float* __restrict__ out,
                                                     const int* __restrict__ actidx,
                                                     const int* __restrict__ nactpad)
{
    const int rowi = blockIdx.x;
    if (rowi >= *nactpad) return;
    const int src = actidx[rowi];
    const float4* s = (const float4*)(in + (size_t)src * DD);
    float4* d = (float4*)(out + (size_t)rowi * DD);
    d[threadIdx.x] = s[threadIdx.x];
}

// ---------------- active-row scan (pads actidx tail) ----------------
__global__ void __launch_bounds__(1024) scan_kernel(const unsigned* __restrict__ mask,
                                                    const int* __restrict__ lens,
                                                    int* __restrict__ actidx,
                                                    int* __restrict__ nact,
                                                    int* __restrict__ nactpad)
{
    const int t = threadIdx.x;
    bool f[8];
    int cnt = 0;
#pragma unroll
    for (int j = 0; j < 8; j++) {
        int n = t * 8 + j;
        int b = n >> 10, tt = n & 1023;
        f[j] = (tt < lens[b]) && (mask[n] != 0u);
        cnt += f[j] ? 1 : 0;
    }
    __shared__ int sc[1024];
    sc[t] = cnt;
    __syncthreads();
    for (int o = 1; o < 1024; o <<= 1) {
        int v = (t >= o) ? sc[t - o] : 0;
        __syncthreads();
        sc[t] += v;
        __syncthreads();
    }
    int pos = sc[t] - cnt;
#pragma unroll
    for (int j = 0; j < 8; j++)
        if (f[j]) actidx[pos++] = t * 8 + j;
    __syncthreads();
    int tot = sc[1023];
    int pad = (tot + 127) & ~127;
    if (pad == 0) pad = 128;
    if (t == 0) { *nact = tot; *nactpad = pad; }
    __syncthreads();
    int fill = actidx[0];
    for (int i = tot + t; i < pad; i += 1024) actidx[i] = fill;
}

// ---------------- mask mix ----------------
__global__ void __launch_bounds__(256) maskmix_kernel(const float* __restrict__ x,
                                                      const unsigned* __restrict__ mask,
                                                      const float* __restrict__ memb,
                                                      float* __restrict__ out)
{
    int idx = blockIdx.x * 256 + threadIdx.x;
    int n = idx >> 9, d = idx & 511;
    out[idx] = (mask[n] != 0u) ? memb[d] : x[idx];
}

// ---------------- codebook column norms ----------------
__global__ void __launch_bounds__(256) enorm_kernel(const float* __restrict__ emb,
                                                    float* __restrict__ enorm)
{
    int v = blockIdx.x * 256 + threadIdx.x;
    float s = 0.f;
    for (int e = 0; e < DD; e++) {
        float x = emb[(size_t)e * VV + v];
        s += x * x;
    }
    enorm[v] = s;
}

// ---------------- argmin (compact rows) ----------------
__global__ void __launch_bounds__(256) argmin_kernel(const float* __restrict__ big,
                                                     const float* __restrict__ enorm,
                                                     int* __restrict__ tgt,
                                                     const int* __restrict__ nact)
{
    const int n = blockIdx.x;
    if (n >= *nact) return;
    const float* row = big + (size_t)n * VV;
    const int tid = threadIdx.x;
    float best = 3.4e38f;
    int bi = 0;
    for (int v = tid; v < VV; v += 256) {
        float sc = enorm[v] - 2.f * row[v];
        if (sc < best) { best = sc; bi = v; }
    }
    __shared__ float bv[256];
    __shared__ int bix[256];
    bv[tid] = best; bix[tid] = bi;
    __syncthreads();
    for (int o = 128; o > 0; o >>= 1) {
        if (tid < o) {
            if (bv[tid + o] < bv[tid] || (bv[tid + o] == bv[tid] && bix[tid + o] < bix[tid])) {
                bv[tid] = bv[tid + o]; bix[tid] = bix[tid + o];
            }
        }
        __syncthreads();
    }
    if (tid == 0) tgt[n] = bix[0];
}

// ---------------- weight transpose-convert (coalesced 16B writes) ----------------
__global__ void __launch_bounds__(256) tconv_kernel(const float* __restrict__ W,
                                                    __nv_bfloat16* __restrict__ Wt,
                                                    int K, int N)
{
    W  += (size_t)blockIdx.z * K * N;
    Wt += (size_t)blockIdx.z * K * N;
    __shared__ float tile[64][33];
    int n0 = blockIdx.x * 32, k0 = blockIdx.y * 64;
    int nx = threadIdx.x & 31, ky = threadIdx.x >> 5;
#pragma unroll
    for (int i = 0; i < 64; i += 8)
        tile[ky + i][nx] = W[(size_t)(k0 + ky + i) * N + n0 + nx];
    __syncthreads();
    int n = threadIdx.x >> 3, kg = threadIdx.x & 7;
    __nv_bfloat16 v[8];
#pragma unroll
    for (int j = 0; j < 8; j++)
        v[j] = __float2bfloat16(tile[kg * 8 + j][n]);
    *(float4*)&Wt[(size_t)(n0 + n) * K + k0 + kg * 8] = *(float4*)v;
}

// ---------------- embedding transpose + hi/lo split ----------------
__global__ void __launch_bounds__(256) embsplit_kernel(const float* __restrict__ emb,
                                                       __nv_bfloat16* __restrict__ embt)
{
    __shared__ float tile[32][33];
    int v0 = blockIdx.x * 32, e0 = blockIdx.y * 32;
    int tx = threadIdx.x & 31, ty = threadIdx.x >> 5;
#pragma unroll
    for (int i = 0; i < 32; i += 8)
        tile[ty + i][tx] = emb[(size_t)(e0 + ty + i) * VV + v0 + tx];
    __syncthreads();
#pragma unroll
    for (int i = 0; i < 32; i += 8) {
        float a = tile[tx][ty + i];
        int v = v0 + ty + i, e = e0 + tx;
        __nv_bfloat16 hi = __float2bfloat16(a);
        __nv_bfloat16 lo = __float2bfloat16(a - __bfloat162float(hi));
        size_t base = (size_t)v * KSP;
        embt[base + e] = hi;
        embt[base + DD + e] = lo;
        embt[base + 2 * DD + e] = hi;
    }
}

// ---------------- z hi/lo split (compact rows) ----------------
__global__ void __launch_bounds__(256) zsplit_kernel(const float* __restrict__ z,
                                                     __nv_bfloat16* __restrict__ zs,
                                                     const int* __restrict__ nactpad)
{
    int idx = blockIdx.x * 256 + threadIdx.x;
    int n = idx >> 9, e = idx & 511;
    if (n >= *nactpad) return;
    float a = z[idx];
    __nv_bfloat16 hi = __float2bfloat16(a);
    __nv_bfloat16 lo = __float2bfloat16(a - __bfloat162float(hi));
    size_t base = (size_t)n * KSP;
    zs[base + e] = hi;
    zs[base + DD + e] = hi;
    zs[base + 2 * DD + e] = lo;
}

// =======================================================================
// bf16 HMMA flash attention
// =======================================================================
__global__ void __launch_bounds__(128) attnmma_kernel(const __nv_bfloat16* __restrict__ qkvb,
                                                      const int* __restrict__ lens,
                                                      __nv_bfloat16* __restrict__ out)
{
    const int b = blockIdx.z, h = blockIdx.y, q0 = blockIdx.x * 64;
    const int len = lens[b];
    if (q0 >= len) return;
    const int tid = threadIdx.x;
    const int wid = tid >> 5, lane = tid & 31;
    const int ktmax = (len + 63) >> 6;

    __shared__ __align__(128) __nv_bfloat16 Qs[64 * 64];
    __shared__ __align__(128) __nv_bfloat16 KB[2][64 * 64];
    __shared__ __align__(128) __nv_bfloat16 VB[2][64 * 64];
    const uint32_t sq = smem_u32(Qs);
    const uint32_t skb[2] = { smem_u32(KB[0]), smem_u32(KB[1]) };
    const uint32_t svb[2] = { smem_u32(VB[0]), smem_u32(VB[1]) };

    auto load_kv = [&](int kt) {
        const __nv_bfloat16* kbase = qkvb + (size_t)(b * TT + kt * 64) * (3 * DD) + DD + h * HD;
        const __nv_bfloat16* vbase = qkvb + (size_t)(b * TT + kt * 64) * (3 * DD) + 2 * DD + h * HD;
        uint32_t dk = skb[kt & 1], dv = svb[kt & 1];
#pragma unroll
        for (int c = 0; c < 4; c++) {
            int idx = tid * 4 + c;
            int row = idx >> 3, seg = idx & 7;
            uint32_t off = SWZ((uint32_t)(row * 128 + seg * 16));
            cp16(dk + off, kbase + (size_t)row * (3 * DD) + seg * 8);
            cp16(dv + off, vbase + (size_t)row * (3 * DD) + seg * 8);
        }
        asm volatile("cp.async.commit_group;");
    };

    {
        const __nv_bfloat16* base = qkvb + (size_t)(b * TT + q0) * (3 * DD) + h * HD;
#pragma unroll
        for (int c = 0; c < 4; c++) {
            int idx = tid * 4 + c;
            int row = idx >> 3, seg = idx & 7;
            cp16(sq + SWZ((uint32_t)(row * 128 + seg * 16)), base + (size_t)row * (3 * DD) + seg * 8);
        }
        asm volatile("cp.async.commit_group;");
    }
    load_kv(0);
    asm volatile("cp.async.wait_group 0;");
    __syncthreads();

    uint32_t af[4][4];
#pragma unroll
    for (int ks = 0; ks < 4; ks++) {
        int row = wid * 16 + (lane & 15);
        uint32_t addr = sq + SWZ((uint32_t)(row * 128 + ks * 32 + ((lane >> 4) << 4)));
        ldsm_x4(af[ks][0], af[ks][1], af[ks][2], af[ks][3], addr);
    }

    float m0 = -1e30f, m1 = -1e30f, l0 = 0.f, l1 = 0.f;
    float oacc[8][4];
#pragma unroll
    for (int nb = 0; nb < 8; nb++)
#pragma unroll
        for (int q = 0; q < 4; q++) oacc[nb][q] = 0.f;

    const int g = lane >> 2, tq = lane & 3;

    for (int kt = 0; kt < ktmax; kt++) {
        if (kt + 1 < ktmax) load_kv(kt + 1);

        const uint32_t sk = skb[kt & 1], sv = svb[kt & 1];

        float s[8][4];
#pragma unroll
        for (int nb = 0; nb < 8; nb++)
#pragma unroll
            for (int q = 0; q < 4; q++) s[nb][q] = 0.f;
#pragma unroll
        for (int ks = 0; ks < 4; ks++) {
            uint32_t bf[8][2];
#pragma unroll
            for (int p = 0; p < 4; p++) {
                int nr = p * 16 + ((lane >> 4) << 3) + (lane & 7);
                uint32_t addr = sk + SWZ((uint32_t)(nr * 128 + ks * 32 + (((lane >> 3) & 1) << 4)));
                ldsm_x4(bf[p * 2][0], bf[p * 2][1], bf[p * 2 + 1][0], bf[p * 2 + 1][1], addr);
            }
#pragma unroll
            for (int nb = 0; nb < 8; nb++)
                mma16816(s[nb], af[ks], bf[nb]);
        }

#pragma unroll
        for (int nb = 0; nb < 8; nb++) {
            int k0c = kt * 64 + nb * 8 + tq * 2;
            float ba = (k0c < len) ? 0.f : -1e9f;
            float bb2 = (k0c + 1 < len) ? 0.f : -1e9f;
            s[nb][0] = s[nb][0] * 0.125f + ba;
            s[nb][1] = s[nb][1] * 0.125f + bb2;
            s[nb][2] = s[nb][2] * 0.125f + ba;
            s[nb][3] = s[nb][3] * 0.125f + bb2;
        }

        float mt0 = -1e30f, mt1 = -1e30f;
#pragma unroll
        for (int nb = 0; nb < 8; nb++) {
            mt0 = fmaxf(mt0, fmaxf(s[nb][0], s[nb][1]));
            mt1 = fmaxf(mt1, fmaxf(s[nb][2], s[nb][3]));
        }
        mt0 = fmaxf(mt0, __shfl_xor_sync(0xffffffffu, mt0, 1));
        mt0 = fmaxf(mt0, __shfl_xor_sync(0xffffffffu, mt0, 2));
        mt1 = fmaxf(mt1, __shfl_xor_sync(0xffffffffu, mt1, 1));
        mt1 = fmaxf(mt1, __shfl_xor_sync(0xffffffffu, mt1, 2));

        float mn0 = fmaxf(m0, mt0), mn1 = fmaxf(m1, mt1);
        float a0 = __expf(m0 - mn0), a1 = __expf(m1 - mn1);
        m0 = mn0; m1 = mn1;

        float r0 = 0.f, r1 = 0.f;
#pragma unroll
        for (int nb = 0; nb < 8; nb++) {
            s[nb][0] = __expf(s[nb][0] - m0);
            s[nb][1] = __expf(s[nb][1] - m0);
            s[nb][2] = __expf(s[nb][2] - m1);
            s[nb][3] = __expf(s[nb][3] - m1);
            r0 += s[nb][0] + s[nb][1];
            r1 += s[nb][2] + s[nb][3];
        }
        r0 += __shfl_xor_sync(0xffffffffu, r0, 1);
        r0 += __shfl_xor_sync(0xffffffffu, r0, 2);
        r1 += __shfl_xor_sync(0xffffffffu, r1, 1);
        r1 += __shfl_xor_sync(0xffffffffu, r1, 2);
        l0 = l0 * a0 + r0;
        l1 = l1 * a1 + r1;

#pragma unroll
        for (int nb = 0; nb < 8; nb++) {
            oacc[nb][0] *= a0; oacc[nb][1] *= a0;
            oacc[nb][2] *= a1; oacc[nb][3] *= a1;
        }

        uint32_t ap[4][4];
#pragma unroll
        for (int kk = 0; kk < 4; kk++) {
            ap[kk][0] = packbf(s[2 * kk][0],     s[2 * kk][1]);
            ap[kk][1] = packbf(s[2 * kk][2],     s[2 * kk][3]);
            ap[kk][2] = packbf(s[2 * kk + 1][0], s[2 * kk + 1][1]);
            ap[kk][3] = packbf(s[2 * kk + 1][2], s[2 * kk + 1][3]);
        }

#pragma unroll
        for (int kk = 0; kk < 4; kk++) {
            uint32_t bfv[8][2];
#pragma unroll
            for (int p = 0; p < 4; p++) {
                int key = kk * 16 + ((lane >> 3) & 1) * 8 + (lane & 7);
                uint32_t dbyte = (uint32_t)(p * 32 + ((lane >> 4) & 1) * 16);
                uint32_t addr = sv + SWZ((uint32_t)(key * 128) + dbyte);
                ldsm_x4_t(bfv[p * 2][0], bfv[p * 2][1], bfv[p * 2 + 1][0], bfv[p * 2 + 1][1], addr);
            }
#pragma unroll
            for (int nb = 0; nb < 8; nb++)
                mma16816(oacc[nb], ap[kk], bfv[nb]);
        }

        if (kt + 1 < ktmax) {
            asm volatile("cp.async.wait_group 0;");
            __syncthreads();
        }
    }

    float i0 = 1.f / l0, i1 = 1.f / l1;
    int row0 = b * TT + q0 + wid * 16 + g;
#pragma unroll
    for (int nb = 0; nb < 8; nb++) {
        int col = h * HD + nb * 8 + tq * 2;
        *(__nv_bfloat162*)(out + (size_t)row0 * DD + col) =
            __nv_bfloat162(__float2bfloat16(oacc[nb][0] * i0), __float2bfloat16(oacc[nb][1] * i0));
        *(__nv_bfloat162*)(out + (size_t)(row0 + 8) * DD + col) =
            __nv_bfloat162(__float2bfloat16(oacc[nb][2] * i1), __float2bfloat16(oacc[nb][3] * i1));
    }
}

// ---------------- compact row loss ----------------
__global__ void __launch_bounds__(256) rowloss_kernel(const float* __restrict__ big,
                                                      const int* __restrict__ tgt,
                                                      const int* __restrict__ nact,
                                                      float* __restrict__ ent)
{
    const int n = blockIdx.x;
    if (n >= *nact) return;
    const float* row = big + (size_t)n * VV;
    const int tid = threadIdx.x;
    float mx = -1e30f;
    for (int v = tid; v < VV; v += 256) mx = fmaxf(mx, row[v]);
    __shared__ float sm[256];
    sm[tid] = mx;
    __syncthreads();
    for (int o = 128; o > 0; o >>= 1) {
        if (tid < o) sm[tid] = fmaxf(sm[tid], sm[tid + o]);
        __syncthreads();
    }
    mx = sm[0];
    __syncthreads();
    float s = 0.f;
    for (int v = tid; v < VV; v += 256) s += __expf(row[v] - mx);
    sm[tid] = s;
    __syncthreads();
    for (int o = 128; o > 0; o >>= 1) {
        if (tid < o) sm[tid] += sm[tid + o];
        __syncthreads();
    }
    if (tid == 0) ent[n] = mx + logf(sm[0]) - row[tgt[n]];
}

__global__ void __launch_bounds__(1024) finalize_kernel(const float* __restrict__ ent,
                                                        const int* __restrict__ nact,
                                                        float* __restrict__ out)
{
    const int tid = threadIdx.x;
    const int N = *nact;
    float s = 0.f;
    for (int n = tid; n < N; n += 1024) s += ent[n];
    __shared__ float ss[1024];
    ss[tid] = s;
    __syncthreads();
    for (int o = 512; o > 0; o >>= 1) {
        if (tid < o) ss[tid] += ss[tid + o];
        __syncthreads();
    }
    if (tid == 0) out[0] = ss[0] / (float)N;
}

// ---------------- host ----------------
extern "C" void kernel_launch(void* const* d_in, const int* in_sizes, int n_in,
                              void* d_out, int out_size)
{
    (void)in_sizes; (void)n_in; (void)out_size;
    const float*    xs    = (const float*)d_in[0];
    const int*      lens  = (const int*)d_in[1];
    const unsigned* mask  = (const unsigned*)d_in[2];
    const float*    W_emb = (const float*)d_in[3];
    const float*    ln1_s = (const float*)d_in[4];
    const float*    ln1_b = (const float*)d_in[5];
    const float*    Wqkv  = (const float*)d_in[6];
    const float*    Wo    = (const float*)d_in[7];
    const float*    ln2_s = (const float*)d_in[8];
    const float*    ln2_b = (const float*)d_in[9];
    const float*    W1    = (const float*)d_in[10];
    const float*    W2    = (const float*)d_in[11];
    const float*    an_s  = (const float*)d_in[12];
    const float*    an_b  = (const float*)d_in[13];
    const float*    iln_s = (const float*)d_in[14];
    const float*    iln_b = (const float*)d_in[15];
    const float*    memb  = (const float*)d_in[16];
    const float*    top   = (const float*)d_in[17];
    const float*    proj  = (const float*)d_in[18];
    const float*    emb   = (const float*)d_in[19];

    float *px, *pres, *ph, *pz, *pbig, *penorm, *pent;
    int *ptgt, *pactidx, *pnact, *pnactpad;
    __nv_bfloat16 *phb, *pqkvb, *pattnb, *pffnb, *pzs, *pembt, *pwqkvt, *pwot, *pw1t, *pw2t, *ptopt;
    cudaGetSymbolAddress((void**)&px, g_x);
    cudaGetSymbolAddress((void**)&pres, g_res);
    cudaGetSymbolAddress((void**)&ph, g_h);
    cudaGetSymbolAddress((void**)&pz, g_z);
    cudaGetSymbolAddress((void**)&pbig, g_big);
    cudaGetSymbolAddress((void**)&penorm, g_enorm);
    cudaGetSymbolAddress((void**)&pent, g_ent);
    cudaGetSymbolAddress((void**)&ptgt, g_tgt);
    cudaGetSymbolAddress((void**)&pactidx, g_actidx);
    cudaGetSymbolAddress((void**)&pnact, g_nact);
    cudaGetSymbolAddress((void**)&pnactpad, g_nactpad);
    cudaGetSymbolAddress((void**)&phb, g_hb);
    cudaGetSymbolAddress((void**)&pqkvb, g_qkvb);
    cudaGetSymbolAddress((void**)&pattnb, g_attnb);
    cudaGetSymbolAddress((void**)&pffnb, g_ffnb);
    cudaGetSymbolAddress((void**)&pzs, g_zs);
    cudaGetSymbolAddress((void**)&pembt, g_embt);
    cudaGetSymbolAddress((void**)&pwqkvt, g_wqkvt);
    cudaGetSymbolAddress((void**)&pwot, g_wot);
    cudaGetSymbolAddress((void**)&pw1t, g_w1t);
    cudaGetSymbolAddress((void**)&pw2t, g_w2t);
    cudaGetSymbolAddress((void**)&ptopt, g_topt);

    cudaFuncSetAttribute(hgemm_kernel<0>, cudaFuncAttributeMaxDynamicSharedMemorySize, HG_SMEM);
    cudaFuncSetAttribute(hgemm_kernel<1>, cudaFuncAttributeMaxDynamicSharedMemorySize, HG_SMEM);
    cudaFuncSetAttribute(hgemm_kernel<2>, cudaFuncAttributeMaxDynamicSharedMemorySize, HG_SMEM);
    cudaFuncSetAttribute(hgemm_kernel<3>, cudaFuncAttributeMaxDynamicSharedMemorySize, HG_SMEM);

    dim3 tb(256);

    // ---- weight prep ----
    tconv_kernel<<<dim3(3 * DD / 32, DD / 64, LL), tb>>>(Wqkv, pwqkvt, DD, 3 * DD);
    tconv_kernel<<<dim3(DD / 32, DD / 64, LL), tb>>>(Wo, pwot, DD, DD);
    tconv_kernel<<<dim3(FF / 32, DD / 64, LL), tb>>>(W1, pw1t, DD, FF);
    tconv_kernel<<<dim3(DD / 32, FF / 64, LL), tb>>>(W2, pw2t, FF, DD);
    tconv_kernel<<<dim3(VV / 32, DD / 64, 1), tb>>>(top, ptopt, DD, VV);
    embsplit_kernel<<<dim3(VV / 32, DD / 32), tb>>>(emb, pembt);
    enorm_kernel<<<VV / 256, tb>>>(emb, penorm);

    // ---- active-row compaction ----
    scan_kernel<<<1, 1024>>>(mask, lens, pactidx, pnact, pnactpad);

    // ---- 1. embed (fp32, lens-limited) + PE ----
    sgemm_kernel<<<dim3(DD / BN, NTOK / BM), tb>>>(NTOK, DD, DD, xs, W_emb, px, nullptr, lens);
    pe_add_kernel<<<NTOK, tb>>>(px, lens);

    // ---- 2. targets on ACTIVE rows only ----
    lnw_kernel<float, true><<<NTOK / 8, tb>>>(px, ph, iln_s, iln_b, nullptr, pnactpad, pactidx);
    sgemm_kernel<<<dim3(DD / BN, NTOK / BM), tb>>>(NTOK, DD, DD, ph, proj, pz, pnactpad, nullptr);
    zsplit_kernel<<<(NTOK * DD) / 256, tb>>>(pz, pzs, pnactpad);
    hgemm_kernel<0><<<dim3(VV / 128, NTOK / 128), 256, HG_SMEM>>>(NTOK, VV, KSP, pzs, pembt, pbig, nullptr, pnactpad, nullptr, nullptr);
    argmin_kernel<<<NTOK, tb>>>(pbig, penorm, ptgt, pnact);

    // ---- 3. masked stream ----
    maskmix_kernel<<<(NTOK * DD) / 256, tb>>>(px, mask, memb, pres);

    // ---- 4. encoder layers 0..4 (full, lens-limited) ----
    for (int l = 0; l < LL - 1; l++) {
        lnw_kernel<__nv_bfloat16, false><<<NTOK / 8, tb>>>(pres, phb, ln1_s + l * DD, ln1_b + l * DD, lens, nullptr, nullptr);
        hgemm_kernel<3><<<dim3(3 * DD / 128, NTOK / 128), 256, HG_SMEM>>>(NTOK, 3 * DD, DD,
                phb, pwqkvt + (size_t)l * 3 * DD * DD, nullptr, pqkvb, nullptr, lens, nullptr);
        attnmma_kernel<<<dim3(TT / 64, HH, 8), 128>>>(pqkvb, lens, pattnb);
        hgemm_kernel<1><<<dim3(DD / 128, NTOK / 128), 256, HG_SMEM>>>(NTOK, DD, DD,
                pattnb, pwot + (size_t)l * DD * DD, pres, nullptr, nullptr, lens, nullptr);
        lnw_kernel<__nv_bfloat16, false><<<NTOK / 8, tb>>>(pres, phb, ln2_s + l * DD, ln2_b + l * DD, lens, nullptr, nullptr);
        hgemm_kernel<2><<<dim3(FF / 128, NTOK / 128), 256, HG_SMEM>>>(NTOK, FF, DD,
                phb, pw1t + (size_t)l * FF * DD, nullptr, pffnb, nullptr, lens, nullptr);
        hgemm_kernel<1><<<dim3(DD / 128, NTOK / 128), 256, HG_SMEM>>>(NTOK, DD, FF,
                pffnb, pw2t + (size_t)l * DD * FF, pres, nullptr, nullptr, lens, nullptr);
    }

    // ---- last layer: attention full, post-attention COMPACT (active rows only) ----
    {
        const int l = LL - 1;
        lnw_kernel<__nv_bfloat16, false><<<NTOK / 8, tb>>>(pres, phb, ln1_s + l * DD, ln1_b + l * DD, lens, nullptr, nullptr);
        hgemm_kernel<3><<<dim3(3 * DD / 128, NTOK / 128), 256, HG_SMEM>>>(NTOK, 3 * DD, DD,
                phb, pwqkvt + (size_t)l * 3 * DD * DD, nullptr, pqkvb, nullptr, lens, nullptr);
        attnmma_kernel<<<dim3(TT / 64, HH, 8), 128>>>(pqkvb, lens, pattnb);
        // compact residual: ph[i] = pres[actidx[i]]
        gather_kernel<<<NTOK, 128>>>(pres, ph, pactidx, pnactpad);
        // ph += gathered(attn) @ Wo   (A-row gather, compact C)
        hgemm_kernel<1><<<dim3(DD / 128, NTOK / 128), 256, HG_SMEM>>>(NTOK, DD, DD,
                pattnb, pwot + (size_t)l * DD * DD, ph, nullptr, pnactpad, nullptr, pactidx);
        // LN2 compact
        lnw_kernel<__nv_bfloat16, false><<<NTOK / 8, tb>>>(ph, phb, ln2_s + l * DD, ln2_b + l * DD, nullptr, pnactpad, nullptr);
        // FFN compact
        hgemm_kernel<2><<<dim3(FF / 128, NTOK / 128), 256, HG_SMEM>>>(NTOK, FF, DD,
                phb, pw1t + (size_t)l * FF * DD, nullptr, pffnb, pnactpad, nullptr, nullptr);
        hgemm_kernel<1><<<dim3(DD / 128, NTOK / 128), 256, HG_SMEM>>>(NTOK, DD, FF,
                pffnb, pw2t + (size_t)l * DD * FF, ph, nullptr, pnactpad, nullptr, nullptr);
    }

    // ---- 5. final LN (compact) + logits + loss ----
    lnw_kernel<__nv_bfloat16, false><<<NTOK / 8, tb>>>(ph, phb, an_s, an_b, nullptr, pnactpad, nullptr);
    hgemm_kernel<0><<<dim3(VV / 128, NTOK / 128), 256, HG_SMEM>>>(NTOK, VV, DD, phb, ptopt, pbig, nullptr, pnactpad, nullptr, nullptr);
    rowloss_kernel<<<NTOK, tb>>>(pbig, ptgt, pnact, pent);
    finalize_kernel<<<1, 1024>>>(pent, pnact, (float*)d_out);
}

// round 14
// speedup vs baseline: 6.8098x; 1.0204x over previous
#include <cuda_runtime.h>
#include <cuda_bf16.h>
#include <math.h>
#include <stdint.h>

// ---------------- model dims ----------------
#define NTOK 8192
#define TT   1024
#define DD   512
#define FF   2048
#define VV   8192
#define HH   8
#define HD   64
#define LL   6
#define KSP  1536

// ---------------- scratch ----------------
__device__ float g_x   [NTOK * DD];
__device__ float g_res [NTOK * DD];
__device__ float g_h   [NTOK * DD];        // dist-path LN rows; later compact residual
__device__ float g_z   [NTOK * DD];
__device__ float g_big [(size_t)NTOK * VV];
__device__ float g_enorm[VV];
__device__ int   g_tgt [NTOK];
__device__ float g_ent [NTOK];
__device__ int   g_actidx[NTOK];
__device__ int   g_nact;
__device__ int   g_nactpad;
__device__ __nv_bfloat16 g_hb   [NTOK * DD];
__device__ __nv_bfloat16 g_qkvb [NTOK * 3 * DD];
__device__ __nv_bfloat16 g_attnb[NTOK * DD];
__device__ __nv_bfloat16 g_ffnb [NTOK * FF];
__device__ __nv_bfloat16 g_zs   [(size_t)NTOK * KSP];   // xs-split for embed, then z-split for dist
__device__ __nv_bfloat16 g_embt [(size_t)VV * KSP];
__device__ __nv_bfloat16 g_wembs[DD * KSP];             // split W_embed [N=512][3K]
__device__ __nv_bfloat16 g_wqkvt[LL * 3 * DD * DD];
__device__ __nv_bfloat16 g_wot  [LL * DD * DD];
__device__ __nv_bfloat16 g_w1t  [LL * FF * DD];
__device__ __nv_bfloat16 g_w2t  [LL * DD * FF];
__device__ __nv_bfloat16 g_topt [VV * DD];

// ---------------- helpers ----------------
__device__ __forceinline__ uint32_t smem_u32(const void* p) {
    uint32_t a;
    asm("{ .reg .u64 t; cvta.to.shared.u64 t, %1; cvt.u32.u64 %0, t; }" : "=r"(a) : "l"(p));
    return a;
}
__device__ __forceinline__ void cp16(uint32_t dst, const void* src) {
    asm volatile("cp.async.cg.shared.global [%0], [%1], 16;" :: "r"(dst), "l"(src));
}
__device__ __forceinline__ void ldsm_x4(uint32_t& r0, uint32_t& r1, uint32_t& r2, uint32_t& r3, uint32_t addr) {
    asm volatile("ldmatrix.sync.aligned.m8n8.x4.shared.b16 {%0,%1,%2,%3}, [%4];"
                 : "=r"(r0), "=r"(r1), "=r"(r2), "=r"(r3) : "r"(addr));
}
__device__ __forceinline__ void ldsm_x4_t(uint32_t& r0, uint32_t& r1, uint32_t& r2, uint32_t& r3, uint32_t addr) {
    asm volatile("ldmatrix.sync.aligned.m8n8.x4.trans.shared.b16 {%0,%1,%2,%3}, [%4];"
                 : "=r"(r0), "=r"(r1), "=r"(r2), "=r"(r3) : "r"(addr));
}
__device__ __forceinline__ void mma16816(float* d, const uint32_t* a, const uint32_t* b) {
    asm volatile("mma.sync.aligned.m16n8k16.row.col.f32.bf16.bf16.f32 "
                 "{%0,%1,%2,%3}, {%4,%5,%6,%7}, {%8,%9}, {%0,%1,%2,%3};"
                 : "+f"(d[0]), "+f"(d[1]), "+f"(d[2]), "+f"(d[3])
                 : "r"(a[0]), "r"(a[1]), "r"(a[2]), "r"(a[3]), "r"(b[0]), "r"(b[1]));
}
__device__ __forceinline__ uint32_t packbf(float a, float b) {
    __nv_bfloat162 t(__float2bfloat16(a), __float2bfloat16(b));
    return *(uint32_t*)&t;
}
#define SWZ(o) ((o) ^ (((o) >> 3) & 0x70))

// =======================================================================
// bf16 HMMA GEMM, 3-stage cp.async pipeline.
// MODE 0: fp32 store; 1: fp32 +=; 2: bf16 relu; 3: bf16 store
// rowlim: skip blocks with bm >= *rowlim
// blens:  skip blocks with (bm%1024) >= blens[bm/1024]
// agidx:  if non-null, A rows gathered via agidx[bm+row]; C rows compact
// =======================================================================
#define HG_SMEM (3 * 32768)

template <int MODE>
__global__ void __launch_bounds__(256) hgemm_kernel(int M, int N, int K,
                                                    const __nv_bfloat16* __restrict__ A,
                                                    const __nv_bfloat16* __restrict__ Bt,
                                                    float* __restrict__ Cf,
                                                    __nv_bfloat16* __restrict__ Cb,
                                                    const int* __restrict__ rowlim,
                                                    const int* __restrict__ blens,
                                                    const int* __restrict__ agidx)
{
    const int bm = blockIdx.y * 128, bn = blockIdx.x * 128;
    if (rowlim && bm >= *rowlim) return;
    if (blens && (bm & 1023) >= blens[bm >> 10]) return;
    extern __shared__ char smem[];
    const uint32_t sb = smem_u32(smem);
    const int tid  = threadIdx.x;
    const int wid  = tid >> 5, lane = tid & 31;
    const int wm   = wid >> 2;
    const int wn   = wid & 3;
    const int nch  = K >> 6;

    auto load_chunk = [&](int ci) {
        uint32_t buf = sb + (uint32_t)(ci % 3) * 32768u;
        const __nv_bfloat16* bp = Bt + (size_t)bn * K + (size_t)ci * 64;
#pragma unroll
        for (int c = 0; c < 4; c++) {
            int idx = tid * 4 + c;
            int row = idx >> 3, seg = idx & 7;
            uint32_t off = SWZ((uint32_t)(row * 128 + seg * 16));
            int ra = agidx ? agidx[bm + row] : (bm + row);
            cp16(buf + off,          A + (size_t)ra * K + (size_t)ci * 64 + seg * 8);
            cp16(buf + 16384u + off, bp + (size_t)row * K + seg * 8);
        }
        asm volatile("cp.async.commit_group;");
    };

    load_chunk(0);
    if (nch > 1) load_chunk(1);
    if (nch > 2) load_chunk(2);

    float acc[4][4][4];
#pragma unroll
    for (int mi = 0; mi < 4; mi++)
#pragma unroll
        for (int ni = 0; ni < 4; ni++)
#pragma unroll
            for (int q = 0; q < 4; q++) acc[mi][ni][q] = 0.f;

    for (int ci = 0; ci < nch; ci++) {
        if (ci + 3 <= nch)      asm volatile("cp.async.wait_group 2;");
        else if (ci + 2 == nch) asm volatile("cp.async.wait_group 1;");
        else                    asm volatile("cp.async.wait_group 0;");
        __syncthreads();

        uint32_t ab = sb + (uint32_t)(ci % 3) * 32768u;
        uint32_t bb = ab + 16384u;
#pragma unroll
        for (int ks = 0; ks < 4; ks++) {
            uint32_t af[4][4], bf[4][2];
#pragma unroll
            for (int mi = 0; mi < 4; mi++) {
                int row = wm * 64 + mi * 16 + (lane & 15);
                uint32_t addr = ab + SWZ((uint32_t)(row * 128 + ks * 32 + ((lane >> 4) << 4)));
                ldsm_x4(af[mi][0], af[mi][1], af[mi][2], af[mi][3], addr);
            }
#pragma unroll
            for (int p = 0; p < 2; p++) {
                int nr = wn * 32 + p * 16 + ((lane >> 4) << 3) + (lane & 7);
                uint32_t addr = bb + SWZ((uint32_t)(nr * 128 + ks * 32 + (((lane >> 3) & 1) << 4)));
                ldsm_x4(bf[p * 2][0], bf[p * 2][1], bf[p * 2 + 1][0], bf[p * 2 + 1][1], addr);
            }
#pragma unroll
            for (int mi = 0; mi < 4; mi++)
#pragma unroll
                for (int ni = 0; ni < 4; ni++)
                    mma16816(acc[mi][ni], af[mi], bf[ni]);
        }
        __syncthreads();
        if (ci + 3 < nch) load_chunk(ci + 3);
    }

    const int g = lane >> 2, tig = lane & 3;
#pragma unroll
    for (int mi = 0; mi < 4; mi++) {
#pragma unroll
        for (int ni = 0; ni < 4; ni++) {
            int r0 = bm + wm * 64 + mi * 16 + g;
            int c0 = bn + wn * 32 + ni * 8 + tig * 2;
            float* a4 = acc[mi][ni];
            if (MODE == 0) {
                *(float2*)(Cf + (size_t)r0 * N + c0)       = make_float2(a4[0], a4[1]);
                *(float2*)(Cf + (size_t)(r0 + 8) * N + c0) = make_float2(a4[2], a4[3]);
            } else if (MODE == 1) {
                float2* d0 = (float2*)(Cf + (size_t)r0 * N + c0);
                float2* d1 = (float2*)(Cf + (size_t)(r0 + 8) * N + c0);
                float2 o0 = *d0, o1 = *d1;
                o0.x += a4[0]; o0.y += a4[1];
                o1.x += a4[2]; o1.y += a4[3];
                *d0 = o0; *d1 = o1;
            } else if (MODE == 2) {
                *(__nv_bfloat162*)(Cb + (size_t)r0 * N + c0) =
                    __nv_bfloat162(__float2bfloat16(fmaxf(a4[0], 0.f)), __float2bfloat16(fmaxf(a4[1], 0.f)));
                *(__nv_bfloat162*)(Cb + (size_t)(r0 + 8) * N + c0) =
                    __nv_bfloat162(__float2bfloat16(fmaxf(a4[2], 0.f)), __float2bfloat16(fmaxf(a4[3], 0.f)));
            } else {
                *(__nv_bfloat162*)(Cb + (size_t)r0 * N + c0) =
                    __nv_bfloat162(__float2bfloat16(a4[0]), __float2bfloat16(a4[1]));
                *(__nv_bfloat162*)(Cb + (size_t)(r0 + 8) * N + c0) =
                    __nv_bfloat162(__float2bfloat16(a4[2]), __float2bfloat16(a4[3]));
            }
        }
    }
}

// ---------------- fp32 SGEMM (projection only) ----------------
#define BM 128
#define BN 128
#define BK 8
__global__ void __launch_bounds__(256) sgemm_kernel(int M, int N, int K,
                                                    const float* __restrict__ A,
                                                    const float* __restrict__ B,
                                                    float* __restrict__ C,
                                                    const int* __restrict__ rowlim,
                                                    const int* __restrict__ blens)
{
    const int bm = blockIdx.y * BM, bn = blockIdx.x * BN;
    if (rowlim && bm >= *rowlim) return;
    if (blens && (bm & 1023) >= blens[bm >> 10]) return;
    __shared__ float As[BK][BM];
    __shared__ float Bs[BK][BN];
    const int tid = threadIdx.x;
    const int tx = tid & 15, ty = tid >> 4;
    float acc[8][8];
#pragma unroll
    for (int i = 0; i < 8; i++)
#pragma unroll
        for (int j = 0; j < 8; j++) acc[i][j] = 0.f;
    const int aRow = tid >> 1, aCol = (tid & 1) * 4;
    const int bRow = tid >> 5, bCol = (tid & 31) * 4;
    const float* Aptr = A + (size_t)(bm + aRow) * K + aCol;
    const float* Bptr = B + (size_t)bRow * N + bn + bCol;
    for (int k0 = 0; k0 < K; k0 += BK) {
        float4 av = *(const float4*)(Aptr + k0);
        float4 bv = *(const float4*)(Bptr + (size_t)k0 * N);
        As[aCol + 0][aRow] = av.x; As[aCol + 1][aRow] = av.y;
        As[aCol + 2][aRow] = av.z; As[aCol + 3][aRow] = av.w;
        *(float4*)&Bs[bRow][bCol] = bv;
        __syncthreads();
#pragma unroll
        for (int k = 0; k < BK; k++) {
            float a[8], b[8];
#pragma unroll
            for (int i = 0; i < 8; i++) a[i] = As[k][ty * 8 + i];
#pragma unroll
            for (int j = 0; j < 8; j++) b[j] = Bs[k][tx * 8 + j];
#pragma unroll
            for (int i = 0; i < 8; i++)
#pragma unroll
                for (int j = 0; j < 8; j++) acc[i][j] += a[i] * b[j];
        }
        __syncthreads();
    }
#pragma unroll
    for (int i = 0; i < 8; i++) {
        float* crow = C + (size_t)(bm + ty * 8 + i) * N + bn + tx * 8;
#pragma unroll
        for (int j = 0; j < 8; j += 4)
            *(float4*)(crow + j) = make_float4(acc[i][j], acc[i][j + 1], acc[i][j + 2], acc[i][j + 3]);
    }
}

// ---------------- PE add (lens-limited) ----------------
__global__ void __launch_bounds__(256) pe_add_kernel(float* __restrict__ x,
                                                     const int* __restrict__ lens)
{
    const int n = blockIdx.x;
    const int t = n & (TT - 1);
    if (t >= ((lens[n >> 10] + 127) & ~127)) return;
    const int j = threadIdx.x;
    double freq = exp(-(double)j * (9.210340371976184 / 256.0));
    double ang = (double)t * freq;
    float* p = x + (size_t)n * DD + 2 * j;
    p[0] += (float)sin(ang);
    p[1] += (float)cos(ang);
}

// ---------------- warp-per-row layernorm ----------------
template <typename T, bool GATHER>
__global__ void __launch_bounds__(256) lnw_kernel(const float* __restrict__ in,
                                                  T* __restrict__ out,
                                                  const float* __restrict__ gam,
                                                  const float* __restrict__ bet,
                                                  const int* __restrict__ lens,
                                                  const int* __restrict__ rowlim,
                                                  const int* __restrict__ actidx)
{
    const int w = (blockIdx.x * 256 + threadIdx.x) >> 5;
    const int lane = threadIdx.x & 31;
    if (rowlim && w >= *rowlim) return;
    if (lens && (w & 1023) >= ((lens[w >> 10] + 127) & ~127)) return;
    const int src = GATHER ? actidx[w] : w;
    const float* row = in + (size_t)src * DD;
    float v[16];
    float s = 0.f, s2 = 0.f;
#pragma unroll
    for (int k = 0; k < 4; k++) {
        float4 t = *(const float4*)(row + k * 128 + lane * 4);
        v[k * 4 + 0] = t.x; v[k * 4 + 1] = t.y; v[k * 4 + 2] = t.z; v[k * 4 + 3] = t.w;
        s  += t.x + t.y + t.z + t.w;
        s2 += t.x * t.x + t.y * t.y + t.z * t.z + t.w * t.w;
    }
#pragma unroll
    for (int o = 16; o > 0; o >>= 1) {
        s  += __shfl_xor_sync(0xffffffffu, s, o);
        s2 += __shfl_xor_sync(0xffffffffu, s2, o);
    }
    const float mean = s * (1.f / DD);
    const float var = s2 * (1.f / DD) - mean * mean;
    const float r = rsqrtf(var + 1e-5f);
#pragma unroll
    for (int k = 0; k < 4; k++) {
        const int c = k * 128 + lane * 4;
        float o0 = (v[k * 4 + 0] - mean) * r * gam[c + 0] + bet[c + 0];
        float o1 = (v[k * 4 + 1] - mean) * r * gam[c + 1] + bet[c + 1];
        float o2 = (v[k * 4 + 2] - mean) * r * gam[c + 2] + bet[c + 2];
        float o3 = (v[k * 4 + 3] - mean) * r * gam[c + 3] + bet[c + 3];
        if (sizeof(T) == 4) {
            *(float4*)((float*)out + (size_t)w * DD + c) = make_float4(o0, o1, o2, o3);
        } else {
            uint2 pk;
            pk.x = packbf(o0, o1);
            pk.y = packbf(o2, o3);
            *(uint2*)((__nv_bfloat16*)out + (size_t)w * DD + c) = pk;
        }
    }
}

// ---------------- row gather (fp32, compact) ----------------
__global__ void __launch_bounds__(128) gather_kernel(const float* __restrict__ in,
                                                     float* __restrict__ out,
                                                     const int* __restrict__ actidx,
                                                     const int* __restrict__ nactpad)
{
    const int rowi = blockIdx.x;
    if (rowi >= *nactpad) return;
    const int src = actidx[rowi];
    const float4* s = (const float4*)(in + (size_t)src * DD);
    float4* d = (float4*)(out + (size_t)rowi * DD);
    d[threadIdx.x] = s[threadIdx.x];
}

// ---------------- active-row scan (pads actidx tail) ----------------
__global__ void __launch_bounds__(1024) scan_kernel(const unsigned* __restrict__ mask,
                                                    const int* __restrict__ lens,
                                                    int* __restrict__ actidx,
                                                    int* __restrict__ nact,
                                                    int* __restrict__ nactpad)
{
    const int t = threadIdx.x;
    bool f[8];
    int cnt = 0;
#pragma unroll
    for (int j = 0; j < 8; j++) {
        int n = t * 8 + j;
        int b = n >> 10, tt = n & 1023;
        f[j] = (tt < lens[b]) && (mask[n] != 0u);
        cnt += f[j] ? 1 : 0;
    }
    __shared__ int sc[1024];
    sc[t] = cnt;
    __syncthreads();
    for (int o = 1; o < 1024; o <<= 1) {
        int v = (t >= o) ? sc[t - o] : 0;
        __syncthreads();
        sc[t] += v;
        __syncthreads();
    }
    int pos = sc[t] - cnt;
#pragma unroll
    for (int j = 0; j < 8; j++)
        if (f[j]) actidx[pos++] = t * 8 + j;
    __syncthreads();
    int tot = sc[1023];
    int pad = (tot + 127) & ~127;
    if (pad == 0) pad = 128;
    if (t == 0) { *nact = tot; *nactpad = pad; }
    __syncthreads();
    int fill = actidx[0];
    for (int i = tot + t; i < pad; i += 1024) actidx[i] = fill;
}

// ---------------- mask mix ----------------
__global__ void __launch_bounds__(256) maskmix_kernel(const float* __restrict__ x,
                                                      const unsigned* __restrict__ mask,
                                                      const float* __restrict__ memb,
                                                      float* __restrict__ out)
{
    int idx = blockIdx.x * 256 + threadIdx.x;
    int n = idx >> 9, d = idx & 511;
    out[idx] = (mask[n] != 0u) ? memb[d] : x[idx];
}

// ---------------- codebook column norms ----------------
__global__ void __launch_bounds__(256) enorm_kernel(const float* __restrict__ emb,
                                                    float* __restrict__ enorm)
{
    int v = blockIdx.x * 256 + threadIdx.x;
    float s = 0.f;
    for (int e = 0; e < DD; e++) {
        float x = emb[(size_t)e * VV + v];
        s += x * x;
    }
    enorm[v] = s;
}

// ---------------- argmin (compact rows) ----------------
__global__ void __launch_bounds__(256) argmin_kernel(const float* __restrict__ big,
                                                     const float* __restrict__ enorm,
                                                     int* __restrict__ tgt,
                                                     const int* __restrict__ nact)
{
    const int n = blockIdx.x;
    if (n >= *nact) return;
    const float* row = big + (size_t)n * VV;
    const int tid = threadIdx.x;
    float best = 3.4e38f;
    int bi = 0;
    for (int v = tid; v < VV; v += 256) {
        float sc = enorm[v] - 2.f * row[v];
        if (sc < best) { best = sc; bi = v; }
    }
    __shared__ float bv[256];
    __shared__ int bix[256];
    bv[tid] = best; bix[tid] = bi;
    __syncthreads();
    for (int o = 128; o > 0; o >>= 1) {
        if (tid < o) {
            if (bv[tid + o] < bv[tid] || (bv[tid + o] == bv[tid] && bix[tid + o] < bix[tid])) {
                bv[tid] = bv[tid + o]; bix[tid] = bix[tid + o];
            }
        }
        __syncthreads();
    }
    if (tid == 0) tgt[n] = bix[0];
}

// ---------------- weight transpose-convert (coalesced 16B writes) ----------------
__global__ void __launch_bounds__(256) tconv_kernel(const float* __restrict__ W,
                                                    __nv_bfloat16* __restrict__ Wt,
                                                    int K, int N)
{
    W  += (size_t)blockIdx.z * K * N;
    Wt += (size_t)blockIdx.z * K * N;
    __shared__ float tile[64][33];
    int n0 = blockIdx.x * 32, k0 = blockIdx.y * 64;
    int nx = threadIdx.x & 31, ky = threadIdx.x >> 5;
#pragma unroll
    for (int i = 0; i < 64; i += 8)
        tile[ky + i][nx] = W[(size_t)(k0 + ky + i) * N + n0 + nx];
    __syncthreads();
    int n = threadIdx.x >> 3, kg = threadIdx.x & 7;
    __nv_bfloat16 v[8];
#pragma unroll
    for (int j = 0; j < 8; j++)
        v[j] = __float2bfloat16(tile[kg * 8 + j][n]);
    *(float4*)&Wt[(size_t)(n0 + n) * K + k0 + kg * 8] = *(float4*)v;
}

// ---------------- embedding transpose + hi/lo split ----------------
__global__ void __launch_bounds__(256) embsplit_kernel(const float* __restrict__ emb,
                                                       __nv_bfloat16* __restrict__ embt)
{
    __shared__ float tile[32][33];
    int v0 = blockIdx.x * 32, e0 = blockIdx.y * 32;
    int tx = threadIdx.x & 31, ty = threadIdx.x >> 5;
#pragma unroll
    for (int i = 0; i < 32; i += 8)
        tile[ty + i][tx] = emb[(size_t)(e0 + ty + i) * VV + v0 + tx];
    __syncthreads();
#pragma unroll
    for (int i = 0; i < 32; i += 8) {
        float a = tile[tx][ty + i];
        int v = v0 + ty + i, e = e0 + tx;
        __nv_bfloat16 hi = __float2bfloat16(a);
        __nv_bfloat16 lo = __float2bfloat16(a - __bfloat162float(hi));
        size_t base = (size_t)v * KSP;
        embt[base + e] = hi;
        embt[base + DD + e] = lo;
        embt[base + 2 * DD + e] = hi;
    }
}

// ---------------- W_embed transpose + hi/lo split: W[K,N] -> Wt[N][3K] (hi|lo|hi) ----------------
__global__ void __launch_bounds__(256) wsplit_kernel(const float* __restrict__ W,
                                                     __nv_bfloat16* __restrict__ Wt)
{
    __shared__ float tile[32][33];
    int n0 = blockIdx.x * 32, k0 = blockIdx.y * 32;
    int tx = threadIdx.x & 31, ty = threadIdx.x >> 5;
#pragma unroll
    for (int i = 0; i < 32; i += 8)
        tile[ty + i][tx] = W[(size_t)(k0 + ty + i) * DD + n0 + tx];
    __syncthreads();
#pragma unroll
    for (int i = 0; i < 32; i += 8) {
        float a = tile[tx][ty + i];          // W[k0+tx][n0+ty+i]
        int n = n0 + ty + i, k = k0 + tx;
        __nv_bfloat16 hi = __float2bfloat16(a);
        __nv_bfloat16 lo = __float2bfloat16(a - __bfloat162float(hi));
        size_t base = (size_t)n * KSP;
        Wt[base + k] = hi;
        Wt[base + DD + k] = lo;
        Wt[base + 2 * DD + k] = hi;
    }
}

// ---------------- xs hi/lo split (lens-limited rows): xs[N,D] -> zs[N][3D] (hi|hi|lo) ----------------
__global__ void __launch_bounds__(256) xsplit_kernel(const float* __restrict__ x,
                                                     __nv_bfloat16* __restrict__ zs,
                                                     const int* __restrict__ lens)
{
    int idx = blockIdx.x * 256 + threadIdx.x;
    int n = idx >> 9, e = idx & 511;
    if ((n & 1023) >= ((lens[n >> 10] + 127) & ~127)) return;
    float a = x[idx];
    __nv_bfloat16 hi = __float2bfloat16(a);
    __nv_bfloat16 lo = __float2bfloat16(a - __bfloat162float(hi));
    size_t base = (size_t)n * KSP;
    zs[base + e] = hi;
    zs[base + DD + e] = hi;
    zs[base + 2 * DD + e] = lo;
}

// ---------------- z hi/lo split (compact rows) ----------------
__global__ void __launch_bounds__(256) zsplit_kernel(const float* __restrict__ z,
                                                     __nv_bfloat16* __restrict__ zs,
                                                     const int* __restrict__ nactpad)
{
    int idx = blockIdx.x * 256 + threadIdx.x;
    int n = idx >> 9, e = idx & 511;
    if (n >= *nactpad) return;
    float a = z[idx];
    __nv_bfloat16 hi = __float2bfloat16(a);
    __nv_bfloat16 lo = __float2bfloat16(a - __bfloat162float(hi));
    size_t base = (size_t)n * KSP;
    zs[base + e] = hi;
    zs[base + DD + e] = hi;
    zs[base + 2 * DD + e] = lo;
}

// =======================================================================
// bf16 HMMA flash attention
// =======================================================================
__global__ void __launch_bounds__(128) attnmma_kernel(const __nv_bfloat16* __restrict__ qkvb,
                                                      const int* __restrict__ lens,
                                                      __nv_bfloat16* __restrict__ out)
{
    const int b = blockIdx.z, h = blockIdx.y, q0 = blockIdx.x * 64;
    const int len = lens[b];
    if (q0 >= len) return;
    const int tid = threadIdx.x;
    const int wid = tid >> 5, lane = tid & 31;
    const int ktmax = (len + 63) >> 6;

    __shared__ __align__(128) __nv_bfloat16 Qs[64 * 64];
    __shared__ __align__(128) __nv_bfloat16 KB[2][64 * 64];
    __shared__ __align__(128) __nv_bfloat16 VB[2][64 * 64];
    const uint32_t sq = smem_u32(Qs);
    const uint32_t skb[2] = { smem_u32(KB[0]), smem_u32(KB[1]) };
    const uint32_t svb[2] = { smem_u32(VB[0]), smem_u32(VB[1]) };

    auto load_kv = [&](int kt) {
        const __nv_bfloat16* kbase = qkvb + (size_t)(b * TT + kt * 64) * (3 * DD) + DD + h * HD;
        const __nv_bfloat16* vbase = qkvb + (size_t)(b * TT + kt * 64) * (3 * DD) + 2 * DD + h * HD;
        uint32_t dk = skb[kt & 1], dv = svb[kt & 1];
#pragma unroll
        for (int c = 0; c < 4; c++) {
            int idx = tid * 4 + c;
            int row = idx >> 3, seg = idx & 7;
            uint32_t off = SWZ((uint32_t)(row * 128 + seg * 16));
            cp16(dk + off, kbase + (size_t)row * (3 * DD) + seg * 8);
            cp16(dv + off, vbase + (size_t)row * (3 * DD) + seg * 8);
        }
        asm volatile("cp.async.commit_group;");
    };

    {
        const __nv_bfloat16* base = qkvb + (size_t)(b * TT + q0) * (3 * DD) + h * HD;
#pragma unroll
        for (int c = 0; c < 4; c++) {
            int idx = tid * 4 + c;
            int row = idx >> 3, seg = idx & 7;
            cp16(sq + SWZ((uint32_t)(row * 128 + seg * 16)), base + (size_t)row * (3 * DD) + seg * 8);
        }
        asm volatile("cp.async.commit_group;");
    }
    load_kv(0);
    asm volatile("cp.async.wait_group 0;");
    __syncthreads();

    uint32_t af[4][4];
#pragma unroll
    for (int ks = 0; ks < 4; ks++) {
        int row = wid * 16 + (lane & 15);
        uint32_t addr = sq + SWZ((uint32_t)(row * 128 + ks * 32 + ((lane >> 4) << 4)));
        ldsm_x4(af[ks][0], af[ks][1], af[ks][2], af[ks][3], addr);
    }

    float m0 = -1e30f, m1 = -1e30f, l0 = 0.f, l1 = 0.f;
    float oacc[8][4];
#pragma unroll
    for (int nb = 0; nb < 8; nb++)
#pragma unroll
        for (int q = 0; q < 4; q++) oacc[nb][q] = 0.f;

    const int g = lane >> 2, tq = lane & 3;

    for (int kt = 0; kt < ktmax; kt++) {
        if (kt + 1 < ktmax) load_kv(kt + 1);

        const uint32_t sk = skb[kt & 1], sv = svb[kt & 1];

        float s[8][4];
#pragma unroll
        for (int nb = 0; nb < 8; nb++)
#pragma unroll
            for (int q = 0; q < 4; q++) s[nb][q] = 0.f;
#pragma unroll
        for (int ks = 0; ks < 4; ks++) {
            uint32_t bf[8][2];
#pragma unroll
            for (int p = 0; p < 4; p++) {
                int nr = p * 16 + ((lane >> 4) << 3) + (lane & 7);
                uint32_t addr = sk + SWZ((uint32_t)(nr * 128 + ks * 32 + (((lane >> 3) & 1) << 4)));
                ldsm_x4(bf[p * 2][0], bf[p * 2][1], bf[p * 2 + 1][0], bf[p * 2 + 1][1], addr);
            }
#pragma unroll
            for (int nb = 0; nb < 8; nb++)
                mma16816(s[nb], af[ks], bf[nb]);
        }

#pragma unroll
        for (int nb = 0; nb < 8; nb++) {
            int k0c = kt * 64 + nb * 8 + tq * 2;
            float ba = (k0c < len) ? 0.f : -1e9f;
            float bb2 = (k0c + 1 < len) ? 0.f : -1e9f;
            s[nb][0] = s[nb][0] * 0.125f + ba;
            s[nb][1] = s[nb][1] * 0.125f + bb2;
            s[nb][2] = s[nb][2] * 0.125f + ba;
            s[nb][3] = s[nb][3] * 0.125f + bb2;
        }

        float mt0 = -1e30f, mt1 = -1e30f;
#pragma unroll
        for (int nb = 0; nb < 8; nb++) {
            mt0 = fmaxf(mt0, fmaxf(s[nb][0], s[nb][1]));
            mt1 = fmaxf(mt1, fmaxf(s[nb][2], s[nb][3]));
        }
        mt0 = fmaxf(mt0, __shfl_xor_sync(0xffffffffu, mt0, 1));
        mt0 = fmaxf(mt0, __shfl_xor_sync(0xffffffffu, mt0, 2));
        mt1 = fmaxf(mt1, __shfl_xor_sync(0xffffffffu, mt1, 1));
        mt1 = fmaxf(mt1, __shfl_xor_sync(0xffffffffu, mt1, 2));

        float mn0 = fmaxf(m0, mt0), mn1 = fmaxf(m1, mt1);
        float a0 = __expf(m0 - mn0), a1 = __expf(m1 - mn1);
        m0 = mn0; m1 = mn1;

        float r0 = 0.f, r1 = 0.f;
#pragma unroll
        for (int nb = 0; nb < 8; nb++) {
            s[nb][0] = __expf(s[nb][0] - m0);
            s[nb][1] = __expf(s[nb][1] - m0);
            s[nb][2] = __expf(s[nb][2] - m1);
            s[nb][3] = __expf(s[nb][3] - m1);
            r0 += s[nb][0] + s[nb][1];
            r1 += s[nb][2] + s[nb][3];
        }
        r0 += __shfl_xor_sync(0xffffffffu, r0, 1);
        r0 += __shfl_xor_sync(0xffffffffu, r0, 2);
        r1 += __shfl_xor_sync(0xffffffffu, r1, 1);
        r1 += __shfl_xor_sync(0xffffffffu, r1, 2);
        l0 = l0 * a0 + r0;
        l1 = l1 * a1 + r1;

#pragma unroll
        for (int nb = 0; nb < 8; nb++) {
            oacc[nb][0] *= a0; oacc[nb][1] *= a0;
            oacc[nb][2] *= a1; oacc[nb][3] *= a1;
        }

        uint32_t ap[4][4];
#pragma unroll
        for (int kk = 0; kk < 4; kk++) {
            ap[kk][0] = packbf(s[2 * kk][0],     s[2 * kk][1]);
            ap[kk][1] = packbf(s[2 * kk][2],     s[2 * kk][3]);
            ap[kk][2] = packbf(s[2 * kk + 1][0], s[2 * kk + 1][1]);
            ap[kk][3] = packbf(s[2 * kk + 1][2], s[2 * kk + 1][3]);
        }

#pragma unroll
        for (int kk = 0; kk < 4; kk++) {
            uint32_t bfv[8][2];
#pragma unroll
            for (int p = 0; p < 4; p++) {
                int key = kk * 16 + ((lane >> 3) & 1) * 8 + (lane & 7);
                uint32_t dbyte = (uint32_t)(p * 32 + ((lane >> 4) & 1) * 16);
                uint32_t addr = sv + SWZ((uint32_t)(key * 128) + dbyte);
                ldsm_x4_t(bfv[p * 2][0], bfv[p * 2][1], bfv[p * 2 + 1][0], bfv[p * 2 + 1][1], addr);
            }
#pragma unroll
            for (int nb = 0; nb < 8; nb++)
                mma16816(oacc[nb], ap[kk], bfv[nb]);
        }

        if (kt + 1 < ktmax) {
            asm volatile("cp.async.wait_group 0;");
            __syncthreads();
        }
    }

    float i0 = 1.f / l0, i1 = 1.f / l1;
    int row0 = b * TT + q0 + wid * 16 + g;
#pragma unroll
    for (int nb = 0; nb < 8; nb++) {
        int col = h * HD + nb * 8 + tq * 2;
        *(__nv_bfloat162*)(out + (size_t)row0 * DD + col) =
            __nv_bfloat162(__float2bfloat16(oacc[nb][0] * i0), __float2bfloat16(oacc[nb][1] * i0));
        *(__nv_bfloat162*)(out + (size_t)(row0 + 8) * DD + col) =
            __nv_bfloat162(__float2bfloat16(oacc[nb][2] * i1), __float2bfloat16(oacc[nb][3] * i1));
    }
}

// ---------------- compact row loss ----------------
__global__ void __launch_bounds__(256) rowloss_kernel(const float* __restrict__ big,
                                                      const int* __restrict__ tgt,
                                                      const int* __restrict__ nact,
                                                      float* __restrict__ ent)
{
    const int n = blockIdx.x;
    if (n >= *nact) return;
    const float* row = big + (size_t)n * VV;
    const int tid = threadIdx.x;
    float mx = -1e30f;
    for (int v = tid; v < VV; v += 256) mx = fmaxf(mx, row[v]);
    __shared__ float sm[256];
    sm[tid] = mx;
    __syncthreads();
    for (int o = 128; o > 0; o >>= 1) {
        if (tid < o) sm[tid] = fmaxf(sm[tid], sm[tid + o]);
        __syncthreads();
    }
    mx = sm[0];
    __syncthreads();
    float s = 0.f;
    for (int v = tid; v < VV; v += 256) s += __expf(row[v] - mx);
    sm[tid] = s;
    __syncthreads();
    for (int o = 128; o > 0; o >>= 1) {
        if (tid < o) sm[tid] += sm[tid + o];
        __syncthreads();
    }
    if (tid == 0) ent[n] = mx + logf(sm[0]) - row[tgt[n]];
}

__global__ void __launch_bounds__(1024) finalize_kernel(const float* __restrict__ ent,
                                                        const int* __restrict__ nact,
                                                        float* __restrict__ out)
{
    const int tid = threadIdx.x;
    const int N = *nact;
    float s = 0.f;
    for (int n = tid; n < N; n += 1024) s += ent[n];
    __shared__ float ss[1024];
    ss[tid] = s;
    __syncthreads();
    for (int o = 512; o > 0; o >>= 1) {
        if (tid < o) ss[tid] += ss[tid + o];
        __syncthreads();
    }
    if (tid == 0) out[0] = ss[0] / (float)N;
}

// ---------------- host ----------------
extern "C" void kernel_launch(void* const* d_in, const int* in_sizes, int n_in,
                              void* d_out, int out_size)
{
    (void)in_sizes; (void)n_in; (void)out_size;
    const float*    xs    = (const float*)d_in[0];
    const int*      lens  = (const int*)d_in[1];
    const unsigned* mask  = (const unsigned*)d_in[2];
    const float*    W_emb = (const float*)d_in[3];
    const float*    ln1_s = (const float*)d_in[4];
    const float*    ln1_b = (const float*)d_in[5];
    const float*    Wqkv  = (const float*)d_in[6];
    const float*    Wo    = (const float*)d_in[7];
    const float*    ln2_s = (const float*)d_in[8];
    const float*    ln2_b = (const float*)d_in[9];
    const float*    W1    = (const float*)d_in[10];
    const float*    W2    = (const float*)d_in[11];
    const float*    an_s  = (const float*)d_in[12];
    const float*    an_b  = (const float*)d_in[13];
    const float*    iln_s = (const float*)d_in[14];
    const float*    iln_b = (const float*)d_in[15];
    const float*    memb  = (const float*)d_in[16];
    const float*    top   = (const float*)d_in[17];
    const float*    proj  = (const float*)d_in[18];
    const float*    emb   = (const float*)d_in[19];

    float *px, *pres, *ph, *pz, *pbig, *penorm, *pent;
    int *ptgt, *pactidx, *pnact, *pnactpad;
    __nv_bfloat16 *phb, *pqkvb, *pattnb, *pffnb, *pzs, *pembt, *pwembs, *pwqkvt, *pwot, *pw1t, *pw2t, *ptopt;
    cudaGetSymbolAddress((void**)&px, g_x);
    cudaGetSymbolAddress((void**)&pres, g_res);
    cudaGetSymbolAddress((void**)&ph, g_h);
    cudaGetSymbolAddress((void**)&pz, g_z);
    cudaGetSymbolAddress((void**)&pbig, g_big);
    cudaGetSymbolAddress((void**)&penorm, g_enorm);
    cudaGetSymbolAddress((void**)&pent, g_ent);
    cudaGetSymbolAddress((void**)&ptgt, g_tgt);
    cudaGetSymbolAddress((void**)&pactidx, g_actidx);
    cudaGetSymbolAddress((void**)&pnact, g_nact);
    cudaGetSymbolAddress((void**)&pnactpad, g_nactpad);
    cudaGetSymbolAddress((void**)&phb, g_hb);
    cudaGetSymbolAddress((void**)&pqkvb, g_qkvb);
    cudaGetSymbolAddress((void**)&pattnb, g_attnb);
    cudaGetSymbolAddress((void**)&pffnb, g_ffnb);
    cudaGetSymbolAddress((void**)&pzs, g_zs);
    cudaGetSymbolAddress((void**)&pembt, g_embt);
    cudaGetSymbolAddress((void**)&pwembs, g_wembs);
    cudaGetSymbolAddress((void**)&pwqkvt, g_wqkvt);
    cudaGetSymbolAddress((void**)&pwot, g_wot);
    cudaGetSymbolAddress((void**)&pw1t, g_w1t);
    cudaGetSymbolAddress((void**)&pw2t, g_w2t);
    cudaGetSymbolAddress((void**)&ptopt, g_topt);

    cudaFuncSetAttribute(hgemm_kernel<0>, cudaFuncAttributeMaxDynamicSharedMemorySize, HG_SMEM);
    cudaFuncSetAttribute(hgemm_kernel<1>, cudaFuncAttributeMaxDynamicSharedMemorySize, HG_SMEM);
    cudaFuncSetAttribute(hgemm_kernel<2>, cudaFuncAttributeMaxDynamicSharedMemorySize, HG_SMEM);
    cudaFuncSetAttribute(hgemm_kernel<3>, cudaFuncAttributeMaxDynamicSharedMemorySize, HG_SMEM);

    dim3 tb(256);

    // ---- weight prep ----
    tconv_kernel<<<dim3(3 * DD / 32, DD / 64, LL), tb>>>(Wqkv, pwqkvt, DD, 3 * DD);
    tconv_kernel<<<dim3(DD / 32, DD / 64, LL), tb>>>(Wo, pwot, DD, DD);
    tconv_kernel<<<dim3(FF / 32, DD / 64, LL), tb>>>(W1, pw1t, DD, FF);
    tconv_kernel<<<dim3(DD / 32, FF / 64, LL), tb>>>(W2, pw2t, FF, DD);
    tconv_kernel<<<dim3(VV / 32, DD / 64, 1), tb>>>(top, ptopt, DD, VV);
    embsplit_kernel<<<dim3(VV / 32, DD / 32), tb>>>(emb, pembt);
    wsplit_kernel<<<dim3(DD / 32, DD / 32), tb>>>(W_emb, pwembs);
    enorm_kernel<<<VV / 256, tb>>>(emb, penorm);

    // ---- active-row compaction ----
    scan_kernel<<<1, 1024>>>(mask, lens, pactidx, pnact, pnactpad);

    // ---- 1. embed via split-bf16 HMMA (lens-limited) + PE ----
    xsplit_kernel<<<(NTOK * DD) / 256, tb>>>(xs, pzs, lens);
    hgemm_kernel<0><<<dim3(DD / 128, NTOK / 128), 256, HG_SMEM>>>(NTOK, DD, KSP,
            pzs, pwembs, px, nullptr, nullptr, lens, nullptr);
    pe_add_kernel<<<NTOK, tb>>>(px, lens);

    // ---- 2. targets on ACTIVE rows only ----
    lnw_kernel<float, true><<<NTOK / 8, tb>>>(px, ph, iln_s, iln_b, nullptr, pnactpad, pactidx);
    sgemm_kernel<<<dim3(DD / BN, NTOK / BM), tb>>>(NTOK, DD, DD, ph, proj, pz, pnactpad, nullptr);
    zsplit_kernel<<<(NTOK * DD) / 256, tb>>>(pz, pzs, pnactpad);
    hgemm_kernel<0><<<dim3(VV / 128, NTOK / 128), 256, HG_SMEM>>>(NTOK, VV, KSP, pzs, pembt, pbig, nullptr, pnactpad, nullptr, nullptr);
    argmin_kernel<<<NTOK, tb>>>(pbig, penorm, ptgt, pnact);

    // ---- 3. masked stream ----
    maskmix_kernel<<<(NTOK * DD) / 256, tb>>>(px, mask, memb, pres);

    // ---- 4. encoder layers 0..4 (full, lens-limited) ----
    for (int l = 0; l < LL - 1; l++) {
        lnw_kernel<__nv_bfloat16, false><<<NTOK / 8, tb>>>(pres, phb, ln1_s + l * DD, ln1_b + l * DD, lens, nullptr, nullptr);
        hgemm_kernel<3><<<dim3(3 * DD / 128, NTOK / 128), 256, HG_SMEM>>>(NTOK, 3 * DD, DD,
                phb, pwqkvt + (size_t)l * 3 * DD * DD, nullptr, pqkvb, nullptr, lens, nullptr);
        attnmma_kernel<<<dim3(TT / 64, HH, 8), 128>>>(pqkvb, lens, pattnb);
        hgemm_kernel<1><<<dim3(DD / 128, NTOK / 128), 256, HG_SMEM>>>(NTOK, DD, DD,
                pattnb, pwot + (size_t)l * DD * DD, pres, nullptr, nullptr, lens, nullptr);
        lnw_kernel<__nv_bfloat16, false><<<NTOK / 8, tb>>>(pres, phb, ln2_s + l * DD, ln2_b + l * DD, lens, nullptr, nullptr);
        hgemm_kernel<2><<<dim3(FF / 128, NTOK / 128), 256, HG_SMEM>>>(NTOK, FF, DD,
                phb, pw1t + (size_t)l * FF * DD, nullptr, pffnb, nullptr, lens, nullptr);
        hgemm_kernel<1><<<dim3(DD / 128, NTOK / 128), 256, HG_SMEM>>>(NTOK, DD, FF,
                pffnb, pw2t + (size_t)l * DD * FF, pres, nullptr, nullptr, lens, nullptr);
    }

    // ---- last layer: attention full, post-attention COMPACT ----
    {
        const int l = LL - 1;
        lnw_kernel<__nv_bfloat16, false><<<NTOK / 8, tb>>>(pres, phb, ln1_s + l * DD, ln1_b + l * DD, lens, nullptr, nullptr);
        hgemm_kernel<3><<<dim3(3 * DD / 128, NTOK / 128), 256, HG_SMEM>>>(NTOK, 3 * DD, DD,
                phb, pwqkvt + (size_t)l * 3 * DD * DD, nullptr, pqkvb, nullptr, lens, nullptr);
        attnmma_kernel<<<dim3(TT / 64, HH, 8), 128>>>(pqkvb, lens, pattnb);
        gather_kernel<<<NTOK, 128>>>(pres, ph, pactidx, pnactpad);
        hgemm_kernel<1><<<dim3(DD / 128, NTOK / 128), 256, HG_SMEM>>>(NTOK, DD, DD,
                pattnb, pwot + (size_t)l * DD * DD, ph, nullptr, pnactpad, nullptr, pactidx);
        lnw_kernel<__nv_bfloat16, false><<<NTOK / 8, tb>>>(ph, phb, ln2_s + l * DD, ln2_b + l * DD, nullptr, pnactpad, nullptr);
        hgemm_kernel<2><<<dim3(FF / 128, NTOK / 128), 256, HG_SMEM>>>(NTOK, FF, DD,
                phb, pw1t + (size_t)l * FF * DD, nullptr, pffnb, pnactpad, nullptr, nullptr);
        hgemm_kernel<1><<<dim3(DD / 128, NTOK / 128), 256, HG_SMEM>>>(NTOK, DD, FF,
                pffnb, pw2t + (size_t)l * DD * FF, ph, nullptr, pnactpad, nullptr, nullptr);
    }

    // ---- 5. final LN (compact) + logits + loss ----
    lnw_kernel<__nv_bfloat16, false><<<NTOK / 8, tb>>>(ph, phb, an_s, an_b, nullptr, pnactpad, nullptr);
    hgemm_kernel<0><<<dim3(VV / 128, NTOK / 128), 256, HG_SMEM>>>(NTOK, VV, DD, phb, ptopt, pbig, nullptr, pnactpad, nullptr, nullptr);
    rowloss_kernel<<<NTOK, tb>>>(pbig, ptgt, pnact, pent);
    finalize_kernel<<<1, 1024>>>(pent, pnact, (float*)d_out);
}